// round 2
// baseline (speedup 1.0000x reference)
#include <cuda_runtime.h>
#include <math.h>

// ---------------- problem constants ----------------
#define BATCH   2
#define SEQ     512
#define DM      768
#define DI      1536          // d_inner
#define DS      16            // d_state
#define M_TOT   (BATCH*SEQ)   // 1024
#define XZ_LD   (2*DI)        // 3072
#define XDBL_LD (DI + 2*DS)   // 1568

// ---------------- scratch (static __device__, no allocs) ----------------
__device__ float g_xz    [M_TOT * XZ_LD];    // [bt][3072]  (x_inner | z)
__device__ float g_xconvT[DI * M_TOT];       // [d][bt]  silu(conv(x_inner))
__device__ float g_xdbl  [M_TOT * XDBL_LD];  // [bt][1568]  (delta_raw | B | C)
__device__ float g_deltaT[DI * M_TOT];       // [d][bt]  softplus'd delta
__device__ float g_zT    [DI * M_TOT];       // [d][bt]  silu(z)
__device__ float g_BT    [DS * M_TOT];       // [n][bt]
__device__ float g_CT2   [DS * M_TOT];       // [n][bt]
__device__ float g_ypreT [DI * M_TOT];       // [d][bt]

__device__ __forceinline__ float softplusf(float x) {
    if (x > 20.f) return x;
    return log1pf(expf(x));
}
__device__ __forceinline__ float siluf(float x) {
    return x / (1.f + expf(-x));
}

// ---------------- tiled SGEMM: C = act(A @ W^T (+bias)) ----------------
// A: row-major [M,K] (lda=K-ish) or, if ACOL, stored as [K][M] (lda = m-stride)
// W: row-major [N,K].  BK=8, 256 threads, TMxTN per thread, double-buffered.
// CT: store C transposed, C[col*ldc + row].
template <int BM, int BN, int TM, int TN, bool ACOL, bool SP, bool CT>
__global__ __launch_bounds__(256)
void sgemm(const float* __restrict__ A, int lda,
           const float* __restrict__ W, int ldw,
           const float* __restrict__ bias,
           float* __restrict__ C, int ldc,
           int N, int K)
{
    __shared__ float As[2][8][BM + 4];
    __shared__ float Ws[2][8][BN + 4];

    const int bm = blockIdx.y * BM;
    const int bn = blockIdx.x * BN;
    const int tid = threadIdx.x;
    const int tx = tid % (BN / TN);
    const int ty = tid / (BN / TN);

    // A loaders (2*BM float4 per tile)
    const bool aactive = tid < 2 * BM;
    const int arow = tid >> 1;            // row-major: m-row
    const int ak   = (tid & 1) * 4;       // row-major: k offset
    const int ck   = ACOL ? tid / (BM / 4) : 0;         // col-major: k-row
    const int cm4  = ACOL ? (tid % (BM / 4)) * 4 : 0;   // col-major: m offset

    // W loaders (2*BN float4 per tile)
    const bool wactive = tid < 2 * BN;
    const int wrow = tid >> 1;
    const int wk   = (tid & 1) * 4;
    const bool wok = wactive && (bn + wrow) < N;

    float4 areg, wreg;

    auto loadA = [&](int k0) {
        if (aactive) {
            if (ACOL) areg = *(const float4*)(A + (size_t)(k0 + ck) * lda + bm + cm4);
            else      areg = *(const float4*)(A + (size_t)(bm + arow) * lda + k0 + ak);
        }
    };
    auto loadW = [&](int k0) {
        if (wok) wreg = *(const float4*)(W + (size_t)(bn + wrow) * ldw + k0 + wk);
        else     wreg = make_float4(0.f, 0.f, 0.f, 0.f);
    };
    auto storeA = [&](int buf) {
        if (aactive) {
            if (ACOL) {
                *(float4*)&As[buf][ck][cm4] = areg;
            } else {
                As[buf][ak + 0][arow] = areg.x; As[buf][ak + 1][arow] = areg.y;
                As[buf][ak + 2][arow] = areg.z; As[buf][ak + 3][arow] = areg.w;
            }
        }
    };
    auto storeW = [&](int buf) {
        if (wactive) {
            Ws[buf][wk + 0][wrow] = wreg.x; Ws[buf][wk + 1][wrow] = wreg.y;
            Ws[buf][wk + 2][wrow] = wreg.z; Ws[buf][wk + 3][wrow] = wreg.w;
        }
    };

    float acc[TM][TN];
#pragma unroll
    for (int i = 0; i < TM; i++)
#pragma unroll
        for (int j = 0; j < TN; j++) acc[i][j] = 0.f;

    loadA(0); loadW(0);
    storeA(0); storeW(0);
    __syncthreads();

    const int nIter = K / 8;
    int buf = 0;
    for (int it = 0; it < nIter; it++) {
        if (it + 1 < nIter) { loadA((it + 1) * 8); loadW((it + 1) * 8); }

#pragma unroll
        for (int kk = 0; kk < 8; kk++) {
            float a[TM], b[TN];
            *(float4*)&a[0] = *(const float4*)&As[buf][kk][ty * TM];
            if (TM == 8) *(float4*)&a[4] = *(const float4*)&As[buf][kk][ty * TM + 4];
            *(float4*)&b[0] = *(const float4*)&Ws[buf][kk][tx * TN];
            if (TN == 8) *(float4*)&b[4] = *(const float4*)&Ws[buf][kk][tx * TN + 4];
#pragma unroll
            for (int i = 0; i < TM; i++)
#pragma unroll
                for (int j = 0; j < TN; j++)
                    acc[i][j] = fmaf(a[i], b[j], acc[i][j]);
        }

        if (it + 1 < nIter) { storeA(buf ^ 1); storeW(buf ^ 1); }
        __syncthreads();
        buf ^= 1;
    }

#pragma unroll
    for (int i = 0; i < TM; i++) {
        const int row = bm + ty * TM + i;
#pragma unroll
        for (int j = 0; j < TN; j++) {
            const int col = bn + tx * TN + j;
            if (col < N) {
                float v = acc[i][j];
                if (SP) v = softplusf(v + bias[col]);
                if (CT) C[(size_t)col * ldc + row] = v;
                else    C[(size_t)row * ldc + col] = v;
            }
        }
    }
}

// ---------------- depthwise causal conv (k=4) + bias + SiLU -> transposed ----
// grid: (SEQ/128, DI/32, BATCH), block (32, 8)
__global__ __launch_bounds__(256)
void conv_silu_T_kernel(const float* __restrict__ conv_w, const float* __restrict__ conv_b)
{
    __shared__ float s[32][133];   // [d][tt], tt covers t0-3 .. t0+127
    const int t0 = blockIdx.x * 128;
    const int d0 = blockIdx.y * 32;
    const int b  = blockIdx.z;

    // load: lanes along d (coalesced 128B rows of g_xz)
    for (int tt = threadIdx.y; tt < 131; tt += 8) {
        const int gt = t0 - 3 + tt;
        float v = 0.f;
        if (gt >= 0)
            v = g_xz[(size_t)(b * SEQ + gt) * XZ_LD + d0 + threadIdx.x];
        s[threadIdx.x][tt] = v;
    }
    __syncthreads();

    // compute: lanes along t (coalesced stores to xconvT)
    for (int dd = threadIdx.y; dd < 32; dd += 8) {
        const int d = d0 + dd;
        const float w0 = conv_w[d * 4 + 0];
        const float w1 = conv_w[d * 4 + 1];
        const float w2 = conv_w[d * 4 + 2];
        const float w3 = conv_w[d * 4 + 3];
        const float cb = conv_b[d];
#pragma unroll
        for (int tc = 0; tc < 4; tc++) {
            const int tl = tc * 32 + threadIdx.x;
            float acc = cb;
            acc = fmaf(s[dd][tl + 0], w0, acc);
            acc = fmaf(s[dd][tl + 1], w1, acc);
            acc = fmaf(s[dd][tl + 2], w2, acc);
            acc = fmaf(s[dd][tl + 3], w3, acc);
            g_xconvT[(size_t)d * M_TOT + b * SEQ + t0 + tl] = siluf(acc);
        }
    }
}

// ---------------- silu(z) transpose: zT[d][bt] = silu(xz[bt][DI+d]) ----------
// grid (M_TOT/32, DI/32), block (32, 8)
__global__ __launch_bounds__(256)
void siluz_T_kernel()
{
    __shared__ float ts[32][33];
    const int bt0 = blockIdx.x * 32;
    const int d0  = blockIdx.y * 32;
#pragma unroll
    for (int j = 0; j < 4; j++) {
        const int bt = bt0 + threadIdx.y + j * 8;
        ts[threadIdx.y + j * 8][threadIdx.x] =
            g_xz[(size_t)bt * XZ_LD + DI + d0 + threadIdx.x];
    }
    __syncthreads();
#pragma unroll
    for (int j = 0; j < 4; j++) {
        const int d = d0 + threadIdx.y + j * 8;
        g_zT[(size_t)d * M_TOT + bt0 + threadIdx.x] =
            siluf(ts[threadIdx.x][threadIdx.y + j * 8]);
    }
}

// ---------------- pack B,C slices transposed ----------------
__global__ __launch_bounds__(256)
void pack_bc_kernel()
{
    const int idx = blockIdx.x * 256 + threadIdx.x;   // 0 .. 2*DS*M_TOT-1
    const int half = DS * M_TOT;
    const int which = idx / half;
    const int r  = idx % half;
    const int n  = r / M_TOT;
    const int bt = r % M_TOT;
    const float v = g_xdbl[(size_t)bt * XDBL_LD + DI + which * DS + n];
    if (which) g_CT2[r] = v; else g_BT[r] = v;
}

// ---------------- fused selective-scan kernel ----------------
// Grid: (DI, BATCH), 512 threads (16 warps, warp w owns state n=w).
// Exact replica of the reference (non-associative) Blelloch up/down sweep, in
// LINEAR space. Epilogue: sum_n h*C + x_conv*Dp, * silu(z), transposed store.
#define WPAD 528   // 512 + 16 pad (idx + idx>>5)
__global__ __launch_bounds__(512)
void scan_kernel(const float* __restrict__ A_log, const float* __restrict__ Dp)
{
    const int d = blockIdx.x;
    const int b = blockIdx.y;
    extern __shared__ float sm[];
    float* sdelta = sm;              // [512]
    float* sxc    = sm + SEQ;        // [512]
    const int tid  = threadIdx.x;
    const int warp = tid >> 5;
    const int lane = tid & 31;
    float* cw = sm + 2 * SEQ + warp * (2 * WPAD);
    float* vw = cw + WPAD;

    // coalesced column loads
    sdelta[tid] = g_deltaT[(size_t)d * M_TOT + b * SEQ + tid];
    sxc[tid]    = g_xconvT[(size_t)d * M_TOT + b * SEQ + tid];
    __syncthreads();

    const int n = warp;                          // state index 0..15
    const float a = -expf(A_log[d * DS + n]);

    // build c[t], v[t]  (coalesced B load per warp)
    for (int t = lane; t < SEQ; t += 32) {
        const float dt = sdelta[t];
        const float Bt = g_BT[n * M_TOT + b * SEQ + t];
        cw[t + (t >> 5)] = expf(dt * a) + 1e-12f;
        vw[t + (t >> 5)] = fabsf(dt * Bt * sxc[t]) + 1e-12f;
    }
    __syncwarp();

    // up-sweep (9 levels)
#pragma unroll
    for (int lev = 0; lev < 9; lev++) {
        const int half = 1 << lev;
        const int np   = SEQ >> (lev + 1);
        for (int i = lane; i < np; i += 32) {
            const int r = ((i + 1) << (lev + 1)) - 1;
            const int l = r - half;
            const int pr = r + (r >> 5), pl = l + (l >> 5);
            const float cl = cw[pl], cr = cw[pr];
            const float vl = vw[pl], vr = vw[pr];
            vw[pr] = fmaf(cr, vr, vl);
            cw[pr] = cl * cr;
        }
        __syncwarp();
    }
    // down-sweep
#pragma unroll
    for (int lev = 8; lev >= 0; lev--) {
        const int half = 1 << lev;
        const int np   = SEQ >> (lev + 1);
        for (int i = lane; i < np; i += 32) {
            const int r = ((i + 1) << (lev + 1)) - 1;
            const int l = r - half;
            const int pr = r + (r >> 5), pl = l + (l >> 5);
            const float vr = vw[pr];
            const float vl = vw[pl];
            const float cr = cw[pr];
            vw[pr] = fmaf(cr, vr, vl);
            vw[pl] = vr;
        }
        __syncwarp();
    }

    // multiply by C (per state, coalesced)
    for (int t = lane; t < SEQ; t += 32) {
        const float Ct = g_CT2[n * M_TOT + b * SEQ + t];
        vw[t + (t >> 5)] *= Ct;
    }
    __syncthreads();

    // reduce across 16 states + epilogue, coalesced transposed store
    {
        const int t = tid;
        const int pt = t + (t >> 5);
        float acc = 0.f;
#pragma unroll
        for (int w = 0; w < 16; w++)
            acc += sm[2 * SEQ + w * (2 * WPAD) + WPAD + pt];
        const float gz = g_zT[(size_t)d * M_TOT + b * SEQ + t];
        float yv = fmaf(sxc[t], Dp[d], acc);
        yv *= gz;
        g_ypreT[(size_t)d * M_TOT + b * SEQ + t] = yv;
    }
}

// ---------------- launch ----------------
extern "C" void kernel_launch(void* const* d_in, const int* in_sizes, int n_in,
                              void* d_out, int out_size)
{
    const float* x      = (const float*)d_in[0];
    const float* W_in   = (const float*)d_in[1];
    const float* conv_w = (const float*)d_in[2];
    const float* conv_b = (const float*)d_in[3];
    const float* W_x    = (const float*)d_in[4];
    const float* W_dt   = (const float*)d_in[5];
    const float* b_dt   = (const float*)d_in[6];
    const float* A_log  = (const float*)d_in[7];
    const float* Dp     = (const float*)d_in[8];
    const float* W_out  = (const float*)d_in[9];
    float* out = (float*)d_out;

    float *xz, *xconvT, *xdbl, *deltaT, *ypreT;
    cudaGetSymbolAddress((void**)&xz,     g_xz);
    cudaGetSymbolAddress((void**)&xconvT, g_xconvT);
    cudaGetSymbolAddress((void**)&xdbl,   g_xdbl);
    cudaGetSymbolAddress((void**)&deltaT, g_deltaT);
    cudaGetSymbolAddress((void**)&ypreT,  g_ypreT);

    const int scan_smem = (2 * SEQ + 16 * 2 * WPAD) * sizeof(float);  // 71680 B
    cudaFuncSetAttribute(scan_kernel, cudaFuncAttributeMaxDynamicSharedMemorySize, scan_smem);

    // 1) xz = x @ W_in^T    [1024, 3072]   grid 24x8
    sgemm<128, 128, 8, 8, false, false, false>
        <<<dim3(XZ_LD / 128, M_TOT / 128), 256>>>(
        x, DM, W_in, DM, nullptr, xz, XZ_LD, XZ_LD, DM);

    // 2) depthwise causal conv + bias + silu -> xconvT [1536][1024]
    conv_silu_T_kernel<<<dim3(SEQ / 128, DI / 32, BATCH), dim3(32, 8)>>>(conv_w, conv_b);

    // 2b) silu(z) transposed
    siluz_T_kernel<<<dim3(M_TOT / 32, DI / 32), dim3(32, 8)>>>();

    // 3) x_dbl = x_conv @ W_x^T   [1024, 1568]   grid 13x16 (A col-major)
    sgemm<64, 128, 4, 8, true, false, false>
        <<<dim3((XDBL_LD + 127) / 128, M_TOT / 64), 256>>>(
        xconvT, M_TOT, W_x, DI, nullptr, xdbl, XDBL_LD, XDBL_LD, DI);

    // 3b) pack B, C transposed
    pack_bc_kernel<<<(2 * DS * M_TOT) / 256, 256>>>();

    // 4) deltaT = softplus(delta_raw @ W_dt^T + b_dt)^T   [1536][1024]  grid 12x16
    sgemm<64, 128, 4, 8, false, true, true>
        <<<dim3(DI / 128, M_TOT / 64), 256>>>(
        xdbl, XDBL_LD, W_dt, DI, b_dt, deltaT, M_TOT, DI, DI);

    // 5) fused scan + C-reduction + Dp + silu(z) gate -> ypreT [1536][1024]
    scan_kernel<<<dim3(DI, BATCH), 512, scan_smem>>>(A_log, Dp);

    // 6) out = ypre @ W_out^T   [1024, 768]  (A col-major via ypreT)  grid 12x16
    sgemm<64, 64, 4, 4, true, false, false>
        <<<dim3(DM / 64, M_TOT / 64), 256>>>(
        ypreT, M_TOT, W_out, DI, nullptr, out, DM, DM, DI);
}

// round 4
// speedup vs baseline: 2.4783x; 2.4783x over previous
#include <cuda_runtime.h>
#include <math.h>
#include <stdint.h>

// ---------------- problem constants ----------------
#define BATCH   2
#define SEQ     512
#define DM      768
#define DI      1536
#define DS      16
#define M_TOT   (BATCH*SEQ)   // 1024
#define XZ_LD   (2*DI)        // 3072
#define XDBL_LD (DI + 2*DS)   // 1568
#define NX_PAD  1664          // W_x N padded to multiple of 128

// ---------------- scratch ----------------
__device__ float g_x32    [M_TOT * DM];
__device__ float g_Win32  [XZ_LD * DM];
__device__ float g_Wx32   [NX_PAD * DI];
__device__ float g_Wdt32  [DI * DI];
__device__ float g_Wout32 [DM * DI];
__device__ float g_xz     [M_TOT * XZ_LD];
__device__ float g_xconvT [DI * M_TOT];
__device__ float g_xconv32[M_TOT * DI];
__device__ float g_xdbl   [M_TOT * XDBL_LD];
__device__ float g_deltaT [DI * M_TOT];
__device__ float g_zT     [DI * M_TOT];
__device__ float g_BT     [DS * M_TOT];
__device__ float g_CT2    [DS * M_TOT];
__device__ float g_ypreT  [DI * M_TOT];
__device__ float g_ypre   [M_TOT * DI];

// ---------------- helpers ----------------
__device__ __forceinline__ float softplusf(float x) {
    if (x > 20.f) return x;
    return log1pf(expf(x));
}
__device__ __forceinline__ float siluf(float x) {
    return x / (1.f + expf(-x));
}
__device__ __forceinline__ float tf32r(float x) {
    uint32_t u;
    asm("cvt.rna.tf32.f32 %0, %1;" : "=r"(u) : "f"(x));
    return __uint_as_float(u);
}
__device__ __forceinline__ void cpa16(uint32_t dst, const float* src) {
    asm volatile("cp.async.cg.shared.global [%0], [%1], 16;\n" :: "r"(dst), "l"(src));
}
__device__ __forceinline__ void cpa_commit() {
    asm volatile("cp.async.commit_group;\n" ::: "memory");
}
__device__ __forceinline__ void mma_tf32(float* c, const uint32_t* a, const uint32_t* b) {
    asm volatile(
        "mma.sync.aligned.m16n8k8.row.col.f32.tf32.tf32.f32 "
        "{%0,%1,%2,%3}, {%4,%5,%6,%7}, {%8,%9}, {%0,%1,%2,%3};"
        : "+f"(c[0]), "+f"(c[1]), "+f"(c[2]), "+f"(c[3])
        : "r"(a[0]), "r"(a[1]), "r"(a[2]), "r"(a[3]), "r"(b[0]), "r"(b[1]));
}

// ---------------- mma.sync tf32 GEMM: C[1024, N] = act(A @ W^T (+bias)) ----
// A row-major [1024, K], W row-major [N, K], both tf32-pre-rounded.
// 128x128x16 tile, 128 threads (4 warps, 64x64 each), 3-stage cp.async.
#define GST 3
#define AROW 20                       // 16 + 4 pad floats per smem row
#define STG_FLT (2 * 128 * AROW)      // A + B rows per stage
#define GSMEM (GST * STG_FLT * 4)

template<bool SP, bool CT>
__global__ __launch_bounds__(128)
void mmagemm(const float* __restrict__ A, int lda,
             const float* __restrict__ W, int ldw,
             const float* __restrict__ bias,
             float* __restrict__ C, int ldc,
             int K, int Nstore)
{
    extern __shared__ __align__(16) float smem[];
    const int tid  = threadIdx.x;
    const int warp = tid >> 5;
    const int lane = tid & 31;
    const int bm = blockIdx.y * 128;
    const int bn = blockIdx.x * 128;
    const int wm = (warp & 1) * 64;
    const int wn = (warp >> 1) * 64;

    const uint32_t sbase = (uint32_t)__cvta_generic_to_shared(smem);

    // loader: thread -> (row = tid>>2, 16B chunk = tid&3), 4 row-passes
    const int lrow = tid >> 2;
    const int lch  = tid & 3;

    float acc[4][8][4];
#pragma unroll
    for (int i = 0; i < 4; i++)
#pragma unroll
        for (int j = 0; j < 8; j++)
#pragma unroll
            for (int k = 0; k < 4; k++) acc[i][j][k] = 0.f;

    const int nIter = K / 16;

    auto load_stage = [&](int s, int kt) {
        const uint32_t aB = sbase + (uint32_t)s * STG_FLT * 4;
        const uint32_t bB = aB + 128 * AROW * 4;
        const float* ap = A + (size_t)(bm + lrow) * lda + kt * 16 + lch * 4;
        const float* wp = W + (size_t)(bn + lrow) * ldw + kt * 16 + lch * 4;
#pragma unroll
        for (int p = 0; p < 4; p++) {
            cpa16(aB + (uint32_t)(lrow + p * 32) * AROW * 4 + lch * 16,
                  ap + (size_t)p * 32 * lda);
            cpa16(bB + (uint32_t)(lrow + p * 32) * AROW * 4 + lch * 16,
                  wp + (size_t)p * 32 * ldw);
        }
    };

    load_stage(0, 0); cpa_commit();
    if (nIter > 1) load_stage(1, 1);
    cpa_commit();

    for (int it = 0; it < nIter; it++) {
        asm volatile("cp.async.wait_group 1;\n" ::: "memory");
        __syncthreads();

        const int s = it % GST;
        const float* As = smem + (size_t)s * STG_FLT;
        const float* Ws = As + 128 * AROW;

#pragma unroll
        for (int ks = 0; ks < 2; ks++) {
            const int k0 = ks * 8;
            uint32_t af[4][4];
#pragma unroll
            for (int mt = 0; mt < 4; mt++) {
                const int ar = wm + mt * 16 + (lane >> 2);
                const int ac = k0 + (lane & 3);
                af[mt][0] = __float_as_uint(As[ar * AROW + ac]);
                af[mt][1] = __float_as_uint(As[(ar + 8) * AROW + ac]);
                af[mt][2] = __float_as_uint(As[ar * AROW + ac + 4]);
                af[mt][3] = __float_as_uint(As[(ar + 8) * AROW + ac + 4]);
            }
#pragma unroll
            for (int nt = 0; nt < 8; nt++) {
                const int br = wn + nt * 8 + (lane >> 2);
                const int bc = k0 + (lane & 3);
                uint32_t bf[2];
                bf[0] = __float_as_uint(Ws[br * AROW + bc]);
                bf[1] = __float_as_uint(Ws[br * AROW + bc + 4]);
#pragma unroll
                for (int mt = 0; mt < 4; mt++)
                    mma_tf32(acc[mt][nt], af[mt], bf);
            }
        }

        __syncthreads();
        if (it + 2 < nIter) load_stage((it + 2) % GST, it + 2);
        cpa_commit();
    }

    // epilogue
#pragma unroll
    for (int mt = 0; mt < 4; mt++) {
        const int row = bm + wm + mt * 16 + (lane >> 2);
#pragma unroll
        for (int nt = 0; nt < 8; nt++) {
            const int col = bn + wn + nt * 8 + (lane & 3) * 2;
            float v0 = acc[mt][nt][0], v1 = acc[mt][nt][1];
            float v2 = acc[mt][nt][2], v3 = acc[mt][nt][3];
            if (SP) {
                v0 = softplusf(v0 + bias[col]);     v1 = softplusf(v1 + bias[col + 1]);
                v2 = softplusf(v2 + bias[col]);     v3 = softplusf(v3 + bias[col + 1]);
            }
            if (!CT) {
                if (col < Nstore) {
                    *(float2*)(C + (size_t)row * ldc + col)       = make_float2(v0, v1);
                    *(float2*)(C + (size_t)(row + 8) * ldc + col) = make_float2(v2, v3);
                }
            } else {
                if (col < Nstore) {
                    C[(size_t)col * ldc + row]           = v0;
                    C[(size_t)(col + 1) * ldc + row]     = v1;
                    C[(size_t)col * ldc + row + 8]       = v2;
                    C[(size_t)(col + 1) * ldc + row + 8] = v3;
                }
            }
        }
    }
}

// ---------------- pre-pass: tf32 rounding ----------------
__global__ __launch_bounds__(256)
void round_copy_kernel(const float* __restrict__ src, float* __restrict__ dst, int n4)
{
    const int i = blockIdx.x * 256 + threadIdx.x;
    if (i < n4) {
        float4 v = ((const float4*)src)[i];
        v.x = tf32r(v.x); v.y = tf32r(v.y); v.z = tf32r(v.z); v.w = tf32r(v.w);
        ((float4*)dst)[i] = v;
    }
}
__global__ __launch_bounds__(256)
void pad_wx_kernel(const float* __restrict__ Wx)
{
    const int i = blockIdx.x * 256 + threadIdx.x;   // over NX_PAD*DI/4
    const int n  = i / (DI / 4);
    const int k4 = i % (DI / 4);
    float4 v = make_float4(0.f, 0.f, 0.f, 0.f);
    if (n < XDBL_LD) {
        float4 s = ((const float4*)Wx)[(size_t)n * (DI / 4) + k4];
        v.x = tf32r(s.x); v.y = tf32r(s.y); v.z = tf32r(s.z); v.w = tf32r(s.w);
    }
    ((float4*)g_Wx32)[(size_t)n * (DI / 4) + k4] = v;
}

// ---------------- depthwise causal conv + bias + SiLU -> both layouts -------
__global__ __launch_bounds__(256)
void conv_silu_T_kernel(const float* __restrict__ conv_w, const float* __restrict__ conv_b)
{
    __shared__ float s[32][133];
    __shared__ float r[128][33];
    const int t0 = blockIdx.x * 128;
    const int d0 = blockIdx.y * 32;
    const int b  = blockIdx.z;

    for (int tt = threadIdx.y; tt < 131; tt += 8) {
        const int gt = t0 - 3 + tt;
        float v = 0.f;
        if (gt >= 0)
            v = g_xz[(size_t)(b * SEQ + gt) * XZ_LD + d0 + threadIdx.x];
        s[threadIdx.x][tt] = v;
    }
    __syncthreads();

    for (int dd = threadIdx.y; dd < 32; dd += 8) {
        const int d = d0 + dd;
        const float w0 = conv_w[d * 4 + 0];
        const float w1 = conv_w[d * 4 + 1];
        const float w2 = conv_w[d * 4 + 2];
        const float w3 = conv_w[d * 4 + 3];
        const float cb = conv_b[d];
#pragma unroll
        for (int tc = 0; tc < 4; tc++) {
            const int tl = tc * 32 + threadIdx.x;
            float acc = cb;
            acc = fmaf(s[dd][tl + 0], w0, acc);
            acc = fmaf(s[dd][tl + 1], w1, acc);
            acc = fmaf(s[dd][tl + 2], w2, acc);
            acc = fmaf(s[dd][tl + 3], w3, acc);
            const float v = siluf(acc);
            g_xconvT[(size_t)d * M_TOT + b * SEQ + t0 + tl] = v;
            r[tl][dd] = v;
        }
    }
    __syncthreads();
    for (int tt = threadIdx.y; tt < 128; tt += 8)
        g_xconv32[(size_t)(b * SEQ + t0 + tt) * DI + d0 + threadIdx.x] =
            tf32r(r[tt][threadIdx.x]);
}

// ---------------- silu(z) transpose ----------------
__global__ __launch_bounds__(256)
void siluz_T_kernel()
{
    __shared__ float ts[32][33];
    const int bt0 = blockIdx.x * 32;
    const int d0  = blockIdx.y * 32;
#pragma unroll
    for (int j = 0; j < 4; j++) {
        const int bt = bt0 + threadIdx.y + j * 8;
        ts[threadIdx.y + j * 8][threadIdx.x] =
            g_xz[(size_t)bt * XZ_LD + DI + d0 + threadIdx.x];
    }
    __syncthreads();
#pragma unroll
    for (int j = 0; j < 4; j++) {
        const int d = d0 + threadIdx.y + j * 8;
        g_zT[(size_t)d * M_TOT + bt0 + threadIdx.x] =
            siluf(ts[threadIdx.x][threadIdx.y + j * 8]);
    }
}

// ---------------- pack B,C transposed ----------------
__global__ __launch_bounds__(256)
void pack_bc_kernel()
{
    const int idx = blockIdx.x * 256 + threadIdx.x;
    const int half = DS * M_TOT;
    const int which = idx / half;
    const int rr = idx % half;
    const int n  = rr / M_TOT;
    const int bt = rr % M_TOT;
    const float v = g_xdbl[(size_t)bt * XDBL_LD + DI + which * DS + n];
    if (which) g_CT2[rr] = v; else g_BT[rr] = v;
}

// ---------------- ypreT -> ypre (row-major, tf32-rounded) ----------------
__global__ __launch_bounds__(256)
void transpose_round_kernel()
{
    __shared__ float ts[32][33];
    const int bt0 = blockIdx.x * 32;
    const int d0  = blockIdx.y * 32;
#pragma unroll
    for (int j = 0; j < 4; j++) {
        const int d = d0 + threadIdx.y + j * 8;
        ts[threadIdx.y + j * 8][threadIdx.x] =
            g_ypreT[(size_t)d * M_TOT + bt0 + threadIdx.x];
    }
    __syncthreads();
#pragma unroll
    for (int j = 0; j < 4; j++) {
        const int bt = bt0 + threadIdx.y + j * 8;
        g_ypre[(size_t)bt * DI + d0 + threadIdx.x] =
            tf32r(ts[threadIdx.x][threadIdx.y + j * 8]);
    }
}

// ---------------- fused selective-scan kernel ----------------
#define WPAD 528
__global__ __launch_bounds__(512)
void scan_kernel(const float* __restrict__ A_log, const float* __restrict__ Dp)
{
    const int d = blockIdx.x;
    const int b = blockIdx.y;
    extern __shared__ float sm[];
    float* sdelta = sm;
    float* sxc    = sm + SEQ;
    const int tid  = threadIdx.x;
    const int warp = tid >> 5;
    const int lane = tid & 31;
    float* cw = sm + 2 * SEQ + warp * (2 * WPAD);
    float* vw = cw + WPAD;

    sdelta[tid] = g_deltaT[(size_t)d * M_TOT + b * SEQ + tid];
    sxc[tid]    = g_xconvT[(size_t)d * M_TOT + b * SEQ + tid];
    __syncthreads();

    const int n = warp;
    const float a = -expf(A_log[d * DS + n]);

    for (int t = lane; t < SEQ; t += 32) {
        const float dt = sdelta[t];
        const float Bt = g_BT[n * M_TOT + b * SEQ + t];
        cw[t + (t >> 5)] = expf(dt * a) + 1e-12f;
        vw[t + (t >> 5)] = fabsf(dt * Bt * sxc[t]) + 1e-12f;
    }
    __syncwarp();

#pragma unroll
    for (int lev = 0; lev < 9; lev++) {
        const int half = 1 << lev;
        const int np   = SEQ >> (lev + 1);
        for (int i = lane; i < np; i += 32) {
            const int rr = ((i + 1) << (lev + 1)) - 1;
            const int l = rr - half;
            const int pr = rr + (rr >> 5), pl = l + (l >> 5);
            const float cl = cw[pl], cr = cw[pr];
            const float vl = vw[pl], vr = vw[pr];
            vw[pr] = fmaf(cr, vr, vl);
            cw[pr] = cl * cr;
        }
        __syncwarp();
    }
#pragma unroll
    for (int lev = 8; lev >= 0; lev--) {
        const int half = 1 << lev;
        const int np   = SEQ >> (lev + 1);
        for (int i = lane; i < np; i += 32) {
            const int rr = ((i + 1) << (lev + 1)) - 1;
            const int l = rr - half;
            const int pr = rr + (rr >> 5), pl = l + (l >> 5);
            const float vr = vw[pr];
            const float vl = vw[pl];
            const float cr = cw[pr];
            vw[pr] = fmaf(cr, vr, vl);
            vw[pl] = vr;
        }
        __syncwarp();
    }

    for (int t = lane; t < SEQ; t += 32) {
        const float Ct = g_CT2[n * M_TOT + b * SEQ + t];
        vw[t + (t >> 5)] *= Ct;
    }
    __syncthreads();

    {
        const int t = tid;
        const int pt = t + (t >> 5);
        float acc = 0.f;
#pragma unroll
        for (int w = 0; w < 16; w++)
            acc += sm[2 * SEQ + w * (2 * WPAD) + WPAD + pt];
        const float gz = g_zT[(size_t)d * M_TOT + b * SEQ + t];
        float yv = fmaf(sxc[t], Dp[d], acc);
        yv *= gz;
        g_ypreT[(size_t)d * M_TOT + b * SEQ + t] = yv;
    }
}

// ---------------- launch ----------------
extern "C" void kernel_launch(void* const* d_in, const int* in_sizes, int n_in,
                              void* d_out, int out_size)
{
    const float* x      = (const float*)d_in[0];
    const float* W_in   = (const float*)d_in[1];
    const float* conv_w = (const float*)d_in[2];
    const float* conv_b = (const float*)d_in[3];
    const float* W_x    = (const float*)d_in[4];
    const float* W_dt   = (const float*)d_in[5];
    const float* b_dt   = (const float*)d_in[6];
    const float* A_log  = (const float*)d_in[7];
    const float* Dp     = (const float*)d_in[8];
    const float* W_out  = (const float*)d_in[9];
    float* out = (float*)d_out;

    float *x32, *Win32, *Wx32, *Wdt32, *Wout32, *xz, *xconv32, *xdbl, *deltaT, *ypre;
    cudaGetSymbolAddress((void**)&x32,    g_x32);
    cudaGetSymbolAddress((void**)&Win32,  g_Win32);
    cudaGetSymbolAddress((void**)&Wx32,   g_Wx32);
    cudaGetSymbolAddress((void**)&Wdt32,  g_Wdt32);
    cudaGetSymbolAddress((void**)&Wout32, g_Wout32);
    cudaGetSymbolAddress((void**)&xz,     g_xz);
    cudaGetSymbolAddress((void**)&xconv32,g_xconv32);
    cudaGetSymbolAddress((void**)&xdbl,   g_xdbl);
    cudaGetSymbolAddress((void**)&deltaT, g_deltaT);
    cudaGetSymbolAddress((void**)&ypre,   g_ypre);

    cudaFuncSetAttribute(mmagemm<false,false>, cudaFuncAttributeMaxDynamicSharedMemorySize, GSMEM);
    cudaFuncSetAttribute(mmagemm<true,true>,   cudaFuncAttributeMaxDynamicSharedMemorySize, GSMEM);
    const int scan_smem = (2 * SEQ + 16 * 2 * WPAD) * sizeof(float);
    cudaFuncSetAttribute(scan_kernel, cudaFuncAttributeMaxDynamicSharedMemorySize, scan_smem);

    // 0) tf32 pre-rounding
    round_copy_kernel<<<(M_TOT * DM / 4 + 255) / 256, 256>>>(x, x32, M_TOT * DM / 4);
    round_copy_kernel<<<(XZ_LD * DM / 4 + 255) / 256, 256>>>(W_in, Win32, XZ_LD * DM / 4);
    round_copy_kernel<<<(DI * DI / 4 + 255) / 256, 256>>>(W_dt, Wdt32, DI * DI / 4);
    round_copy_kernel<<<(DM * DI / 4 + 255) / 256, 256>>>(W_out, Wout32, DM * DI / 4);
    pad_wx_kernel<<<(NX_PAD * DI / 4 + 255) / 256, 256>>>(W_x);

    // 1) xz = x @ W_in^T    [1024, 3072]
    mmagemm<false,false><<<dim3(XZ_LD / 128, M_TOT / 128), 128, GSMEM>>>(
        x32, DM, Win32, DM, nullptr, xz, XZ_LD, DM, XZ_LD);

    // 2) conv + silu -> xconvT (fp32) + xconv32 (tf32)
    conv_silu_T_kernel<<<dim3(SEQ / 128, DI / 32, BATCH), dim3(32, 8)>>>(conv_w, conv_b);

    // 2b) silu(z) transposed
    siluz_T_kernel<<<dim3(M_TOT / 32, DI / 32), dim3(32, 8)>>>();

    // 3) x_dbl = x_conv @ W_x^T   [1024, 1568] (N padded 1664)
    mmagemm<false,false><<<dim3(NX_PAD / 128, M_TOT / 128), 128, GSMEM>>>(
        xconv32, DI, Wx32, DI, nullptr, xdbl, XDBL_LD, DI, XDBL_LD);

    // 3b) pack B, C transposed
    pack_bc_kernel<<<(2 * DS * M_TOT) / 256, 256>>>();

    // 4) deltaT = softplus(delta_raw @ W_dt^T + b_dt), stored transposed
    mmagemm<true,true><<<dim3(DI / 128, M_TOT / 128), 128, GSMEM>>>(
        xdbl, XDBL_LD, Wdt32, DI, b_dt, deltaT, M_TOT, DI, DI);

    // 5) fused scan
    scan_kernel<<<dim3(DI, BATCH), 512, scan_smem>>>(A_log, Dp);

    // 5b) ypreT -> ypre row-major, tf32-rounded
    transpose_round_kernel<<<dim3(M_TOT / 32, DI / 32), dim3(32, 8)>>>();

    // 6) out = ypre @ W_out^T   [1024, 768]
    mmagemm<false,false><<<dim3(DM / 128, M_TOT / 128), 128, GSMEM>>>(
        ypre, DI, Wout32, DI, nullptr, out, DM, DI, DM);
}

// round 6
// speedup vs baseline: 2.9006x; 1.1704x over previous
#include <cuda_runtime.h>
#include <math.h>
#include <stdint.h>

// ---------------- problem constants ----------------
#define BATCH   2
#define SEQ     512
#define DM      768
#define DI      1536
#define DS      16
#define M_TOT   (BATCH*SEQ)   // 1024
#define XZ_LD   (2*DI)        // 3072
#define XDBL_LD (DI + 2*DS)   // 1568
#define NX_PAD  1664

// ---------------- scratch ----------------
__device__ float g_x32    [M_TOT * DM];      // tf32-rounded x
__device__ float g_Win32  [XZ_LD * DM];
__device__ float g_Wx32   [NX_PAD * DI];
__device__ float g_Wdt32  [DI * DI];
__device__ float g_Wout32 [DM * DI];
__device__ float g_xin    [M_TOT * DI];      // x_inner (GEMM1 out, fp32)
__device__ float g_zT     [DI * M_TOT];      // silu(z) transposed
__device__ float g_xconvT [DI * M_TOT];      // [d][bt] fp32 (scan)
__device__ float g_xconv32[M_TOT * DI];      // [bt][d] tf32 (GEMM2 A)
__device__ float g_xdbl   [M_TOT * DI];      // delta_raw (GEMM2 out, fp32)
__device__ float g_BT     [DS * M_TOT];
__device__ float g_CT2    [DS * M_TOT];
__device__ float g_deltaT [DI * M_TOT];      // softplus'd delta, [d][bt]
__device__ float g_ypreT  [DI * M_TOT];      // [d][bt] tf32-rounded

// ---------------- helpers ----------------
__device__ __forceinline__ float softplusf(float x) {
    if (x > 20.f) return x;
    return log1pf(expf(x));
}
__device__ __forceinline__ float siluf(float x) {
    return x / (1.f + expf(-x));
}
__device__ __forceinline__ float tf32r(float x) {
    uint32_t u;
    asm("cvt.rna.tf32.f32 %0, %1;" : "=r"(u) : "f"(x));
    return __uint_as_float(u);
}
__device__ __forceinline__ void cpa16(uint32_t dst, const float* src) {
    asm volatile("cp.async.cg.shared.global [%0], [%1], 16;\n" :: "r"(dst), "l"(src));
}
__device__ __forceinline__ void cpa_commit() {
    asm volatile("cp.async.commit_group;\n" ::: "memory");
}
__device__ __forceinline__ void mma_tf32(float* c, const uint32_t* a, const uint32_t* b) {
    asm volatile(
        "mma.sync.aligned.m16n8k8.row.col.f32.tf32.tf32.f32 "
        "{%0,%1,%2,%3}, {%4,%5,%6,%7}, {%8,%9}, {%0,%1,%2,%3};"
        : "+f"(c[0]), "+f"(c[1]), "+f"(c[2]), "+f"(c[3])
        : "r"(a[0]), "r"(a[1]), "r"(a[2]), "r"(a[3]), "r"(b[0]), "r"(b[1]));
}

// ---------------- mma.sync tf32 GEMM ----------------
// C[1024, N] = A @ W^T ; A row-major [1024,K] (or col-major [K,1024] if ACOL),
// W row-major [N,K]. 128 threads (4 warps), 3-stage cp.async pipeline.
// EPI: 0 plain store, 1 softplus+bias+transposed (deltaT),
//      2 split x_inner|silu(z)->zT, 3 split xdbl|BT|CT2.
#define GST 3
#define AROWF 20

template<int BM, int BN, int WR, int WC, int EPI, bool ACOL>
__global__ __launch_bounds__(128)
void mmagemm(const float* __restrict__ A, int lda,
             const float* __restrict__ W, int ldw,
             const float* __restrict__ bias,
             float* __restrict__ C, int ldc, int K)
{
    constexpr int WM = BM / WR, WN = BN / WC;
    constexpr int MT = WM / 16, NT = WN / 8;
    constexpr int ACROW = BM + 8;
    constexpr int ASZ = ACOL ? 16 * ACROW : BM * AROWF;
    constexpr int BSZ = BN * AROWF;
    constexpr int STG = ASZ + BSZ;

    extern __shared__ __align__(16) float smem[];
    const int tid = threadIdx.x, warp = tid >> 5, lane = tid & 31;
    const int bm = blockIdx.y * BM, bn = blockIdx.x * BN;
    const int wm = (warp % WR) * WM, wn = (warp / WR) * WN;
    const uint32_t sbase = (uint32_t)__cvta_generic_to_shared(smem);

    float acc[MT][NT][4];
#pragma unroll
    for (int i = 0; i < MT; i++)
#pragma unroll
        for (int j = 0; j < NT; j++)
#pragma unroll
            for (int k = 0; k < 4; k++) acc[i][j][k] = 0.f;

    const int nIter = K / 16;

    auto load_stage = [&](int s, int kt) {
        const uint32_t aB = sbase + (uint32_t)s * STG * 4;
        const uint32_t bB = aB + ASZ * 4;
        if (ACOL) {
#pragma unroll
            for (int p = 0; p < (16 * (BM / 4)) / 128; p++) {
                const int chunk = tid + p * 128;
                const int krow = chunk / (BM / 4);
                const int mch = chunk % (BM / 4);
                cpa16(aB + (uint32_t)(krow * ACROW + mch * 4) * 4,
                      A + (size_t)(kt * 16 + krow) * lda + bm + mch * 4);
            }
        } else {
#pragma unroll
            for (int p = 0; p < BM / 32; p++) {
                const int row = (tid >> 2) + p * 32;
                const int ch = tid & 3;
                cpa16(aB + (uint32_t)(row * AROWF + ch * 4) * 4,
                      A + (size_t)(bm + row) * lda + kt * 16 + ch * 4);
            }
        }
#pragma unroll
        for (int p = 0; p < BN / 32; p++) {
            const int row = (tid >> 2) + p * 32;
            const int ch = tid & 3;
            cpa16(bB + (uint32_t)(row * AROWF + ch * 4) * 4,
                  W + (size_t)(bn + row) * ldw + kt * 16 + ch * 4);
        }
    };

    load_stage(0, 0); cpa_commit();
    load_stage(1, 1); cpa_commit();

    for (int it = 0; it < nIter; it++) {
        asm volatile("cp.async.wait_group 1;\n" ::: "memory");
        __syncthreads();

        const float* As = smem + (size_t)(it % GST) * STG;
        const float* Ws = As + ASZ;

#pragma unroll
        for (int ks = 0; ks < 2; ks++) {
            const int k0 = ks * 8;
            uint32_t af[MT][4];
#pragma unroll
            for (int mt = 0; mt < MT; mt++) {
                const int ar = wm + mt * 16 + (lane >> 2);
                const int ac = k0 + (lane & 3);
                if (ACOL) {
                    af[mt][0] = __float_as_uint(As[ac * ACROW + ar]);
                    af[mt][1] = __float_as_uint(As[ac * ACROW + ar + 8]);
                    af[mt][2] = __float_as_uint(As[(ac + 4) * ACROW + ar]);
                    af[mt][3] = __float_as_uint(As[(ac + 4) * ACROW + ar + 8]);
                } else {
                    af[mt][0] = __float_as_uint(As[ar * AROWF + ac]);
                    af[mt][1] = __float_as_uint(As[(ar + 8) * AROWF + ac]);
                    af[mt][2] = __float_as_uint(As[ar * AROWF + ac + 4]);
                    af[mt][3] = __float_as_uint(As[(ar + 8) * AROWF + ac + 4]);
                }
            }
#pragma unroll
            for (int nt = 0; nt < NT; nt++) {
                const int br = wn + nt * 8 + (lane >> 2);
                const int bc = k0 + (lane & 3);
                uint32_t bf[2];
                bf[0] = __float_as_uint(Ws[br * AROWF + bc]);
                bf[1] = __float_as_uint(Ws[br * AROWF + bc + 4]);
#pragma unroll
                for (int mt = 0; mt < MT; mt++)
                    mma_tf32(acc[mt][nt], af[mt], bf);
            }
        }

        __syncthreads();
        if (it + 2 < nIter) load_stage((it + 2) % GST, it + 2);
        cpa_commit();
    }

    // ---- epilogue ----
#pragma unroll
    for (int mt = 0; mt < MT; mt++) {
        const int row = bm + wm + mt * 16 + (lane >> 2);
#pragma unroll
        for (int nt = 0; nt < NT; nt++) {
            const int col = bn + wn + nt * 8 + (lane & 3) * 2;
            const float v0 = acc[mt][nt][0], v1 = acc[mt][nt][1];
            const float v2 = acc[mt][nt][2], v3 = acc[mt][nt][3];
            if (EPI == 0) {
                *(float2*)(C + (size_t)row * ldc + col)       = make_float2(v0, v1);
                *(float2*)(C + (size_t)(row + 8) * ldc + col) = make_float2(v2, v3);
            } else if (EPI == 1) {
                const float b0 = bias[col], b1 = bias[col + 1];
                C[(size_t)col * ldc + row]            = softplusf(v0 + b0);
                C[(size_t)(col + 1) * ldc + row]      = softplusf(v1 + b1);
                C[(size_t)col * ldc + row + 8]        = softplusf(v2 + b0);
                C[(size_t)(col + 1) * ldc + row + 8]  = softplusf(v3 + b1);
            } else if (EPI == 2) {
                if (col < DI) {
                    *(float2*)(g_xin + (size_t)row * DI + col)       = make_float2(v0, v1);
                    *(float2*)(g_xin + (size_t)(row + 8) * DI + col) = make_float2(v2, v3);
                } else {
                    const int dd = col - DI;
                    g_zT[(size_t)dd * M_TOT + row]           = siluf(v0);
                    g_zT[(size_t)(dd + 1) * M_TOT + row]     = siluf(v1);
                    g_zT[(size_t)dd * M_TOT + row + 8]       = siluf(v2);
                    g_zT[(size_t)(dd + 1) * M_TOT + row + 8] = siluf(v3);
                }
            } else {  // EPI == 3
                if (col < DI) {
                    *(float2*)(g_xdbl + (size_t)row * DI + col)       = make_float2(v0, v1);
                    *(float2*)(g_xdbl + (size_t)(row + 8) * DI + col) = make_float2(v2, v3);
                } else if (col < DI + DS) {
                    const int nn = col - DI;
                    g_BT[(size_t)nn * M_TOT + row]           = v0;
                    g_BT[(size_t)(nn + 1) * M_TOT + row]     = v1;
                    g_BT[(size_t)nn * M_TOT + row + 8]       = v2;
                    g_BT[(size_t)(nn + 1) * M_TOT + row + 8] = v3;
                } else if (col < DI + 2 * DS) {
                    const int nn = col - DI - DS;
                    g_CT2[(size_t)nn * M_TOT + row]           = v0;
                    g_CT2[(size_t)(nn + 1) * M_TOT + row]     = v1;
                    g_CT2[(size_t)nn * M_TOT + row + 8]       = v2;
                    g_CT2[(size_t)(nn + 1) * M_TOT + row + 8] = v3;
                }
            }
        }
    }
}

// ---------------- merged tf32 pre-rounding ----------------
#define NX4    (M_TOT * DM / 4)
#define NWIN4  (XZ_LD * DM / 4)
#define NWDT4  (DI * DI / 4)
#define NWOUT4 (DM * DI / 4)
#define NTOT4  (NX4 + NWIN4 + NWDT4 + NWOUT4)

__global__ __launch_bounds__(256)
void round_all_kernel(const float* __restrict__ x, const float* __restrict__ win,
                      const float* __restrict__ wdt, const float* __restrict__ wout)
{
    int i = blockIdx.x * 256 + threadIdx.x;
    if (i >= NTOT4) return;
    const float4* src;
    float4* dst;
    if (i < NX4)                      { src = (const float4*)x;    dst = (float4*)g_x32; }
    else if ((i -= NX4) < NWIN4)      { src = (const float4*)win;  dst = (float4*)g_Win32; }
    else if ((i -= NWIN4) < NWDT4)    { src = (const float4*)wdt;  dst = (float4*)g_Wdt32; }
    else                              { i -= NWDT4; src = (const float4*)wout; dst = (float4*)g_Wout32; }
    float4 v = src[i];
    v.x = tf32r(v.x); v.y = tf32r(v.y); v.z = tf32r(v.z); v.w = tf32r(v.w);
    dst[i] = v;
}

__global__ __launch_bounds__(256)
void pad_wx_kernel(const float* __restrict__ Wx)
{
    const int i = blockIdx.x * 256 + threadIdx.x;
    if (i >= NX_PAD * DI / 4) return;
    const int n  = i / (DI / 4);
    const int k4 = i % (DI / 4);
    float4 v = make_float4(0.f, 0.f, 0.f, 0.f);
    if (n < XDBL_LD) {
        float4 s = ((const float4*)Wx)[(size_t)n * (DI / 4) + k4];
        v.x = tf32r(s.x); v.y = tf32r(s.y); v.z = tf32r(s.z); v.w = tf32r(s.w);
    }
    ((float4*)g_Wx32)[(size_t)n * (DI / 4) + k4] = v;
}

// ---------------- depthwise causal conv + bias + SiLU -> both layouts ------
__global__ __launch_bounds__(256)
void conv_silu_T_kernel(const float* __restrict__ conv_w, const float* __restrict__ conv_b)
{
    __shared__ float s[32][133];
    __shared__ float r[128][33];
    const int t0 = blockIdx.x * 128;
    const int d0 = blockIdx.y * 32;
    const int b  = blockIdx.z;

    for (int tt = threadIdx.y; tt < 131; tt += 8) {
        const int gt = t0 - 3 + tt;
        float v = 0.f;
        if (gt >= 0)
            v = g_xin[(size_t)(b * SEQ + gt) * DI + d0 + threadIdx.x];
        s[threadIdx.x][tt] = v;
    }
    __syncthreads();

    for (int dd = threadIdx.y; dd < 32; dd += 8) {
        const int d = d0 + dd;
        const float w0 = conv_w[d * 4 + 0];
        const float w1 = conv_w[d * 4 + 1];
        const float w2 = conv_w[d * 4 + 2];
        const float w3 = conv_w[d * 4 + 3];
        const float cb = conv_b[d];
#pragma unroll
        for (int tc = 0; tc < 4; tc++) {
            const int tl = tc * 32 + threadIdx.x;
            float acc = cb;
            acc = fmaf(s[dd][tl + 0], w0, acc);
            acc = fmaf(s[dd][tl + 1], w1, acc);
            acc = fmaf(s[dd][tl + 2], w2, acc);
            acc = fmaf(s[dd][tl + 3], w3, acc);
            const float v = siluf(acc);
            g_xconvT[(size_t)d * M_TOT + b * SEQ + t0 + tl] = v;
            r[tl][dd] = v;
        }
    }
    __syncthreads();
    for (int tt = threadIdx.y; tt < 128; tt += 8)
        g_xconv32[(size_t)(b * SEQ + t0 + tt) * DI + d0 + threadIdx.x] =
            tf32r(r[tt][threadIdx.x]);
}

// ---------------- fused selective scan (EXACT reference tree) ----------------
// Grid (DI, BATCH), 512 threads = 16 warps; warp n owns state n.
// The reference's parallel_scan_log is NOT an inclusive scan (its down-sweep
// skips the identity insertion), so we replicate its up/down-sweep tree
// EXACTLY, in linear space. Lane owns 16 contiguous timesteps:
//   levels 0-3 are lane-local (register tree on c[16], v[16]);
//   levels 4-8 touch only element 15 of each lane (shfl tree across lanes).
__global__ __launch_bounds__(512)
void scan_kernel(const float* __restrict__ A_log, const float* __restrict__ Dp)
{
    __shared__ float ss[16][520];
    const int d = blockIdx.x, b = blockIdx.y;
    const int tid = threadIdx.x, warp = tid >> 5, lane = tid & 31;
    const int n = warp;
    const float a = -expf(A_log[d * DS + n]);
    const size_t cbase = (size_t)d * M_TOT + b * SEQ;
    const size_t nbase = (size_t)n * M_TOT + b * SEQ;
    const int t0 = lane * 16;

    float c[16], v[16];
#pragma unroll
    for (int q = 0; q < 4; q++) {
        const float4 d4 = *(const float4*)(g_deltaT + cbase + t0 + q * 4);
        const float4 x4 = *(const float4*)(g_xconvT + cbase + t0 + q * 4);
        const float4 b4 = *(const float4*)(g_BT + nbase + t0 + q * 4);
        const float dv[4] = {d4.x, d4.y, d4.z, d4.w};
        const float xv[4] = {x4.x, x4.y, x4.z, x4.w};
        const float bv[4] = {b4.x, b4.y, b4.z, b4.w};
#pragma unroll
        for (int i = 0; i < 4; i++) {
            c[q * 4 + i] = expf(dv[i] * a) + 1e-12f;
            v[q * 4 + i] = fabsf(dv[i] * bv[i] * xv[i]) + 1e-12f;
        }
    }

    // up-sweep levels 0..3 (lane-local)
#pragma unroll
    for (int lev = 0; lev < 4; lev++) {
        const int half = 1 << lev;
#pragma unroll
        for (int r = 2 * half - 1; r < 16; r += 2 * half) {
            v[r] = v[r - half] + c[r] * v[r];
            c[r] = c[r - half] * c[r];
        }
    }

    // up-sweep levels 4..8 (cross-lane on element 15)
    float C15 = c[15], V15 = v[15];
#pragma unroll
    for (int dd = 1; dd <= 16; dd <<= 1) {
        const float cl = __shfl_up_sync(0xffffffffu, C15, dd);
        const float vl = __shfl_up_sync(0xffffffffu, V15, dd);
        if ((lane & (2 * dd - 1)) == (2 * dd - 1)) {
            V15 = vl + C15 * V15;
            C15 = cl * C15;
        }
    }

    // down-sweep levels 8..4 (cross-lane on element 15); gather both shfls
    // BEFORE updating so left/right use pre-level values (numpy semantics).
#pragma unroll
    for (int dd = 16; dd >= 1; dd >>= 1) {
        const float vl = __shfl_up_sync(0xffffffffu, V15, dd);
        const float vr = __shfl_down_sync(0xffffffffu, V15, dd);
        const int m = lane & (2 * dd - 1);
        float nv = V15;
        if (m == 2 * dd - 1) nv = vl + C15 * V15;   // right node
        else if (m == dd - 1) nv = vr;              // left node <- old right
        V15 = nv;
    }
    c[15] = C15;
    v[15] = V15;

    // down-sweep levels 3..0 (lane-local)
#pragma unroll
    for (int lev = 3; lev >= 0; lev--) {
        const int half = 1 << lev;
#pragma unroll
        for (int r = 2 * half - 1; r < 16; r += 2 * half) {
            const float tmp = v[r];
            v[r] = v[r - half] + c[r] * v[r];
            v[r - half] = tmp;
        }
    }

    // multiply by C, stage per-state rows to smem
#pragma unroll
    for (int q = 0; q < 4; q++) {
        const float4 c4 = *(const float4*)(g_CT2 + nbase + t0 + q * 4);
        float4 o;
        o.x = v[q * 4 + 0] * c4.x;
        o.y = v[q * 4 + 1] * c4.y;
        o.z = v[q * 4 + 2] * c4.z;
        o.w = v[q * 4 + 3] * c4.w;
        *(float4*)&ss[warp][t0 + q * 4] = o;
    }
    __syncthreads();

    // reduce over 16 states + epilogue
    float acc = 0.f;
#pragma unroll
    for (int w = 0; w < 16; w++) acc += ss[w][tid];
    const float xct = g_xconvT[cbase + tid];
    const float gz  = g_zT[cbase + tid];
    const float yv  = fmaf(xct, Dp[d], acc) * gz;
    g_ypreT[cbase + tid] = tf32r(yv);
}

// ---------------- launch ----------------
extern "C" void kernel_launch(void* const* d_in, const int* in_sizes, int n_in,
                              void* d_out, int out_size)
{
    const float* x      = (const float*)d_in[0];
    const float* W_in   = (const float*)d_in[1];
    const float* conv_w = (const float*)d_in[2];
    const float* conv_b = (const float*)d_in[3];
    const float* W_x    = (const float*)d_in[4];
    const float* W_dt   = (const float*)d_in[5];
    const float* b_dt   = (const float*)d_in[6];
    const float* A_log  = (const float*)d_in[7];
    const float* Dp     = (const float*)d_in[8];
    const float* W_out  = (const float*)d_in[9];
    float* out = (float*)d_out;

    float *x32, *Win32, *Wx32, *Wdt32, *Wout32, *xconv32, *xdbl, *deltaT, *ypreT;
    cudaGetSymbolAddress((void**)&x32,    g_x32);
    cudaGetSymbolAddress((void**)&Win32,  g_Win32);
    cudaGetSymbolAddress((void**)&Wx32,   g_Wx32);
    cudaGetSymbolAddress((void**)&Wdt32,  g_Wdt32);
    cudaGetSymbolAddress((void**)&Wout32, g_Wout32);
    cudaGetSymbolAddress((void**)&xconv32,g_xconv32);
    cudaGetSymbolAddress((void**)&xdbl,   g_xdbl);
    cudaGetSymbolAddress((void**)&deltaT, g_deltaT);
    cudaGetSymbolAddress((void**)&ypreT,  g_ypreT);

    const int SM1 = GST * (128 * AROWF + 128 * AROWF) * 4;   // 61440
    const int SM2 = GST * (64 * AROWF + 128 * AROWF) * 4;    // 46080
    const int SM4 = GST * (16 * 72 + 128 * AROWF) * 4;       // 44544
    cudaFuncSetAttribute((const void*)mmagemm<128,128,2,2,2,false>, cudaFuncAttributeMaxDynamicSharedMemorySize, SM1);
    cudaFuncSetAttribute((const void*)mmagemm<64,128,1,4,3,false>,  cudaFuncAttributeMaxDynamicSharedMemorySize, SM2);
    cudaFuncSetAttribute((const void*)mmagemm<64,128,1,4,1,false>,  cudaFuncAttributeMaxDynamicSharedMemorySize, SM2);
    cudaFuncSetAttribute((const void*)mmagemm<64,128,1,4,0,true>,   cudaFuncAttributeMaxDynamicSharedMemorySize, SM4);

    // 0) tf32 pre-rounding (x, W_in, W_dt, W_out merged) + W_x pad
    round_all_kernel<<<(NTOT4 + 255) / 256, 256>>>(x, W_in, W_dt, W_out);
    pad_wx_kernel<<<(NX_PAD * DI / 4 + 255) / 256, 256>>>(W_x);

    // 1) xz = x @ W_in^T ; x_inner -> g_xin, z -> silu -> g_zT
    mmagemm<128,128,2,2,2,false><<<dim3(XZ_LD / 128, M_TOT / 128), 128, SM1>>>(
        x32, DM, Win32, DM, nullptr, nullptr, 0, DM);

    // 2) conv + silu -> xconvT (fp32) + xconv32 (tf32)
    conv_silu_T_kernel<<<dim3(SEQ / 128, DI / 32, BATCH), dim3(32, 8)>>>(conv_w, conv_b);

    // 3) x_dbl = x_conv @ W_x^T ; delta_raw -> xdbl, B -> BT, C -> CT2
    mmagemm<64,128,1,4,3,false><<<dim3(NX_PAD / 128, M_TOT / 64), 128, SM2>>>(
        xconv32, DI, Wx32, DI, nullptr, nullptr, 0, DI);

    // 4) deltaT = softplus(delta_raw @ W_dt^T + b_dt), transposed store
    mmagemm<64,128,1,4,1,false><<<dim3(DI / 128, M_TOT / 64), 128, SM2>>>(
        xdbl, DI, Wdt32, DI, b_dt, deltaT, M_TOT, DI);

    // 5) fused selective scan (exact reference tree) -> ypreT (tf32-rounded)
    scan_kernel<<<dim3(DI, BATCH), 512>>>(A_log, Dp);

    // 6) out = ypre @ W_out^T (A read column-major from ypreT)
    mmagemm<64,128,1,4,0,true><<<dim3(DM / 128, M_TOT / 64), 128, SM4>>>(
        ypreT, M_TOT, Wout32, DI, nullptr, out, DM, DI);
}

// round 8
// speedup vs baseline: 3.7333x; 1.2871x over previous
#include <cuda_runtime.h>
#include <cuda_fp16.h>
#include <math.h>
#include <stdint.h>

// ---------------- problem constants ----------------
#define BATCH   2
#define SEQ     512
#define DM      768
#define DI      1536
#define DS      16
#define M_TOT   (BATCH*SEQ)   // 1024
#define XZ_LD   (2*DI)        // 3072
#define XDBL_LD (DI + 2*DS)   // 1568
#define NX_PAD  1664

// ---------------- scratch ----------------
__device__ __half g_xh    [M_TOT * DM];      // half x
__device__ __half g_Winh  [XZ_LD * DM];
__device__ __half g_Wxh   [NX_PAD * DI];
__device__ __half g_Wdth  [DI * DI];
__device__ __half g_xconvh[M_TOT * DI];      // [bt][d] half (G2 A)
__device__ __half g_xdblh [M_TOT * DI];      // delta_raw half (G3 A)
__device__ float  g_Wout32[DM * DI];         // tf32-rounded (G4 W)
__device__ float  g_xin   [M_TOT * DI];      // x_inner fp32 (conv input)
__device__ float  g_zT    [DI * M_TOT];      // silu(z) transposed
__device__ float  g_xconvT[DI * M_TOT];      // [d][bt] fp32 (scan)
__device__ float  g_BT    [DS * M_TOT];
__device__ float  g_CT2   [DS * M_TOT];
__device__ float  g_deltaT[DI * M_TOT];      // softplus'd delta [d][bt]
__device__ float  g_ypreT [DI * M_TOT];      // [d][bt] tf32-rounded

// ---------------- helpers ----------------
__device__ __forceinline__ float softplusf(float x) {
    if (x > 20.f) return x;
    return log1pf(expf(x));
}
__device__ __forceinline__ float siluf(float x) {
    return x / (1.f + expf(-x));
}
__device__ __forceinline__ float tf32r(float x) {
    uint32_t u;
    asm("cvt.rna.tf32.f32 %0, %1;" : "=r"(u) : "f"(x));
    return __uint_as_float(u);
}
__device__ __forceinline__ void cpa16(uint32_t dst, const void* src) {
    asm volatile("cp.async.cg.shared.global [%0], [%1], 16;\n" :: "r"(dst), "l"(src));
}
__device__ __forceinline__ void cpa_commit() {
    asm volatile("cp.async.commit_group;\n" ::: "memory");
}
__device__ __forceinline__ void mma_f16(float* c, const uint32_t* a, const uint32_t* b) {
    asm volatile(
        "mma.sync.aligned.m16n8k16.row.col.f32.f16.f16.f32 "
        "{%0,%1,%2,%3}, {%4,%5,%6,%7}, {%8,%9}, {%0,%1,%2,%3};"
        : "+f"(c[0]), "+f"(c[1]), "+f"(c[2]), "+f"(c[3])
        : "r"(a[0]), "r"(a[1]), "r"(a[2]), "r"(a[3]), "r"(b[0]), "r"(b[1]));
}
__device__ __forceinline__ void mma_tf32(float* c, const uint32_t* a, const uint32_t* b) {
    asm volatile(
        "mma.sync.aligned.m16n8k8.row.col.f32.tf32.tf32.f32 "
        "{%0,%1,%2,%3}, {%4,%5,%6,%7}, {%8,%9}, {%0,%1,%2,%3};"
        : "+f"(c[0]), "+f"(c[1]), "+f"(c[2]), "+f"(c[3])
        : "r"(a[0]), "r"(a[1]), "r"(a[2]), "r"(a[3]), "r"(b[0]), "r"(b[1]));
}

// ---------------- fp16 GEMM: act(A @ W^T) ----------------
// A row-major [1024,K] half, W row-major [N,K] half. 128x128x32 tile,
// 128 threads (4 warps of 64x64), 3-stage cp.async.
// EPI: 1 softplus+bias -> f32 transposed (deltaT)
//      2 split: x_inner->g_xin f32 | silu(z)->g_zT f32
//      3 split: delta_raw->g_xdblh half | B->g_BT | C->g_CT2
#define GSTH 3
#define AROWH 40                               // 32 halves + 8 pad
#define HSTG_B (2 * 128 * AROWH * 2)           // 20480 B per stage
#define HSMEM  (GSTH * HSTG_B)                 // 61440 B

template<int EPI>
__global__ __launch_bounds__(128)
void hgemm(const __half* __restrict__ A, int lda,
           const __half* __restrict__ W, int ldw,
           const float* __restrict__ bias,
           float* __restrict__ C, int ldc, int K)
{
    extern __shared__ __align__(16) char smem[];
    const int tid = threadIdx.x, warp = tid >> 5, lane = tid & 31;
    const int bm = blockIdx.y * 128, bn = blockIdx.x * 128;
    const int wm = (warp & 1) * 64, wn = (warp >> 1) * 64;
    const uint32_t sbase = (uint32_t)__cvta_generic_to_shared(smem);

    float acc[4][8][4];
#pragma unroll
    for (int i = 0; i < 4; i++)
#pragma unroll
        for (int j = 0; j < 8; j++)
#pragma unroll
            for (int k = 0; k < 4; k++) acc[i][j][k] = 0.f;

    const int nIter = K / 32;
    const int lrow = tid >> 2, lch = tid & 3;

    auto load_stage = [&](int s, int kt) {
        const uint32_t aB = sbase + (uint32_t)s * HSTG_B;
        const uint32_t bB = aB + 128 * AROWH * 2;
#pragma unroll
        for (int p = 0; p < 4; p++) {
            const int row = lrow + p * 32;
            cpa16(aB + (uint32_t)(row * AROWH + lch * 8) * 2,
                  A + (size_t)(bm + row) * lda + kt * 32 + lch * 8);
            cpa16(bB + (uint32_t)(row * AROWH + lch * 8) * 2,
                  W + (size_t)(bn + row) * ldw + kt * 32 + lch * 8);
        }
    };

    load_stage(0, 0); cpa_commit();
    load_stage(1, 1); cpa_commit();

    for (int it = 0; it < nIter; it++) {
        asm volatile("cp.async.wait_group 1;\n" ::: "memory");
        __syncthreads();

        const uint32_t* As32 = (const uint32_t*)(smem + (size_t)(it % GSTH) * HSTG_B);
        const uint32_t* Bs32 = As32 + 128 * AROWH / 2;

#pragma unroll
        for (int ks = 0; ks < 2; ks++) {
            const int kw = ks * 8 + (lane & 3);
            uint32_t af[4][4];
#pragma unroll
            for (int mt = 0; mt < 4; mt++) {
                const int ar = wm + mt * 16 + (lane >> 2);
                af[mt][0] = As32[ar * 20 + kw];
                af[mt][1] = As32[(ar + 8) * 20 + kw];
                af[mt][2] = As32[ar * 20 + kw + 4];
                af[mt][3] = As32[(ar + 8) * 20 + kw + 4];
            }
#pragma unroll
            for (int nt = 0; nt < 8; nt++) {
                const int br = wn + nt * 8 + (lane >> 2);
                uint32_t bf[2];
                bf[0] = Bs32[br * 20 + kw];
                bf[1] = Bs32[br * 20 + kw + 4];
#pragma unroll
                for (int mt = 0; mt < 4; mt++)
                    mma_f16(acc[mt][nt], af[mt], bf);
            }
        }

        __syncthreads();
        if (it + 2 < nIter) load_stage((it + 2) % GSTH, it + 2);
        cpa_commit();
    }

    // ---- epilogue ----
#pragma unroll
    for (int mt = 0; mt < 4; mt++) {
        const int row = bm + wm + mt * 16 + (lane >> 2);
#pragma unroll
        for (int nt = 0; nt < 8; nt++) {
            const int col = bn + wn + nt * 8 + (lane & 3) * 2;
            const float v0 = acc[mt][nt][0], v1 = acc[mt][nt][1];
            const float v2 = acc[mt][nt][2], v3 = acc[mt][nt][3];
            if (EPI == 1) {
                const float b0 = bias[col], b1 = bias[col + 1];
                C[(size_t)col * ldc + row]            = softplusf(v0 + b0);
                C[(size_t)(col + 1) * ldc + row]      = softplusf(v1 + b1);
                C[(size_t)col * ldc + row + 8]        = softplusf(v2 + b0);
                C[(size_t)(col + 1) * ldc + row + 8]  = softplusf(v3 + b1);
            } else if (EPI == 2) {
                if (col < DI) {
                    *(float2*)(g_xin + (size_t)row * DI + col)       = make_float2(v0, v1);
                    *(float2*)(g_xin + (size_t)(row + 8) * DI + col) = make_float2(v2, v3);
                } else {
                    const int dd = col - DI;
                    g_zT[(size_t)dd * M_TOT + row]           = siluf(v0);
                    g_zT[(size_t)(dd + 1) * M_TOT + row]     = siluf(v1);
                    g_zT[(size_t)dd * M_TOT + row + 8]       = siluf(v2);
                    g_zT[(size_t)(dd + 1) * M_TOT + row + 8] = siluf(v3);
                }
            } else {  // EPI == 3
                if (col < DI) {
                    *(__half2*)(g_xdblh + (size_t)row * DI + col)       = __floats2half2_rn(v0, v1);
                    *(__half2*)(g_xdblh + (size_t)(row + 8) * DI + col) = __floats2half2_rn(v2, v3);
                } else if (col < DI + DS) {
                    const int nn = col - DI;
                    g_BT[(size_t)nn * M_TOT + row]           = v0;
                    g_BT[(size_t)(nn + 1) * M_TOT + row]     = v1;
                    g_BT[(size_t)nn * M_TOT + row + 8]       = v2;
                    g_BT[(size_t)(nn + 1) * M_TOT + row + 8] = v3;
                } else if (col < DI + 2 * DS) {
                    const int nn = col - DI - DS;
                    g_CT2[(size_t)nn * M_TOT + row]           = v0;
                    g_CT2[(size_t)(nn + 1) * M_TOT + row]     = v1;
                    g_CT2[(size_t)nn * M_TOT + row + 8]       = v2;
                    g_CT2[(size_t)(nn + 1) * M_TOT + row + 8] = v3;
                }
            }
        }
    }
}

// ---------------- tf32 ACOL GEMM (G4 only): out = ypreT^T @ Wout^T ---------
// A stored [K][1024] f32 (col-major m), W row-major [N,K] f32 (tf32-rounded).
// 64x128 tile, 4 warps of 64x32, BK=16, 3-stage cp.async.
#define ACROW 72
#define T4_ASZ (16 * ACROW)
#define T4_BSZ (128 * 20)
#define T4_STG (T4_ASZ + T4_BSZ)
#define T4SMEM (3 * T4_STG * 4)        // 44544 B

__global__ __launch_bounds__(128)
void tgemm_acol(const float* __restrict__ A, int lda,
                const float* __restrict__ W, int ldw,
                float* __restrict__ C, int ldc, int K)
{
    extern __shared__ __align__(16) float smemf[];
    const int tid = threadIdx.x, warp = tid >> 5, lane = tid & 31;
    const int bm = blockIdx.y * 64, bn = blockIdx.x * 128;
    const int wn = warp * 32;
    const uint32_t sbase = (uint32_t)__cvta_generic_to_shared(smemf);

    float acc[4][4][4];
#pragma unroll
    for (int i = 0; i < 4; i++)
#pragma unroll
        for (int j = 0; j < 4; j++)
#pragma unroll
            for (int k = 0; k < 4; k++) acc[i][j][k] = 0.f;

    const int nIter = K / 16;

    auto load_stage = [&](int s, int kt) {
        const uint32_t aB = sbase + (uint32_t)s * T4_STG * 4;
        const uint32_t bB = aB + T4_ASZ * 4;
#pragma unroll
        for (int p = 0; p < 2; p++) {
            const int chunk = tid + p * 128;
            const int krow = chunk >> 4, mch = chunk & 15;
            cpa16(aB + (uint32_t)(krow * ACROW + mch * 4) * 4,
                  A + (size_t)(kt * 16 + krow) * lda + bm + mch * 4);
        }
#pragma unroll
        for (int p = 0; p < 4; p++) {
            const int row = (tid >> 2) + p * 32, ch = tid & 3;
            cpa16(bB + (uint32_t)(row * 20 + ch * 4) * 4,
                  W + (size_t)(bn + row) * ldw + kt * 16 + ch * 4);
        }
    };

    load_stage(0, 0); cpa_commit();
    load_stage(1, 1); cpa_commit();

    for (int it = 0; it < nIter; it++) {
        asm volatile("cp.async.wait_group 1;\n" ::: "memory");
        __syncthreads();

        const float* As = smemf + (size_t)(it % 3) * T4_STG;
        const float* Ws = As + T4_ASZ;

#pragma unroll
        for (int ks = 0; ks < 2; ks++) {
            const int k0 = ks * 8;
            const int ac = k0 + (lane & 3);
            uint32_t af[4][4];
#pragma unroll
            for (int mt = 0; mt < 4; mt++) {
                const int ar = mt * 16 + (lane >> 2);
                af[mt][0] = __float_as_uint(As[ac * ACROW + ar]);
                af[mt][1] = __float_as_uint(As[ac * ACROW + ar + 8]);
                af[mt][2] = __float_as_uint(As[(ac + 4) * ACROW + ar]);
                af[mt][3] = __float_as_uint(As[(ac + 4) * ACROW + ar + 8]);
            }
#pragma unroll
            for (int nt = 0; nt < 4; nt++) {
                const int br = wn + nt * 8 + (lane >> 2);
                const int bc = k0 + (lane & 3);
                uint32_t bf[2];
                bf[0] = __float_as_uint(Ws[br * 20 + bc]);
                bf[1] = __float_as_uint(Ws[br * 20 + bc + 4]);
#pragma unroll
                for (int mt = 0; mt < 4; mt++)
                    mma_tf32(acc[mt][nt], af[mt], bf);
            }
        }

        __syncthreads();
        if (it + 2 < nIter) load_stage((it + 2) % 3, it + 2);
        cpa_commit();
    }

#pragma unroll
    for (int mt = 0; mt < 4; mt++) {
        const int row = bm + mt * 16 + (lane >> 2);
#pragma unroll
        for (int nt = 0; nt < 4; nt++) {
            const int col = bn + wn + nt * 8 + (lane & 3) * 2;
            *(float2*)(C + (size_t)row * ldc + col)       = make_float2(acc[mt][nt][0], acc[mt][nt][1]);
            *(float2*)(C + (size_t)(row + 8) * ldc + col) = make_float2(acc[mt][nt][2], acc[mt][nt][3]);
        }
    }
}

// ---------------- merged pre-pass: half conversions + Wout tf32 ----------
#define NX4    (M_TOT * DM / 4)
#define NWIN4  (XZ_LD * DM / 4)
#define NWDT4  (DI * DI / 4)
#define NWXP4  (NX_PAD * DI / 4)
#define NWOUT4 (DM * DI / 4)
#define NTOT4  (NX4 + NWIN4 + NWDT4 + NWXP4 + NWOUT4)

__device__ __forceinline__ void cvt_h4(const float* src, __half* dst, int i) {
    float4 v = ((const float4*)src)[i];
    ((__half2*)dst)[i * 2]     = __floats2half2_rn(v.x, v.y);
    ((__half2*)dst)[i * 2 + 1] = __floats2half2_rn(v.z, v.w);
}

__global__ __launch_bounds__(256)
void prepass_kernel(const float* __restrict__ x, const float* __restrict__ win,
                    const float* __restrict__ wdt, const float* __restrict__ wx,
                    const float* __restrict__ wout)
{
    int i = blockIdx.x * 256 + threadIdx.x;
    if (i >= NTOT4) return;
    if (i < NX4)                    { cvt_h4(x, g_xh, i); return; }
    if ((i -= NX4) < NWIN4)         { cvt_h4(win, g_Winh, i); return; }
    if ((i -= NWIN4) < NWDT4)       { cvt_h4(wdt, g_Wdth, i); return; }
    if ((i -= NWDT4) < NWXP4) {
        const int n  = i / (DI / 4);
        const int k4 = i % (DI / 4);
        float4 v = make_float4(0.f, 0.f, 0.f, 0.f);
        if (n < XDBL_LD) v = ((const float4*)wx)[(size_t)n * (DI / 4) + k4];
        ((__half2*)g_Wxh)[i * 2]     = __floats2half2_rn(v.x, v.y);
        ((__half2*)g_Wxh)[i * 2 + 1] = __floats2half2_rn(v.z, v.w);
        return;
    }
    i -= NWXP4;
    float4 v = ((const float4*)wout)[i];
    v.x = tf32r(v.x); v.y = tf32r(v.y); v.z = tf32r(v.z); v.w = tf32r(v.w);
    ((float4*)g_Wout32)[i] = v;
}

// ---------------- depthwise causal conv + bias + SiLU -> both layouts ------
__global__ __launch_bounds__(256)
void conv_silu_T_kernel(const float* __restrict__ conv_w, const float* __restrict__ conv_b)
{
    __shared__ float s[32][133];
    __shared__ float r[128][33];
    const int t0 = blockIdx.x * 128;
    const int d0 = blockIdx.y * 32;
    const int b  = blockIdx.z;

    for (int tt = threadIdx.y; tt < 131; tt += 8) {
        const int gt = t0 - 3 + tt;
        float v = 0.f;
        if (gt >= 0)
            v = g_xin[(size_t)(b * SEQ + gt) * DI + d0 + threadIdx.x];
        s[threadIdx.x][tt] = v;
    }
    __syncthreads();

    for (int dd = threadIdx.y; dd < 32; dd += 8) {
        const int d = d0 + dd;
        const float w0 = conv_w[d * 4 + 0];
        const float w1 = conv_w[d * 4 + 1];
        const float w2 = conv_w[d * 4 + 2];
        const float w3 = conv_w[d * 4 + 3];
        const float cb = conv_b[d];
#pragma unroll
        for (int tc = 0; tc < 4; tc++) {
            const int tl = tc * 32 + threadIdx.x;
            float acc = cb;
            acc = fmaf(s[dd][tl + 0], w0, acc);
            acc = fmaf(s[dd][tl + 1], w1, acc);
            acc = fmaf(s[dd][tl + 2], w2, acc);
            acc = fmaf(s[dd][tl + 3], w3, acc);
            const float v = siluf(acc);
            g_xconvT[(size_t)d * M_TOT + b * SEQ + t0 + tl] = v;
            r[tl][dd] = v;
        }
    }
    __syncthreads();
    for (int tt = threadIdx.y; tt < 128; tt += 8)
        g_xconvh[(size_t)(b * SEQ + t0 + tt) * DI + d0 + threadIdx.x] =
            __float2half_rn(r[tt][threadIdx.x]);
}

// ---------------- fused selective scan (EXACT reference tree, R6 version) ----
// Grid (DI, BATCH), 512 threads = 16 warps; warp n owns state n.
__global__ __launch_bounds__(512)
void scan_kernel(const float* __restrict__ A_log, const float* __restrict__ Dp)
{
    __shared__ float ss[16][520];
    const int d = blockIdx.x, b = blockIdx.y;
    const int tid = threadIdx.x, warp = tid >> 5, lane = tid & 31;
    const int n = warp;
    const float a = -expf(A_log[d * DS + n]);
    const size_t cbase = (size_t)d * M_TOT + b * SEQ;
    const size_t nbase = (size_t)n * M_TOT + b * SEQ;
    const int t0 = lane * 16;

    float c[16], v[16];
#pragma unroll
    for (int q = 0; q < 4; q++) {
        const float4 d4 = *(const float4*)(g_deltaT + cbase + t0 + q * 4);
        const float4 x4 = *(const float4*)(g_xconvT + cbase + t0 + q * 4);
        const float4 b4 = *(const float4*)(g_BT + nbase + t0 + q * 4);
        const float dv[4] = {d4.x, d4.y, d4.z, d4.w};
        const float xv[4] = {x4.x, x4.y, x4.z, x4.w};
        const float bv[4] = {b4.x, b4.y, b4.z, b4.w};
#pragma unroll
        for (int i = 0; i < 4; i++) {
            c[q * 4 + i] = expf(dv[i] * a) + 1e-12f;
            v[q * 4 + i] = fabsf(dv[i] * bv[i] * xv[i]) + 1e-12f;
        }
    }

    // up-sweep levels 0..3 (lane-local)
#pragma unroll
    for (int lev = 0; lev < 4; lev++) {
        const int half = 1 << lev;
#pragma unroll
        for (int r = 2 * half - 1; r < 16; r += 2 * half) {
            v[r] = v[r - half] + c[r] * v[r];
            c[r] = c[r - half] * c[r];
        }
    }

    // up-sweep levels 4..8 (cross-lane on element 15)
    float C15 = c[15], V15 = v[15];
#pragma unroll
    for (int dd = 1; dd <= 16; dd <<= 1) {
        const float cl = __shfl_up_sync(0xffffffffu, C15, dd);
        const float vl = __shfl_up_sync(0xffffffffu, V15, dd);
        if ((lane & (2 * dd - 1)) == (2 * dd - 1)) {
            V15 = vl + C15 * V15;
            C15 = cl * C15;
        }
    }

    // down-sweep levels 8..4 (gather both shfls BEFORE updating)
#pragma unroll
    for (int dd = 16; dd >= 1; dd >>= 1) {
        const float vl = __shfl_up_sync(0xffffffffu, V15, dd);
        const float vr = __shfl_down_sync(0xffffffffu, V15, dd);
        const int m = lane & (2 * dd - 1);
        float nv = V15;
        if (m == 2 * dd - 1) nv = vl + C15 * V15;   // right node
        else if (m == dd - 1) nv = vr;              // left node <- old right
        V15 = nv;
    }
    c[15] = C15;
    v[15] = V15;

    // down-sweep levels 3..0 (lane-local)
#pragma unroll
    for (int lev = 3; lev >= 0; lev--) {
        const int half = 1 << lev;
#pragma unroll
        for (int r = 2 * half - 1; r < 16; r += 2 * half) {
            const float tmp = v[r];
            v[r] = v[r - half] + c[r] * v[r];
            v[r - half] = tmp;
        }
    }

    // multiply by C, stage per-state rows to smem
#pragma unroll
    for (int q = 0; q < 4; q++) {
        const float4 c4 = *(const float4*)(g_CT2 + nbase + t0 + q * 4);
        float4 o;
        o.x = v[q * 4 + 0] * c4.x;
        o.y = v[q * 4 + 1] * c4.y;
        o.z = v[q * 4 + 2] * c4.z;
        o.w = v[q * 4 + 3] * c4.w;
        *(float4*)&ss[warp][t0 + q * 4] = o;
    }
    __syncthreads();

    // reduce over 16 states + epilogue
    float acc = 0.f;
#pragma unroll
    for (int w = 0; w < 16; w++) acc += ss[w][tid];
    const float xct = g_xconvT[cbase + tid];
    const float gz  = g_zT[cbase + tid];
    const float yv  = fmaf(xct, Dp[d], acc) * gz;
    g_ypreT[cbase + tid] = tf32r(yv);
}

// ---------------- launch ----------------
extern "C" void kernel_launch(void* const* d_in, const int* in_sizes, int n_in,
                              void* d_out, int out_size)
{
    const float* x      = (const float*)d_in[0];
    const float* W_in   = (const float*)d_in[1];
    const float* conv_w = (const float*)d_in[2];
    const float* conv_b = (const float*)d_in[3];
    const float* W_x    = (const float*)d_in[4];
    const float* W_dt   = (const float*)d_in[5];
    const float* b_dt   = (const float*)d_in[6];
    const float* A_log  = (const float*)d_in[7];
    const float* Dp     = (const float*)d_in[8];
    const float* W_out  = (const float*)d_in[9];
    float* out = (float*)d_out;

    __half *xh, *Winh, *Wxh, *Wdth, *xconvh, *xdblh;
    float *Wout32, *deltaT, *ypreT;
    cudaGetSymbolAddress((void**)&xh,     g_xh);
    cudaGetSymbolAddress((void**)&Winh,   g_Winh);
    cudaGetSymbolAddress((void**)&Wxh,    g_Wxh);
    cudaGetSymbolAddress((void**)&Wdth,   g_Wdth);
    cudaGetSymbolAddress((void**)&xconvh, g_xconvh);
    cudaGetSymbolAddress((void**)&xdblh,  g_xdblh);
    cudaGetSymbolAddress((void**)&Wout32, g_Wout32);
    cudaGetSymbolAddress((void**)&deltaT, g_deltaT);
    cudaGetSymbolAddress((void**)&ypreT,  g_ypreT);

    cudaFuncSetAttribute((const void*)hgemm<1>, cudaFuncAttributeMaxDynamicSharedMemorySize, HSMEM);
    cudaFuncSetAttribute((const void*)hgemm<2>, cudaFuncAttributeMaxDynamicSharedMemorySize, HSMEM);
    cudaFuncSetAttribute((const void*)hgemm<3>, cudaFuncAttributeMaxDynamicSharedMemorySize, HSMEM);
    cudaFuncSetAttribute((const void*)tgemm_acol, cudaFuncAttributeMaxDynamicSharedMemorySize, T4SMEM);

    // 0) merged pre-pass
    prepass_kernel<<<(NTOT4 + 255) / 256, 256>>>(x, W_in, W_dt, W_x, W_out);

    // 1) xz = x @ W_in^T ; x_inner -> g_xin, z -> silu -> g_zT
    hgemm<2><<<dim3(XZ_LD / 128, M_TOT / 128), 128, HSMEM>>>(
        xh, DM, Winh, DM, nullptr, nullptr, 0, DM);

    // 2) conv + silu -> xconvT (f32) + xconvh (half)
    conv_silu_T_kernel<<<dim3(SEQ / 128, DI / 32, BATCH), dim3(32, 8)>>>(conv_w, conv_b);

    // 3) x_dbl = x_conv @ W_x^T ; delta_raw -> xdblh, B -> BT, C -> CT2
    hgemm<3><<<dim3(NX_PAD / 128, M_TOT / 128), 128, HSMEM>>>(
        xconvh, DI, Wxh, DI, nullptr, nullptr, 0, DI);

    // 4) deltaT = softplus(delta_raw @ W_dt^T + b_dt), transposed store
    hgemm<1><<<dim3(DI / 128, M_TOT / 128), 128, HSMEM>>>(
        xdblh, DI, Wdth, DI, b_dt, deltaT, M_TOT, DI);

    // 5) fused selective scan (exact reference tree) -> ypreT (tf32-rounded)
    scan_kernel<<<dim3(DI, BATCH), 512>>>(A_log, Dp);

    // 6) out = ypre @ W_out^T (tf32, A column-major via ypreT)
    tgemm_acol<<<dim3(DM / 128, M_TOT / 64), 128, T4SMEM>>>(
        ypreT, M_TOT, Wout32, DI, out, DM, DI);
}

// round 9
// speedup vs baseline: 4.3416x; 1.1629x over previous
#include <cuda_runtime.h>
#include <cuda_fp16.h>
#include <math.h>
#include <stdint.h>

// ---------------- problem constants ----------------
#define BATCH   2
#define SEQ     512
#define DM      768
#define DI      1536
#define DS      16
#define M_TOT   (BATCH*SEQ)   // 1024
#define XZ_LD   (2*DI)        // 3072
#define XDBL_LD (DI + 2*DS)   // 1568
#define NX_PAD  1664

// ---------------- scratch ----------------
__device__ __half g_xh    [M_TOT * DM];
__device__ __half g_Winh  [XZ_LD * DM];
__device__ __half g_Wxh   [NX_PAD * DI];
__device__ __half g_Wdth  [DI * DI];
__device__ __half g_xconvh[M_TOT * DI];
__device__ __half g_xdblh [M_TOT * DI];
__device__ float  g_Wout32[DM * DI];
__device__ float  g_xin   [M_TOT * DI];
__device__ float  g_zT    [DI * M_TOT];
__device__ float  g_xconvT[DI * M_TOT];
__device__ float  g_BT    [DS * M_TOT];
__device__ float  g_CT2   [DS * M_TOT];
__device__ float  g_deltaT[DI * M_TOT];
__device__ float  g_ypreT [DI * M_TOT];

// ---------------- helpers ----------------
__device__ __forceinline__ float softplusf(float x) {
    if (x > 20.f) return x;
    return log1pf(expf(x));
}
__device__ __forceinline__ float siluf(float x) {
    return x / (1.f + expf(-x));
}
__device__ __forceinline__ float tf32r(float x) {
    uint32_t u;
    asm("cvt.rna.tf32.f32 %0, %1;" : "=r"(u) : "f"(x));
    return __uint_as_float(u);
}
__device__ __forceinline__ void cpa16(uint32_t dst, const void* src) {
    asm volatile("cp.async.cg.shared.global [%0], [%1], 16;\n" :: "r"(dst), "l"(src));
}
__device__ __forceinline__ void cpa_commit() {
    asm volatile("cp.async.commit_group;\n" ::: "memory");
}
__device__ __forceinline__ void mma_f16(float* c, const uint32_t* a, const uint32_t* b) {
    asm volatile(
        "mma.sync.aligned.m16n8k16.row.col.f32.f16.f16.f32 "
        "{%0,%1,%2,%3}, {%4,%5,%6,%7}, {%8,%9}, {%0,%1,%2,%3};"
        : "+f"(c[0]), "+f"(c[1]), "+f"(c[2]), "+f"(c[3])
        : "r"(a[0]), "r"(a[1]), "r"(a[2]), "r"(a[3]), "r"(b[0]), "r"(b[1]));
}
__device__ __forceinline__ void mma_tf32(float* c, const uint32_t* a, const uint32_t* b) {
    asm volatile(
        "mma.sync.aligned.m16n8k8.row.col.f32.tf32.tf32.f32 "
        "{%0,%1,%2,%3}, {%4,%5,%6,%7}, {%8,%9}, {%0,%1,%2,%3};"
        : "+f"(c[0]), "+f"(c[1]), "+f"(c[2]), "+f"(c[3])
        : "r"(a[0]), "r"(a[1]), "r"(a[2]), "r"(a[3]), "r"(b[0]), "r"(b[1]));
}

// ---------------- fp16 GEMM: act(A @ W^T) ----------------
// A row-major [1024,K] half, W row-major [N,K] half. 128x128x32 tile,
// 256 threads = 8 warps of 32x64 (MT=2, NT=8).
// 5-stage cp.async, 3 in flight, ONE __syncthreads per k-iter
// (load target (it+3)%5 was consumed at it-2; warp skew <= 1 iter => safe).
#define GSTH 5
#define AROWH 40                               // 32 halves + 8 pad
#define HSTG_B (2 * 128 * AROWH * 2)           // 20480 B per stage
#define HSMEM  (GSTH * HSTG_B)                 // 102400 B

template<int EPI>
__global__ __launch_bounds__(256)
void hgemm(const __half* __restrict__ A, int lda,
           const __half* __restrict__ W, int ldw,
           const float* __restrict__ bias,
           float* __restrict__ C, int ldc, int K)
{
    extern __shared__ __align__(16) char smem[];
    const int tid = threadIdx.x, warp = tid >> 5, lane = tid & 31;
    const int bm = blockIdx.y * 128, bn = blockIdx.x * 128;
    const int wm = (warp & 3) * 32, wn = (warp >> 2) * 64;
    const uint32_t sbase = (uint32_t)__cvta_generic_to_shared(smem);

    float acc[2][8][4];
#pragma unroll
    for (int i = 0; i < 2; i++)
#pragma unroll
        for (int j = 0; j < 8; j++)
#pragma unroll
            for (int k = 0; k < 4; k++) acc[i][j][k] = 0.f;

    const int nIter = K / 32;

    auto load_stage = [&](int s, int kt) {
        const uint32_t aB = sbase + (uint32_t)s * HSTG_B;
        const uint32_t bB = aB + 128 * AROWH * 2;
#pragma unroll
        for (int p = 0; p < 2; p++) {
            const int idx = tid + p * 256;
            const int row = idx >> 2, ch = idx & 3;
            cpa16(aB + (uint32_t)(row * AROWH + ch * 8) * 2,
                  A + (size_t)(bm + row) * lda + kt * 32 + ch * 8);
            cpa16(bB + (uint32_t)(row * AROWH + ch * 8) * 2,
                  W + (size_t)(bn + row) * ldw + kt * 32 + ch * 8);
        }
    };

    load_stage(0, 0); cpa_commit();
    load_stage(1, 1); cpa_commit();
    load_stage(2, 2); cpa_commit();

    for (int it = 0; it < nIter; it++) {
        asm volatile("cp.async.wait_group 2;\n" ::: "memory");
        __syncthreads();

        const uint32_t* As32 = (const uint32_t*)(smem + (size_t)(it % GSTH) * HSTG_B);
        const uint32_t* Bs32 = As32 + 128 * AROWH / 2;

#pragma unroll
        for (int ks = 0; ks < 2; ks++) {
            const int kw = ks * 8 + (lane & 3);
            uint32_t af[2][4];
#pragma unroll
            for (int mt = 0; mt < 2; mt++) {
                const int ar = wm + mt * 16 + (lane >> 2);
                af[mt][0] = As32[ar * 20 + kw];
                af[mt][1] = As32[(ar + 8) * 20 + kw];
                af[mt][2] = As32[ar * 20 + kw + 4];
                af[mt][3] = As32[(ar + 8) * 20 + kw + 4];
            }
#pragma unroll
            for (int nt = 0; nt < 8; nt++) {
                const int br = wn + nt * 8 + (lane >> 2);
                uint32_t bf[2];
                bf[0] = Bs32[br * 20 + kw];
                bf[1] = Bs32[br * 20 + kw + 4];
#pragma unroll
                for (int mt = 0; mt < 2; mt++)
                    mma_f16(acc[mt][nt], af[mt], bf);
            }
        }

        if (it + 3 < nIter) load_stage((it + 3) % GSTH, it + 3);
        cpa_commit();
    }

    // ---- epilogue ----
#pragma unroll
    for (int mt = 0; mt < 2; mt++) {
        const int row = bm + wm + mt * 16 + (lane >> 2);
#pragma unroll
        for (int nt = 0; nt < 8; nt++) {
            const int col = bn + wn + nt * 8 + (lane & 3) * 2;
            const float v0 = acc[mt][nt][0], v1 = acc[mt][nt][1];
            const float v2 = acc[mt][nt][2], v3 = acc[mt][nt][3];
            if (EPI == 1) {
                const float b0 = bias[col], b1 = bias[col + 1];
                C[(size_t)col * ldc + row]            = softplusf(v0 + b0);
                C[(size_t)(col + 1) * ldc + row]      = softplusf(v1 + b1);
                C[(size_t)col * ldc + row + 8]        = softplusf(v2 + b0);
                C[(size_t)(col + 1) * ldc + row + 8]  = softplusf(v3 + b1);
            } else if (EPI == 2) {
                if (col < DI) {
                    *(float2*)(g_xin + (size_t)row * DI + col)       = make_float2(v0, v1);
                    *(float2*)(g_xin + (size_t)(row + 8) * DI + col) = make_float2(v2, v3);
                } else {
                    const int dd = col - DI;
                    g_zT[(size_t)dd * M_TOT + row]           = siluf(v0);
                    g_zT[(size_t)(dd + 1) * M_TOT + row]     = siluf(v1);
                    g_zT[(size_t)dd * M_TOT + row + 8]       = siluf(v2);
                    g_zT[(size_t)(dd + 1) * M_TOT + row + 8] = siluf(v3);
                }
            } else {  // EPI == 3
                if (col < DI) {
                    *(__half2*)(g_xdblh + (size_t)row * DI + col)       = __floats2half2_rn(v0, v1);
                    *(__half2*)(g_xdblh + (size_t)(row + 8) * DI + col) = __floats2half2_rn(v2, v3);
                } else if (col < DI + DS) {
                    const int nn = col - DI;
                    g_BT[(size_t)nn * M_TOT + row]           = v0;
                    g_BT[(size_t)(nn + 1) * M_TOT + row]     = v1;
                    g_BT[(size_t)nn * M_TOT + row + 8]       = v2;
                    g_BT[(size_t)(nn + 1) * M_TOT + row + 8] = v3;
                } else if (col < DI + 2 * DS) {
                    const int nn = col - DI - DS;
                    g_CT2[(size_t)nn * M_TOT + row]           = v0;
                    g_CT2[(size_t)(nn + 1) * M_TOT + row]     = v1;
                    g_CT2[(size_t)nn * M_TOT + row + 8]       = v2;
                    g_CT2[(size_t)(nn + 1) * M_TOT + row + 8] = v3;
                }
            }
        }
    }
}

// ---------------- tf32 ACOL GEMM (G6): out = ypreT^T @ Wout^T ---------
#define ACROW 72
#define T4_ASZ (16 * ACROW)
#define T4_BSZ (128 * 20)
#define T4_STG (T4_ASZ + T4_BSZ)
#define T4SMEM (3 * T4_STG * 4)        // 44544 B

__global__ __launch_bounds__(128)
void tgemm_acol(const float* __restrict__ A, int lda,
                const float* __restrict__ W, int ldw,
                float* __restrict__ C, int ldc, int K)
{
    extern __shared__ __align__(16) float smemf[];
    const int tid = threadIdx.x, warp = tid >> 5, lane = tid & 31;
    const int bm = blockIdx.y * 64, bn = blockIdx.x * 128;
    const int wn = warp * 32;
    const uint32_t sbase = (uint32_t)__cvta_generic_to_shared(smemf);

    float acc[4][4][4];
#pragma unroll
    for (int i = 0; i < 4; i++)
#pragma unroll
        for (int j = 0; j < 4; j++)
#pragma unroll
            for (int k = 0; k < 4; k++) acc[i][j][k] = 0.f;

    const int nIter = K / 16;

    auto load_stage = [&](int s, int kt) {
        const uint32_t aB = sbase + (uint32_t)s * T4_STG * 4;
        const uint32_t bB = aB + T4_ASZ * 4;
#pragma unroll
        for (int p = 0; p < 2; p++) {
            const int chunk = tid + p * 128;
            const int krow = chunk >> 4, mch = chunk & 15;
            cpa16(aB + (uint32_t)(krow * ACROW + mch * 4) * 4,
                  A + (size_t)(kt * 16 + krow) * lda + bm + mch * 4);
        }
#pragma unroll
        for (int p = 0; p < 4; p++) {
            const int row = (tid >> 2) + p * 32, ch = tid & 3;
            cpa16(bB + (uint32_t)(row * 20 + ch * 4) * 4,
                  W + (size_t)(bn + row) * ldw + kt * 16 + ch * 4);
        }
    };

    load_stage(0, 0); cpa_commit();
    load_stage(1, 1); cpa_commit();

    for (int it = 0; it < nIter; it++) {
        asm volatile("cp.async.wait_group 1;\n" ::: "memory");
        __syncthreads();

        const float* As = smemf + (size_t)(it % 3) * T4_STG;
        const float* Ws = As + T4_ASZ;

#pragma unroll
        for (int ks = 0; ks < 2; ks++) {
            const int k0 = ks * 8;
            const int ac = k0 + (lane & 3);
            uint32_t af[4][4];
#pragma unroll
            for (int mt = 0; mt < 4; mt++) {
                const int ar = mt * 16 + (lane >> 2);
                af[mt][0] = __float_as_uint(As[ac * ACROW + ar]);
                af[mt][1] = __float_as_uint(As[ac * ACROW + ar + 8]);
                af[mt][2] = __float_as_uint(As[(ac + 4) * ACROW + ar]);
                af[mt][3] = __float_as_uint(As[(ac + 4) * ACROW + ar + 8]);
            }
#pragma unroll
            for (int nt = 0; nt < 4; nt++) {
                const int br = wn + nt * 8 + (lane >> 2);
                const int bc = k0 + (lane & 3);
                uint32_t bf[2];
                bf[0] = __float_as_uint(Ws[br * 20 + bc]);
                bf[1] = __float_as_uint(Ws[br * 20 + bc + 4]);
#pragma unroll
                for (int mt = 0; mt < 4; mt++)
                    mma_tf32(acc[mt][nt], af[mt], bf);
            }
        }

        __syncthreads();
        if (it + 2 < nIter) load_stage((it + 2) % 3, it + 2);
        cpa_commit();
    }

#pragma unroll
    for (int mt = 0; mt < 4; mt++) {
        const int row = bm + mt * 16 + (lane >> 2);
#pragma unroll
        for (int nt = 0; nt < 4; nt++) {
            const int col = bn + wn + nt * 8 + (lane & 3) * 2;
            *(float2*)(C + (size_t)row * ldc + col)       = make_float2(acc[mt][nt][0], acc[mt][nt][1]);
            *(float2*)(C + (size_t)(row + 8) * ldc + col) = make_float2(acc[mt][nt][2], acc[mt][nt][3]);
        }
    }
}

// ---------------- merged pre-pass ----------------
#define NX4    (M_TOT * DM / 4)
#define NWIN4  (XZ_LD * DM / 4)
#define NWDT4  (DI * DI / 4)
#define NWXP4  (NX_PAD * DI / 4)
#define NWOUT4 (DM * DI / 4)
#define NTOT4  (NX4 + NWIN4 + NWDT4 + NWXP4 + NWOUT4)

__device__ __forceinline__ void cvt_h4(const float* src, __half* dst, int i) {
    float4 v = ((const float4*)src)[i];
    ((__half2*)dst)[i * 2]     = __floats2half2_rn(v.x, v.y);
    ((__half2*)dst)[i * 2 + 1] = __floats2half2_rn(v.z, v.w);
}

__global__ __launch_bounds__(256)
void prepass_kernel(const float* __restrict__ x, const float* __restrict__ win,
                    const float* __restrict__ wdt, const float* __restrict__ wx,
                    const float* __restrict__ wout)
{
    int i = blockIdx.x * 256 + threadIdx.x;
    if (i >= NTOT4) return;
    if (i < NX4)                    { cvt_h4(x, g_xh, i); return; }
    if ((i -= NX4) < NWIN4)         { cvt_h4(win, g_Winh, i); return; }
    if ((i -= NWIN4) < NWDT4)       { cvt_h4(wdt, g_Wdth, i); return; }
    if ((i -= NWDT4) < NWXP4) {
        const int n  = i / (DI / 4);
        const int k4 = i % (DI / 4);
        float4 v = make_float4(0.f, 0.f, 0.f, 0.f);
        if (n < XDBL_LD) v = ((const float4*)wx)[(size_t)n * (DI / 4) + k4];
        ((__half2*)g_Wxh)[i * 2]     = __floats2half2_rn(v.x, v.y);
        ((__half2*)g_Wxh)[i * 2 + 1] = __floats2half2_rn(v.z, v.w);
        return;
    }
    i -= NWXP4;
    float4 v = ((const float4*)wout)[i];
    v.x = tf32r(v.x); v.y = tf32r(v.y); v.z = tf32r(v.z); v.w = tf32r(v.w);
    ((float4*)g_Wout32)[i] = v;
}

// ---------------- depthwise causal conv + bias + SiLU -> both layouts ------
__global__ __launch_bounds__(256)
void conv_silu_T_kernel(const float* __restrict__ conv_w, const float* __restrict__ conv_b)
{
    __shared__ float s[32][133];
    __shared__ float r[128][33];
    const int t0 = blockIdx.x * 128;
    const int d0 = blockIdx.y * 32;
    const int b  = blockIdx.z;

    for (int tt = threadIdx.y; tt < 131; tt += 8) {
        const int gt = t0 - 3 + tt;
        float v = 0.f;
        if (gt >= 0)
            v = g_xin[(size_t)(b * SEQ + gt) * DI + d0 + threadIdx.x];
        s[threadIdx.x][tt] = v;
    }
    __syncthreads();

    for (int dd = threadIdx.y; dd < 32; dd += 8) {
        const int d = d0 + dd;
        const float w0 = conv_w[d * 4 + 0];
        const float w1 = conv_w[d * 4 + 1];
        const float w2 = conv_w[d * 4 + 2];
        const float w3 = conv_w[d * 4 + 3];
        const float cb = conv_b[d];
#pragma unroll
        for (int tc = 0; tc < 4; tc++) {
            const int tl = tc * 32 + threadIdx.x;
            float acc = cb;
            acc = fmaf(s[dd][tl + 0], w0, acc);
            acc = fmaf(s[dd][tl + 1], w1, acc);
            acc = fmaf(s[dd][tl + 2], w2, acc);
            acc = fmaf(s[dd][tl + 3], w3, acc);
            const float v = siluf(acc);
            g_xconvT[(size_t)d * M_TOT + b * SEQ + t0 + tl] = v;
            r[tl][dd] = v;
        }
    }
    __syncthreads();
    for (int tt = threadIdx.y; tt < 128; tt += 8)
        g_xconvh[(size_t)(b * SEQ + t0 + tt) * DI + d0 + threadIdx.x] =
            __float2half_rn(r[tt][threadIdx.x]);
}

// ---------------- fused selective scan (EXACT reference tree) ----------------
__global__ __launch_bounds__(512)
void scan_kernel(const float* __restrict__ A_log, const float* __restrict__ Dp)
{
    __shared__ float ss[16][520];
    const int d = blockIdx.x, b = blockIdx.y;
    const int tid = threadIdx.x, warp = tid >> 5, lane = tid & 31;
    const int n = warp;
    const float a = -expf(A_log[d * DS + n]);
    const size_t cbase = (size_t)d * M_TOT + b * SEQ;
    const size_t nbase = (size_t)n * M_TOT + b * SEQ;
    const int t0 = lane * 16;

    float c[16], v[16];
#pragma unroll
    for (int q = 0; q < 4; q++) {
        const float4 d4 = *(const float4*)(g_deltaT + cbase + t0 + q * 4);
        const float4 x4 = *(const float4*)(g_xconvT + cbase + t0 + q * 4);
        const float4 b4 = *(const float4*)(g_BT + nbase + t0 + q * 4);
        const float dv[4] = {d4.x, d4.y, d4.z, d4.w};
        const float xv[4] = {x4.x, x4.y, x4.z, x4.w};
        const float bv[4] = {b4.x, b4.y, b4.z, b4.w};
#pragma unroll
        for (int i = 0; i < 4; i++) {
            c[q * 4 + i] = expf(dv[i] * a) + 1e-12f;
            v[q * 4 + i] = fabsf(dv[i] * bv[i] * xv[i]) + 1e-12f;
        }
    }

    // up-sweep levels 0..3 (lane-local)
#pragma unroll
    for (int lev = 0; lev < 4; lev++) {
        const int half = 1 << lev;
#pragma unroll
        for (int r = 2 * half - 1; r < 16; r += 2 * half) {
            v[r] = v[r - half] + c[r] * v[r];
            c[r] = c[r - half] * c[r];
        }
    }

    // up-sweep levels 4..8 (cross-lane on element 15)
    float C15 = c[15], V15 = v[15];
#pragma unroll
    for (int dd = 1; dd <= 16; dd <<= 1) {
        const float cl = __shfl_up_sync(0xffffffffu, C15, dd);
        const float vl = __shfl_up_sync(0xffffffffu, V15, dd);
        if ((lane & (2 * dd - 1)) == (2 * dd - 1)) {
            V15 = vl + C15 * V15;
            C15 = cl * C15;
        }
    }

    // down-sweep levels 8..4 (gather both shfls BEFORE updating)
#pragma unroll
    for (int dd = 16; dd >= 1; dd >>= 1) {
        const float vl = __shfl_up_sync(0xffffffffu, V15, dd);
        const float vr = __shfl_down_sync(0xffffffffu, V15, dd);
        const int m = lane & (2 * dd - 1);
        float nv = V15;
        if (m == 2 * dd - 1) nv = vl + C15 * V15;
        else if (m == dd - 1) nv = vr;
        V15 = nv;
    }
    c[15] = C15;
    v[15] = V15;

    // down-sweep levels 3..0 (lane-local)
#pragma unroll
    for (int lev = 3; lev >= 0; lev--) {
        const int half = 1 << lev;
#pragma unroll
        for (int r = 2 * half - 1; r < 16; r += 2 * half) {
            const float tmp = v[r];
            v[r] = v[r - half] + c[r] * v[r];
            v[r - half] = tmp;
        }
    }

    // multiply by C, stage per-state rows to smem
#pragma unroll
    for (int q = 0; q < 4; q++) {
        const float4 c4 = *(const float4*)(g_CT2 + nbase + t0 + q * 4);
        float4 o;
        o.x = v[q * 4 + 0] * c4.x;
        o.y = v[q * 4 + 1] * c4.y;
        o.z = v[q * 4 + 2] * c4.z;
        o.w = v[q * 4 + 3] * c4.w;
        *(float4*)&ss[warp][t0 + q * 4] = o;
    }
    __syncthreads();

    // reduce over 16 states + epilogue
    float acc = 0.f;
#pragma unroll
    for (int w = 0; w < 16; w++) acc += ss[w][tid];
    const float xct = g_xconvT[cbase + tid];
    const float gz  = g_zT[cbase + tid];
    const float yv  = fmaf(xct, Dp[d], acc) * gz;
    g_ypreT[cbase + tid] = tf32r(yv);
}

// ---------------- launch ----------------
extern "C" void kernel_launch(void* const* d_in, const int* in_sizes, int n_in,
                              void* d_out, int out_size)
{
    const float* x      = (const float*)d_in[0];
    const float* W_in   = (const float*)d_in[1];
    const float* conv_w = (const float*)d_in[2];
    const float* conv_b = (const float*)d_in[3];
    const float* W_x    = (const float*)d_in[4];
    const float* W_dt   = (const float*)d_in[5];
    const float* b_dt   = (const float*)d_in[6];
    const float* A_log  = (const float*)d_in[7];
    const float* Dp     = (const float*)d_in[8];
    const float* W_out  = (const float*)d_in[9];
    float* out = (float*)d_out;

    __half *xh, *Winh, *Wxh, *Wdth, *xconvh, *xdblh;
    float *Wout32, *deltaT, *ypreT;
    cudaGetSymbolAddress((void**)&xh,     g_xh);
    cudaGetSymbolAddress((void**)&Winh,   g_Winh);
    cudaGetSymbolAddress((void**)&Wxh,    g_Wxh);
    cudaGetSymbolAddress((void**)&Wdth,   g_Wdth);
    cudaGetSymbolAddress((void**)&xconvh, g_xconvh);
    cudaGetSymbolAddress((void**)&xdblh,  g_xdblh);
    cudaGetSymbolAddress((void**)&Wout32, g_Wout32);
    cudaGetSymbolAddress((void**)&deltaT, g_deltaT);
    cudaGetSymbolAddress((void**)&ypreT,  g_ypreT);

    cudaFuncSetAttribute((const void*)hgemm<1>, cudaFuncAttributeMaxDynamicSharedMemorySize, HSMEM);
    cudaFuncSetAttribute((const void*)hgemm<2>, cudaFuncAttributeMaxDynamicSharedMemorySize, HSMEM);
    cudaFuncSetAttribute((const void*)hgemm<3>, cudaFuncAttributeMaxDynamicSharedMemorySize, HSMEM);
    cudaFuncSetAttribute((const void*)tgemm_acol, cudaFuncAttributeMaxDynamicSharedMemorySize, T4SMEM);

    // 0) merged pre-pass
    prepass_kernel<<<(NTOT4 + 255) / 256, 256>>>(x, W_in, W_dt, W_x, W_out);

    // 1) xz = x @ W_in^T ; x_inner -> g_xin, z -> silu -> g_zT
    hgemm<2><<<dim3(XZ_LD / 128, M_TOT / 128), 256, HSMEM>>>(
        xh, DM, Winh, DM, nullptr, nullptr, 0, DM);

    // 2) conv + silu -> xconvT (f32) + xconvh (half)
    conv_silu_T_kernel<<<dim3(SEQ / 128, DI / 32, BATCH), dim3(32, 8)>>>(conv_w, conv_b);

    // 3) x_dbl = x_conv @ W_x^T ; delta_raw -> xdblh, B -> BT, C -> CT2
    hgemm<3><<<dim3(NX_PAD / 128, M_TOT / 128), 256, HSMEM>>>(
        xconvh, DI, Wxh, DI, nullptr, nullptr, 0, DI);

    // 4) deltaT = softplus(delta_raw @ W_dt^T + b_dt), transposed store
    hgemm<1><<<dim3(DI / 128, M_TOT / 128), 256, HSMEM>>>(
        xdblh, DI, Wdth, DI, b_dt, deltaT, M_TOT, DI);

    // 5) fused selective scan (exact reference tree) -> ypreT (tf32-rounded)
    scan_kernel<<<dim3(DI, BATCH), 512>>>(A_log, Dp);

    // 6) out = ypre @ W_out^T (tf32, A column-major via ypreT)
    tgemm_acol<<<dim3(DM / 128, M_TOT / 64), 128, T4SMEM>>>(
        ypreT, M_TOT, Wout32, DI, out, DM, DI);
}

// round 10
// speedup vs baseline: 4.3912x; 1.0114x over previous
#include <cuda_runtime.h>
#include <cuda_fp16.h>
#include <math.h>
#include <stdint.h>

// ---------------- problem constants ----------------
#define BATCH   2
#define SEQ     512
#define DM      768
#define DI      1536
#define DS      16
#define M_TOT   (BATCH*SEQ)   // 1024
#define XZ_LD   (2*DI)        // 3072
#define XDBL_LD (DI + 2*DS)   // 1568
#define NX_PAD  1664

// ---------------- scratch ----------------
__device__ __half g_xh    [M_TOT * DM];
__device__ __half g_Winh  [XZ_LD * DM];
__device__ __half g_Wxh   [NX_PAD * DI];
__device__ __half g_Wdth  [DI * DI];
__device__ __half g_xconvh[M_TOT * DI];
__device__ __half g_xdblh [M_TOT * DI];
__device__ float  g_Wout32[DM * DI];
__device__ float  g_xin   [M_TOT * DI];
__device__ float  g_zT    [DI * M_TOT];
__device__ float  g_xconvT[DI * M_TOT];
__device__ float  g_BT    [DS * M_TOT];
__device__ float  g_CT2   [DS * M_TOT];
__device__ float  g_deltaT[DI * M_TOT];
__device__ float  g_ypreT [DI * M_TOT];

// ---------------- helpers ----------------
__device__ __forceinline__ float softplusf(float x) {
    if (x > 20.f) return x;
    return log1pf(expf(x));
}
__device__ __forceinline__ float siluf(float x) {
    return x / (1.f + expf(-x));
}
__device__ __forceinline__ float tf32r(float x) {
    uint32_t u;
    asm("cvt.rna.tf32.f32 %0, %1;" : "=r"(u) : "f"(x));
    return __uint_as_float(u);
}
__device__ __forceinline__ void cpa16(uint32_t dst, const void* src) {
    asm volatile("cp.async.cg.shared.global [%0], [%1], 16;\n" :: "r"(dst), "l"(src));
}
__device__ __forceinline__ void cpa_commit() {
    asm volatile("cp.async.commit_group;\n" ::: "memory");
}
__device__ __forceinline__ void mma_f16(float* c, const uint32_t* a, const uint32_t* b) {
    asm volatile(
        "mma.sync.aligned.m16n8k16.row.col.f32.f16.f16.f32 "
        "{%0,%1,%2,%3}, {%4,%5,%6,%7}, {%8,%9}, {%0,%1,%2,%3};"
        : "+f"(c[0]), "+f"(c[1]), "+f"(c[2]), "+f"(c[3])
        : "r"(a[0]), "r"(a[1]), "r"(a[2]), "r"(a[3]), "r"(b[0]), "r"(b[1]));
}
__device__ __forceinline__ void mma_tf32(float* c, const uint32_t* a, const uint32_t* b) {
    asm volatile(
        "mma.sync.aligned.m16n8k8.row.col.f32.tf32.tf32.f32 "
        "{%0,%1,%2,%3}, {%4,%5,%6,%7}, {%8,%9}, {%0,%1,%2,%3};"
        : "+f"(c[0]), "+f"(c[1]), "+f"(c[2]), "+f"(c[3])
        : "r"(a[0]), "r"(a[1]), "r"(a[2]), "r"(a[3]), "r"(b[0]), "r"(b[1]));
}

// ---------------- fp16 GEMM: act(A @ W^T) ----------------
// A row-major [1024,K] half, W row-major [N,K] half. 64x128x32 tile,
// 256 threads = 8 warps of 32x32 (2x4 warp grid), 2 CTAs/SM.
// 5-stage cp.async, 3 in flight, ONE __syncthreads per k-iter.
#define GSTH 5
#define AROWH 40                               // 32 halves + 8 pad
#define HSTG_B ((64 + 128) * AROWH * 2)        // 15360 B per stage
#define HSMEM  (GSTH * HSTG_B)                 // 76800 B

template<int EPI>
__global__ __launch_bounds__(256, 2)
void hgemm(const __half* __restrict__ A, int lda,
           const __half* __restrict__ W, int ldw,
           const float* __restrict__ bias,
           float* __restrict__ C, int ldc, int K)
{
    extern __shared__ __align__(16) char smem[];
    const int tid = threadIdx.x, warp = tid >> 5, lane = tid & 31;
    const int bm = blockIdx.y * 64, bn = blockIdx.x * 128;
    const int wm = (warp & 1) * 32, wn = (warp >> 1) * 32;
    const uint32_t sbase = (uint32_t)__cvta_generic_to_shared(smem);

    float acc[2][4][4];
#pragma unroll
    for (int i = 0; i < 2; i++)
#pragma unroll
        for (int j = 0; j < 4; j++)
#pragma unroll
            for (int k = 0; k < 4; k++) acc[i][j][k] = 0.f;

    const int nIter = K / 32;

    auto load_stage = [&](int s, int kt) {
        const uint32_t aB = sbase + (uint32_t)s * HSTG_B;
        const uint32_t bB = aB + 64 * AROWH * 2;
        // A: 64 rows x 4 chunks = 256 -> one per thread
        {
            const int row = tid >> 2, ch = tid & 3;
            cpa16(aB + (uint32_t)(row * AROWH + ch * 8) * 2,
                  A + (size_t)(bm + row) * lda + kt * 32 + ch * 8);
        }
        // B: 128 rows x 4 chunks = 512 -> two per thread
#pragma unroll
        for (int p = 0; p < 2; p++) {
            const int idx = tid + p * 256;
            const int row = idx >> 2, ch = idx & 3;
            cpa16(bB + (uint32_t)(row * AROWH + ch * 8) * 2,
                  W + (size_t)(bn + row) * ldw + kt * 32 + ch * 8);
        }
    };

    load_stage(0, 0); cpa_commit();
    load_stage(1, 1); cpa_commit();
    load_stage(2, 2); cpa_commit();

    for (int it = 0; it < nIter; it++) {
        asm volatile("cp.async.wait_group 2;\n" ::: "memory");
        __syncthreads();

        const uint32_t* As32 = (const uint32_t*)(smem + (size_t)(it % GSTH) * HSTG_B);
        const uint32_t* Bs32 = As32 + 64 * AROWH / 2;

#pragma unroll
        for (int ks = 0; ks < 2; ks++) {
            const int kw = ks * 8 + (lane & 3);
            uint32_t af[2][4];
#pragma unroll
            for (int mt = 0; mt < 2; mt++) {
                const int ar = wm + mt * 16 + (lane >> 2);
                af[mt][0] = As32[ar * 20 + kw];
                af[mt][1] = As32[(ar + 8) * 20 + kw];
                af[mt][2] = As32[ar * 20 + kw + 4];
                af[mt][3] = As32[(ar + 8) * 20 + kw + 4];
            }
#pragma unroll
            for (int nt = 0; nt < 4; nt++) {
                const int br = wn + nt * 8 + (lane >> 2);
                uint32_t bf[2];
                bf[0] = Bs32[br * 20 + kw];
                bf[1] = Bs32[br * 20 + kw + 4];
#pragma unroll
                for (int mt = 0; mt < 2; mt++)
                    mma_f16(acc[mt][nt], af[mt], bf);
            }
        }

        if (it + 3 < nIter) load_stage((it + 3) % GSTH, it + 3);
        cpa_commit();
    }

    // ---- epilogue ----
#pragma unroll
    for (int mt = 0; mt < 2; mt++) {
        const int row = bm + wm + mt * 16 + (lane >> 2);
#pragma unroll
        for (int nt = 0; nt < 4; nt++) {
            const int col = bn + wn + nt * 8 + (lane & 3) * 2;
            const float v0 = acc[mt][nt][0], v1 = acc[mt][nt][1];
            const float v2 = acc[mt][nt][2], v3 = acc[mt][nt][3];
            if (EPI == 1) {
                const float b0 = bias[col], b1 = bias[col + 1];
                C[(size_t)col * ldc + row]            = softplusf(v0 + b0);
                C[(size_t)(col + 1) * ldc + row]      = softplusf(v1 + b1);
                C[(size_t)col * ldc + row + 8]        = softplusf(v2 + b0);
                C[(size_t)(col + 1) * ldc + row + 8]  = softplusf(v3 + b1);
            } else if (EPI == 2) {
                if (col < DI) {
                    *(float2*)(g_xin + (size_t)row * DI + col)       = make_float2(v0, v1);
                    *(float2*)(g_xin + (size_t)(row + 8) * DI + col) = make_float2(v2, v3);
                } else {
                    const int dd = col - DI;
                    g_zT[(size_t)dd * M_TOT + row]           = siluf(v0);
                    g_zT[(size_t)(dd + 1) * M_TOT + row]     = siluf(v1);
                    g_zT[(size_t)dd * M_TOT + row + 8]       = siluf(v2);
                    g_zT[(size_t)(dd + 1) * M_TOT + row + 8] = siluf(v3);
                }
            } else {  // EPI == 3
                if (col < DI) {
                    *(__half2*)(g_xdblh + (size_t)row * DI + col)       = __floats2half2_rn(v0, v1);
                    *(__half2*)(g_xdblh + (size_t)(row + 8) * DI + col) = __floats2half2_rn(v2, v3);
                } else if (col < DI + DS) {
                    const int nn = col - DI;
                    g_BT[(size_t)nn * M_TOT + row]           = v0;
                    g_BT[(size_t)(nn + 1) * M_TOT + row]     = v1;
                    g_BT[(size_t)nn * M_TOT + row + 8]       = v2;
                    g_BT[(size_t)(nn + 1) * M_TOT + row + 8] = v3;
                } else if (col < DI + 2 * DS) {
                    const int nn = col - DI - DS;
                    g_CT2[(size_t)nn * M_TOT + row]           = v0;
                    g_CT2[(size_t)(nn + 1) * M_TOT + row]     = v1;
                    g_CT2[(size_t)nn * M_TOT + row + 8]       = v2;
                    g_CT2[(size_t)(nn + 1) * M_TOT + row + 8] = v3;
                }
            }
        }
    }
}

// ---------------- tf32 ACOL GEMM (G6): out = ypreT^T @ Wout^T ---------
#define ACROW 72
#define T4_ASZ (16 * ACROW)
#define T4_BSZ (128 * 20)
#define T4_STG (T4_ASZ + T4_BSZ)
#define T4SMEM (3 * T4_STG * 4)        // 44544 B

__global__ __launch_bounds__(128)
void tgemm_acol(const float* __restrict__ A, int lda,
                const float* __restrict__ W, int ldw,
                float* __restrict__ C, int ldc, int K)
{
    extern __shared__ __align__(16) float smemf[];
    const int tid = threadIdx.x, warp = tid >> 5, lane = tid & 31;
    const int bm = blockIdx.y * 64, bn = blockIdx.x * 128;
    const int wn = warp * 32;
    const uint32_t sbase = (uint32_t)__cvta_generic_to_shared(smemf);

    float acc[4][4][4];
#pragma unroll
    for (int i = 0; i < 4; i++)
#pragma unroll
        for (int j = 0; j < 4; j++)
#pragma unroll
            for (int k = 0; k < 4; k++) acc[i][j][k] = 0.f;

    const int nIter = K / 16;

    auto load_stage = [&](int s, int kt) {
        const uint32_t aB = sbase + (uint32_t)s * T4_STG * 4;
        const uint32_t bB = aB + T4_ASZ * 4;
#pragma unroll
        for (int p = 0; p < 2; p++) {
            const int chunk = tid + p * 128;
            const int krow = chunk >> 4, mch = chunk & 15;
            cpa16(aB + (uint32_t)(krow * ACROW + mch * 4) * 4,
                  A + (size_t)(kt * 16 + krow) * lda + bm + mch * 4);
        }
#pragma unroll
        for (int p = 0; p < 4; p++) {
            const int row = (tid >> 2) + p * 32, ch = tid & 3;
            cpa16(bB + (uint32_t)(row * 20 + ch * 4) * 4,
                  W + (size_t)(bn + row) * ldw + kt * 16 + ch * 4);
        }
    };

    load_stage(0, 0); cpa_commit();
    load_stage(1, 1); cpa_commit();

    for (int it = 0; it < nIter; it++) {
        asm volatile("cp.async.wait_group 1;\n" ::: "memory");
        __syncthreads();

        const float* As = smemf + (size_t)(it % 3) * T4_STG;
        const float* Ws = As + T4_ASZ;

#pragma unroll
        for (int ks = 0; ks < 2; ks++) {
            const int k0 = ks * 8;
            const int ac = k0 + (lane & 3);
            uint32_t af[4][4];
#pragma unroll
            for (int mt = 0; mt < 4; mt++) {
                const int ar = mt * 16 + (lane >> 2);
                af[mt][0] = __float_as_uint(As[ac * ACROW + ar]);
                af[mt][1] = __float_as_uint(As[ac * ACROW + ar + 8]);
                af[mt][2] = __float_as_uint(As[(ac + 4) * ACROW + ar]);
                af[mt][3] = __float_as_uint(As[(ac + 4) * ACROW + ar + 8]);
            }
#pragma unroll
            for (int nt = 0; nt < 4; nt++) {
                const int br = wn + nt * 8 + (lane >> 2);
                const int bc = k0 + (lane & 3);
                uint32_t bf[2];
                bf[0] = __float_as_uint(Ws[br * 20 + bc]);
                bf[1] = __float_as_uint(Ws[br * 20 + bc + 4]);
#pragma unroll
                for (int mt = 0; mt < 4; mt++)
                    mma_tf32(acc[mt][nt], af[mt], bf);
            }
        }

        __syncthreads();
        if (it + 2 < nIter) load_stage((it + 2) % 3, it + 2);
        cpa_commit();
    }

#pragma unroll
    for (int mt = 0; mt < 4; mt++) {
        const int row = bm + mt * 16 + (lane >> 2);
#pragma unroll
        for (int nt = 0; nt < 4; nt++) {
            const int col = bn + wn + nt * 8 + (lane & 3) * 2;
            *(float2*)(C + (size_t)row * ldc + col)       = make_float2(acc[mt][nt][0], acc[mt][nt][1]);
            *(float2*)(C + (size_t)(row + 8) * ldc + col) = make_float2(acc[mt][nt][2], acc[mt][nt][3]);
        }
    }
}

// ---------------- merged pre-pass ----------------
#define NX4    (M_TOT * DM / 4)
#define NWIN4  (XZ_LD * DM / 4)
#define NWDT4  (DI * DI / 4)
#define NWXP4  (NX_PAD * DI / 4)
#define NWOUT4 (DM * DI / 4)
#define NTOT4  (NX4 + NWIN4 + NWDT4 + NWXP4 + NWOUT4)

__device__ __forceinline__ void cvt_h4(const float* src, __half* dst, int i) {
    float4 v = ((const float4*)src)[i];
    ((__half2*)dst)[i * 2]     = __floats2half2_rn(v.x, v.y);
    ((__half2*)dst)[i * 2 + 1] = __floats2half2_rn(v.z, v.w);
}

__global__ __launch_bounds__(256)
void prepass_kernel(const float* __restrict__ x, const float* __restrict__ win,
                    const float* __restrict__ wdt, const float* __restrict__ wx,
                    const float* __restrict__ wout)
{
    int i = blockIdx.x * 256 + threadIdx.x;
    if (i >= NTOT4) return;
    if (i < NX4)                    { cvt_h4(x, g_xh, i); return; }
    if ((i -= NX4) < NWIN4)         { cvt_h4(win, g_Winh, i); return; }
    if ((i -= NWIN4) < NWDT4)       { cvt_h4(wdt, g_Wdth, i); return; }
    if ((i -= NWDT4) < NWXP4) {
        const int n  = i / (DI / 4);
        const int k4 = i % (DI / 4);
        float4 v = make_float4(0.f, 0.f, 0.f, 0.f);
        if (n < XDBL_LD) v = ((const float4*)wx)[(size_t)n * (DI / 4) + k4];
        ((__half2*)g_Wxh)[i * 2]     = __floats2half2_rn(v.x, v.y);
        ((__half2*)g_Wxh)[i * 2 + 1] = __floats2half2_rn(v.z, v.w);
        return;
    }
    i -= NWXP4;
    float4 v = ((const float4*)wout)[i];
    v.x = tf32r(v.x); v.y = tf32r(v.y); v.z = tf32r(v.z); v.w = tf32r(v.w);
    ((float4*)g_Wout32)[i] = v;
}

// ---------------- depthwise causal conv + bias + SiLU -> both layouts ------
__global__ __launch_bounds__(256)
void conv_silu_T_kernel(const float* __restrict__ conv_w, const float* __restrict__ conv_b)
{
    __shared__ float s[32][133];
    __shared__ float r[128][33];
    const int t0 = blockIdx.x * 128;
    const int d0 = blockIdx.y * 32;
    const int b  = blockIdx.z;

    for (int tt = threadIdx.y; tt < 131; tt += 8) {
        const int gt = t0 - 3 + tt;
        float v = 0.f;
        if (gt >= 0)
            v = g_xin[(size_t)(b * SEQ + gt) * DI + d0 + threadIdx.x];
        s[threadIdx.x][tt] = v;
    }
    __syncthreads();

    for (int dd = threadIdx.y; dd < 32; dd += 8) {
        const int d = d0 + dd;
        const float w0 = conv_w[d * 4 + 0];
        const float w1 = conv_w[d * 4 + 1];
        const float w2 = conv_w[d * 4 + 2];
        const float w3 = conv_w[d * 4 + 3];
        const float cb = conv_b[d];
#pragma unroll
        for (int tc = 0; tc < 4; tc++) {
            const int tl = tc * 32 + threadIdx.x;
            float acc = cb;
            acc = fmaf(s[dd][tl + 0], w0, acc);
            acc = fmaf(s[dd][tl + 1], w1, acc);
            acc = fmaf(s[dd][tl + 2], w2, acc);
            acc = fmaf(s[dd][tl + 3], w3, acc);
            const float v = siluf(acc);
            g_xconvT[(size_t)d * M_TOT + b * SEQ + t0 + tl] = v;
            r[tl][dd] = v;
        }
    }
    __syncthreads();
    for (int tt = threadIdx.y; tt < 128; tt += 8)
        g_xconvh[(size_t)(b * SEQ + t0 + tt) * DI + d0 + threadIdx.x] =
            __float2half_rn(r[tt][threadIdx.x]);
}

// ---------------- fused selective scan (EXACT reference tree) ----------------
__global__ __launch_bounds__(512)
void scan_kernel(const float* __restrict__ A_log, const float* __restrict__ Dp)
{
    __shared__ float ss[16][520];
    const int d = blockIdx.x, b = blockIdx.y;
    const int tid = threadIdx.x, warp = tid >> 5, lane = tid & 31;
    const int n = warp;
    const float a = -expf(A_log[d * DS + n]);
    const size_t cbase = (size_t)d * M_TOT + b * SEQ;
    const size_t nbase = (size_t)n * M_TOT + b * SEQ;
    const int t0 = lane * 16;

    float c[16], v[16];
#pragma unroll
    for (int q = 0; q < 4; q++) {
        const float4 d4 = *(const float4*)(g_deltaT + cbase + t0 + q * 4);
        const float4 x4 = *(const float4*)(g_xconvT + cbase + t0 + q * 4);
        const float4 b4 = *(const float4*)(g_BT + nbase + t0 + q * 4);
        const float dv[4] = {d4.x, d4.y, d4.z, d4.w};
        const float xv[4] = {x4.x, x4.y, x4.z, x4.w};
        const float bv[4] = {b4.x, b4.y, b4.z, b4.w};
#pragma unroll
        for (int i = 0; i < 4; i++) {
            c[q * 4 + i] = expf(dv[i] * a) + 1e-12f;
            v[q * 4 + i] = fabsf(dv[i] * bv[i] * xv[i]) + 1e-12f;
        }
    }

    // up-sweep levels 0..3 (lane-local)
#pragma unroll
    for (int lev = 0; lev < 4; lev++) {
        const int half = 1 << lev;
#pragma unroll
        for (int r = 2 * half - 1; r < 16; r += 2 * half) {
            v[r] = v[r - half] + c[r] * v[r];
            c[r] = c[r - half] * c[r];
        }
    }

    // up-sweep levels 4..8 (cross-lane on element 15)
    float C15 = c[15], V15 = v[15];
#pragma unroll
    for (int dd = 1; dd <= 16; dd <<= 1) {
        const float cl = __shfl_up_sync(0xffffffffu, C15, dd);
        const float vl = __shfl_up_sync(0xffffffffu, V15, dd);
        if ((lane & (2 * dd - 1)) == (2 * dd - 1)) {
            V15 = vl + C15 * V15;
            C15 = cl * C15;
        }
    }

    // down-sweep levels 8..4 (gather both shfls BEFORE updating)
#pragma unroll
    for (int dd = 16; dd >= 1; dd >>= 1) {
        const float vl = __shfl_up_sync(0xffffffffu, V15, dd);
        const float vr = __shfl_down_sync(0xffffffffu, V15, dd);
        const int m = lane & (2 * dd - 1);
        float nv = V15;
        if (m == 2 * dd - 1) nv = vl + C15 * V15;
        else if (m == dd - 1) nv = vr;
        V15 = nv;
    }
    c[15] = C15;
    v[15] = V15;

    // down-sweep levels 3..0 (lane-local)
#pragma unroll
    for (int lev = 3; lev >= 0; lev--) {
        const int half = 1 << lev;
#pragma unroll
        for (int r = 2 * half - 1; r < 16; r += 2 * half) {
            const float tmp = v[r];
            v[r] = v[r - half] + c[r] * v[r];
            v[r - half] = tmp;
        }
    }

    // multiply by C, stage per-state rows to smem
#pragma unroll
    for (int q = 0; q < 4; q++) {
        const float4 c4 = *(const float4*)(g_CT2 + nbase + t0 + q * 4);
        float4 o;
        o.x = v[q * 4 + 0] * c4.x;
        o.y = v[q * 4 + 1] * c4.y;
        o.z = v[q * 4 + 2] * c4.z;
        o.w = v[q * 4 + 3] * c4.w;
        *(float4*)&ss[warp][t0 + q * 4] = o;
    }
    __syncthreads();

    // reduce over 16 states + epilogue
    float acc = 0.f;
#pragma unroll
    for (int w = 0; w < 16; w++) acc += ss[w][tid];
    const float xct = g_xconvT[cbase + tid];
    const float gz  = g_zT[cbase + tid];
    const float yv  = fmaf(xct, Dp[d], acc) * gz;
    g_ypreT[cbase + tid] = tf32r(yv);
}

// ---------------- launch ----------------
extern "C" void kernel_launch(void* const* d_in, const int* in_sizes, int n_in,
                              void* d_out, int out_size)
{
    const float* x      = (const float*)d_in[0];
    const float* W_in   = (const float*)d_in[1];
    const float* conv_w = (const float*)d_in[2];
    const float* conv_b = (const float*)d_in[3];
    const float* W_x    = (const float*)d_in[4];
    const float* W_dt   = (const float*)d_in[5];
    const float* b_dt   = (const float*)d_in[6];
    const float* A_log  = (const float*)d_in[7];
    const float* Dp     = (const float*)d_in[8];
    const float* W_out  = (const float*)d_in[9];
    float* out = (float*)d_out;

    __half *xh, *Winh, *Wxh, *Wdth, *xconvh, *xdblh;
    float *Wout32, *deltaT, *ypreT;
    cudaGetSymbolAddress((void**)&xh,     g_xh);
    cudaGetSymbolAddress((void**)&Winh,   g_Winh);
    cudaGetSymbolAddress((void**)&Wxh,    g_Wxh);
    cudaGetSymbolAddress((void**)&Wdth,   g_Wdth);
    cudaGetSymbolAddress((void**)&xconvh, g_xconvh);
    cudaGetSymbolAddress((void**)&xdblh,  g_xdblh);
    cudaGetSymbolAddress((void**)&Wout32, g_Wout32);
    cudaGetSymbolAddress((void**)&deltaT, g_deltaT);
    cudaGetSymbolAddress((void**)&ypreT,  g_ypreT);

    cudaFuncSetAttribute((const void*)hgemm<1>, cudaFuncAttributeMaxDynamicSharedMemorySize, HSMEM);
    cudaFuncSetAttribute((const void*)hgemm<2>, cudaFuncAttributeMaxDynamicSharedMemorySize, HSMEM);
    cudaFuncSetAttribute((const void*)hgemm<3>, cudaFuncAttributeMaxDynamicSharedMemorySize, HSMEM);
    cudaFuncSetAttribute((const void*)tgemm_acol, cudaFuncAttributeMaxDynamicSharedMemorySize, T4SMEM);

    // 0) merged pre-pass
    prepass_kernel<<<(NTOT4 + 255) / 256, 256>>>(x, W_in, W_dt, W_x, W_out);

    // 1) xz = x @ W_in^T ; x_inner -> g_xin, z -> silu -> g_zT
    hgemm<2><<<dim3(XZ_LD / 128, M_TOT / 64), 256, HSMEM>>>(
        xh, DM, Winh, DM, nullptr, nullptr, 0, DM);

    // 2) conv + silu -> xconvT (f32) + xconvh (half)
    conv_silu_T_kernel<<<dim3(SEQ / 128, DI / 32, BATCH), dim3(32, 8)>>>(conv_w, conv_b);

    // 3) x_dbl = x_conv @ W_x^T ; delta_raw -> xdblh, B -> BT, C -> CT2
    hgemm<3><<<dim3(NX_PAD / 128, M_TOT / 64), 256, HSMEM>>>(
        xconvh, DI, Wxh, DI, nullptr, nullptr, 0, DI);

    // 4) deltaT = softplus(delta_raw @ W_dt^T + b_dt), transposed store
    hgemm<1><<<dim3(DI / 128, M_TOT / 64), 256, HSMEM>>>(
        xdblh, DI, Wdth, DI, b_dt, deltaT, M_TOT, DI);

    // 5) fused selective scan (exact reference tree) -> ypreT (tf32-rounded)
    scan_kernel<<<dim3(DI, BATCH), 512>>>(A_log, Dp);

    // 6) out = ypre @ W_out^T (tf32, A column-major via ypreT)
    tgemm_acol<<<dim3(DM / 128, M_TOT / 64), 128, T4SMEM>>>(
        ypreT, M_TOT, Wout32, DI, out, DM, DI);
}

// round 11
// speedup vs baseline: 4.5013x; 1.0251x over previous
#include <cuda_runtime.h>
#include <cuda_fp16.h>
#include <math.h>
#include <stdint.h>

// ---------------- problem constants ----------------
#define BATCH   2
#define SEQ     512
#define DM      768
#define DI      1536
#define DS      16
#define M_TOT   (BATCH*SEQ)   // 1024
#define XZ_LD   (2*DI)        // 3072
#define XDBL_LD (DI + 2*DS)   // 1568
#define NX_PAD  1664

// ---------------- scratch ----------------
__device__ __half g_xh    [M_TOT * DM];
__device__ __half g_Winh  [XZ_LD * DM];
__device__ __half g_Wxh   [NX_PAD * DI];
__device__ __half g_Wdth  [DI * DI];
__device__ __half g_xconvh[M_TOT * DI];
__device__ __half g_xdblh [M_TOT * DI];
__device__ float  g_Wout32[DM * DI];
__device__ float  g_xin   [M_TOT * DI];
__device__ float  g_zT    [DI * M_TOT];
__device__ float  g_xconvT[DI * M_TOT];
__device__ float  g_BT    [DS * M_TOT];
__device__ float  g_CT2   [DS * M_TOT];
__device__ float  g_deltaT[DI * M_TOT];
__device__ float  g_ypreT [DI * M_TOT];

// ---------------- helpers ----------------
__device__ __forceinline__ float softplusf(float x) {
    if (x > 20.f) return x;
    return log1pf(expf(x));
}
__device__ __forceinline__ float siluf(float x) {
    return x / (1.f + expf(-x));
}
__device__ __forceinline__ float tf32r(float x) {
    uint32_t u;
    asm("cvt.rna.tf32.f32 %0, %1;" : "=r"(u) : "f"(x));
    return __uint_as_float(u);
}
__device__ __forceinline__ void cpa16(uint32_t dst, const void* src) {
    asm volatile("cp.async.cg.shared.global [%0], [%1], 16;\n" :: "r"(dst), "l"(src));
}
__device__ __forceinline__ void cpa_commit() {
    asm volatile("cp.async.commit_group;\n" ::: "memory");
}
__device__ __forceinline__ void ldmx4(uint32_t* r, uint32_t addr) {
    asm volatile(
        "ldmatrix.sync.aligned.m8n8.x4.shared.b16 {%0,%1,%2,%3}, [%4];"
        : "=r"(r[0]), "=r"(r[1]), "=r"(r[2]), "=r"(r[3]) : "r"(addr));
}
__device__ __forceinline__ void mma_f16(float* c, const uint32_t* a, const uint32_t* b) {
    asm volatile(
        "mma.sync.aligned.m16n8k16.row.col.f32.f16.f16.f32 "
        "{%0,%1,%2,%3}, {%4,%5,%6,%7}, {%8,%9}, {%0,%1,%2,%3};"
        : "+f"(c[0]), "+f"(c[1]), "+f"(c[2]), "+f"(c[3])
        : "r"(a[0]), "r"(a[1]), "r"(a[2]), "r"(a[3]), "r"(b[0]), "r"(b[1]));
}
__device__ __forceinline__ void mma_tf32(float* c, const uint32_t* a, const uint32_t* b) {
    asm volatile(
        "mma.sync.aligned.m16n8k8.row.col.f32.tf32.tf32.f32 "
        "{%0,%1,%2,%3}, {%4,%5,%6,%7}, {%8,%9}, {%0,%1,%2,%3};"
        : "+f"(c[0]), "+f"(c[1]), "+f"(c[2]), "+f"(c[3])
        : "r"(a[0]), "r"(a[1]), "r"(a[2]), "r"(a[3]), "r"(b[0]), "r"(b[1]));
}

// ---------------- fp16 GEMM: act(A @ W^T) ----------------
// A row-major [1024,K] half, W row-major [N,K] half. 64x128x32 tile,
// 256 threads = 8 warps of 32x32, 2 CTAs/SM, ldmatrix fragment loads.
// 5-stage cp.async, 3 in flight, ONE __syncthreads per k-iter.
#define GSTH 5
#define AROWH 40                               // 32 halves + 8 pad
#define HSTG_B ((64 + 128) * AROWH * 2)        // 15360 B per stage
#define HSMEM  (GSTH * HSTG_B)                 // 76800 B

template<int EPI>
__global__ __launch_bounds__(256, 2)
void hgemm(const __half* __restrict__ A, int lda,
           const __half* __restrict__ W, int ldw,
           const float* __restrict__ bias,
           float* __restrict__ C, int ldc, int K)
{
    extern __shared__ __align__(16) char smem[];
    const int tid = threadIdx.x, warp = tid >> 5, lane = tid & 31;
    const int bm = blockIdx.y * 64, bn = blockIdx.x * 128;
    const int wm = (warp & 1) * 32, wn = (warp >> 1) * 32;
    const uint32_t sbase = (uint32_t)__cvta_generic_to_shared(smem);

    // ldmatrix lane -> source row/col within a 16x16 tile
    const int lrow8 = (lane & 7) + ((lane >> 3) & 1) * 8;  // row 0..15
    const int lk8   = (lane >> 4) * 8;                     // k 0 or 8

    float acc[2][4][4];
#pragma unroll
    for (int i = 0; i < 2; i++)
#pragma unroll
        for (int j = 0; j < 4; j++)
#pragma unroll
            for (int k = 0; k < 4; k++) acc[i][j][k] = 0.f;

    const int nIter = K / 32;

    auto load_stage = [&](int s, int kt) {
        const uint32_t aB = sbase + (uint32_t)s * HSTG_B;
        const uint32_t bB = aB + 64 * AROWH * 2;
        {
            const int row = tid >> 2, ch = tid & 3;
            cpa16(aB + (uint32_t)(row * AROWH + ch * 8) * 2,
                  A + (size_t)(bm + row) * lda + kt * 32 + ch * 8);
        }
#pragma unroll
        for (int p = 0; p < 2; p++) {
            const int idx = tid + p * 256;
            const int row = idx >> 2, ch = idx & 3;
            cpa16(bB + (uint32_t)(row * AROWH + ch * 8) * 2,
                  W + (size_t)(bn + row) * ldw + kt * 32 + ch * 8);
        }
    };

    load_stage(0, 0); cpa_commit();
    load_stage(1, 1); cpa_commit();
    load_stage(2, 2); cpa_commit();

    for (int it = 0; it < nIter; it++) {
        asm volatile("cp.async.wait_group 2;\n" ::: "memory");
        __syncthreads();

        const uint32_t stg = sbase + (uint32_t)(it % GSTH) * HSTG_B;
        const uint32_t stgB = stg + 64 * AROWH * 2;

#pragma unroll
        for (int ks = 0; ks < 2; ks++) {
            uint32_t af[2][4], bq[2][4];
#pragma unroll
            for (int mt = 0; mt < 2; mt++)
                ldmx4(af[mt],
                      stg + (uint32_t)((wm + mt * 16 + lrow8) * AROWH + ks * 16 + lk8) * 2);
#pragma unroll
            for (int nh = 0; nh < 2; nh++)
                ldmx4(bq[nh],
                      stgB + (uint32_t)((wn + nh * 16 + lrow8) * AROWH + ks * 16 + lk8) * 2);
#pragma unroll
            for (int nt = 0; nt < 4; nt++) {
                uint32_t bf[2] = { bq[nt >> 1][nt & 1], bq[nt >> 1][(nt & 1) + 2] };
#pragma unroll
                for (int mt = 0; mt < 2; mt++)
                    mma_f16(acc[mt][nt], af[mt], bf);
            }
        }

        if (it + 3 < nIter) load_stage((it + 3) % GSTH, it + 3);
        cpa_commit();
    }

    // ---- epilogue ----
#pragma unroll
    for (int mt = 0; mt < 2; mt++) {
        const int row = bm + wm + mt * 16 + (lane >> 2);
#pragma unroll
        for (int nt = 0; nt < 4; nt++) {
            const int col = bn + wn + nt * 8 + (lane & 3) * 2;
            const float v0 = acc[mt][nt][0], v1 = acc[mt][nt][1];
            const float v2 = acc[mt][nt][2], v3 = acc[mt][nt][3];
            if (EPI == 1) {
                const float b0 = bias[col], b1 = bias[col + 1];
                C[(size_t)col * ldc + row]            = softplusf(v0 + b0);
                C[(size_t)(col + 1) * ldc + row]      = softplusf(v1 + b1);
                C[(size_t)col * ldc + row + 8]        = softplusf(v2 + b0);
                C[(size_t)(col + 1) * ldc + row + 8]  = softplusf(v3 + b1);
            } else if (EPI == 2) {
                if (col < DI) {
                    *(float2*)(g_xin + (size_t)row * DI + col)       = make_float2(v0, v1);
                    *(float2*)(g_xin + (size_t)(row + 8) * DI + col) = make_float2(v2, v3);
                } else {
                    const int dd = col - DI;
                    g_zT[(size_t)dd * M_TOT + row]           = siluf(v0);
                    g_zT[(size_t)(dd + 1) * M_TOT + row]     = siluf(v1);
                    g_zT[(size_t)dd * M_TOT + row + 8]       = siluf(v2);
                    g_zT[(size_t)(dd + 1) * M_TOT + row + 8] = siluf(v3);
                }
            } else {  // EPI == 3
                if (col < DI) {
                    *(__half2*)(g_xdblh + (size_t)row * DI + col)       = __floats2half2_rn(v0, v1);
                    *(__half2*)(g_xdblh + (size_t)(row + 8) * DI + col) = __floats2half2_rn(v2, v3);
                } else if (col < DI + DS) {
                    const int nn = col - DI;
                    g_BT[(size_t)nn * M_TOT + row]           = v0;
                    g_BT[(size_t)(nn + 1) * M_TOT + row]     = v1;
                    g_BT[(size_t)nn * M_TOT + row + 8]       = v2;
                    g_BT[(size_t)(nn + 1) * M_TOT + row + 8] = v3;
                } else if (col < DI + 2 * DS) {
                    const int nn = col - DI - DS;
                    g_CT2[(size_t)nn * M_TOT + row]           = v0;
                    g_CT2[(size_t)(nn + 1) * M_TOT + row]     = v1;
                    g_CT2[(size_t)nn * M_TOT + row + 8]       = v2;
                    g_CT2[(size_t)(nn + 1) * M_TOT + row + 8] = v3;
                }
            }
        }
    }
}

// ---------------- tf32 ACOL GEMM (G6): out = ypreT^T @ Wout^T ---------
#define ACROW 72
#define T4_ASZ (16 * ACROW)
#define T4_BSZ (128 * 20)
#define T4_STG (T4_ASZ + T4_BSZ)
#define T4SMEM (3 * T4_STG * 4)        // 44544 B

__global__ __launch_bounds__(128)
void tgemm_acol(const float* __restrict__ A, int lda,
                const float* __restrict__ W, int ldw,
                float* __restrict__ C, int ldc, int K)
{
    extern __shared__ __align__(16) float smemf[];
    const int tid = threadIdx.x, warp = tid >> 5, lane = tid & 31;
    const int bm = blockIdx.y * 64, bn = blockIdx.x * 128;
    const int wn = warp * 32;
    const uint32_t sbase = (uint32_t)__cvta_generic_to_shared(smemf);

    float acc[4][4][4];
#pragma unroll
    for (int i = 0; i < 4; i++)
#pragma unroll
        for (int j = 0; j < 4; j++)
#pragma unroll
            for (int k = 0; k < 4; k++) acc[i][j][k] = 0.f;

    const int nIter = K / 16;

    auto load_stage = [&](int s, int kt) {
        const uint32_t aB = sbase + (uint32_t)s * T4_STG * 4;
        const uint32_t bB = aB + T4_ASZ * 4;
#pragma unroll
        for (int p = 0; p < 2; p++) {
            const int chunk = tid + p * 128;
            const int krow = chunk >> 4, mch = chunk & 15;
            cpa16(aB + (uint32_t)(krow * ACROW + mch * 4) * 4,
                  A + (size_t)(kt * 16 + krow) * lda + bm + mch * 4);
        }
#pragma unroll
        for (int p = 0; p < 4; p++) {
            const int row = (tid >> 2) + p * 32, ch = tid & 3;
            cpa16(bB + (uint32_t)(row * 20 + ch * 4) * 4,
                  W + (size_t)(bn + row) * ldw + kt * 16 + ch * 4);
        }
    };

    load_stage(0, 0); cpa_commit();
    load_stage(1, 1); cpa_commit();

    for (int it = 0; it < nIter; it++) {
        asm volatile("cp.async.wait_group 1;\n" ::: "memory");
        __syncthreads();

        const float* As = smemf + (size_t)(it % 3) * T4_STG;
        const float* Ws = As + T4_ASZ;

#pragma unroll
        for (int ks = 0; ks < 2; ks++) {
            const int k0 = ks * 8;
            const int ac = k0 + (lane & 3);
            uint32_t af[4][4];
#pragma unroll
            for (int mt = 0; mt < 4; mt++) {
                const int ar = mt * 16 + (lane >> 2);
                af[mt][0] = __float_as_uint(As[ac * ACROW + ar]);
                af[mt][1] = __float_as_uint(As[ac * ACROW + ar + 8]);
                af[mt][2] = __float_as_uint(As[(ac + 4) * ACROW + ar]);
                af[mt][3] = __float_as_uint(As[(ac + 4) * ACROW + ar + 8]);
            }
#pragma unroll
            for (int nt = 0; nt < 4; nt++) {
                const int br = wn + nt * 8 + (lane >> 2);
                const int bc = k0 + (lane & 3);
                uint32_t bf[2];
                bf[0] = __float_as_uint(Ws[br * 20 + bc]);
                bf[1] = __float_as_uint(Ws[br * 20 + bc + 4]);
#pragma unroll
                for (int mt = 0; mt < 4; mt++)
                    mma_tf32(acc[mt][nt], af[mt], bf);
            }
        }

        __syncthreads();
        if (it + 2 < nIter) load_stage((it + 2) % 3, it + 2);
        cpa_commit();
    }

#pragma unroll
    for (int mt = 0; mt < 4; mt++) {
        const int row = bm + mt * 16 + (lane >> 2);
#pragma unroll
        for (int nt = 0; nt < 4; nt++) {
            const int col = bn + wn + nt * 8 + (lane & 3) * 2;
            *(float2*)(C + (size_t)row * ldc + col)       = make_float2(acc[mt][nt][0], acc[mt][nt][1]);
            *(float2*)(C + (size_t)(row + 8) * ldc + col) = make_float2(acc[mt][nt][2], acc[mt][nt][3]);
        }
    }
}

// ---------------- merged pre-pass ----------------
#define NX4    (M_TOT * DM / 4)
#define NWIN4  (XZ_LD * DM / 4)
#define NWDT4  (DI * DI / 4)
#define NWXP4  (NX_PAD * DI / 4)
#define NWOUT4 (DM * DI / 4)
#define NTOT4  (NX4 + NWIN4 + NWDT4 + NWXP4 + NWOUT4)

__device__ __forceinline__ void cvt_h4(const float* src, __half* dst, int i) {
    float4 v = ((const float4*)src)[i];
    ((__half2*)dst)[i * 2]     = __floats2half2_rn(v.x, v.y);
    ((__half2*)dst)[i * 2 + 1] = __floats2half2_rn(v.z, v.w);
}

__global__ __launch_bounds__(256)
void prepass_kernel(const float* __restrict__ x, const float* __restrict__ win,
                    const float* __restrict__ wdt, const float* __restrict__ wx,
                    const float* __restrict__ wout)
{
    int i = blockIdx.x * 256 + threadIdx.x;
    if (i >= NTOT4) return;
    if (i < NX4)                    { cvt_h4(x, g_xh, i); return; }
    if ((i -= NX4) < NWIN4)         { cvt_h4(win, g_Winh, i); return; }
    if ((i -= NWIN4) < NWDT4)       { cvt_h4(wdt, g_Wdth, i); return; }
    if ((i -= NWDT4) < NWXP4) {
        const int n  = i / (DI / 4);
        const int k4 = i % (DI / 4);
        float4 v = make_float4(0.f, 0.f, 0.f, 0.f);
        if (n < XDBL_LD) v = ((const float4*)wx)[(size_t)n * (DI / 4) + k4];
        ((__half2*)g_Wxh)[i * 2]     = __floats2half2_rn(v.x, v.y);
        ((__half2*)g_Wxh)[i * 2 + 1] = __floats2half2_rn(v.z, v.w);
        return;
    }
    i -= NWXP4;
    float4 v = ((const float4*)wout)[i];
    v.x = tf32r(v.x); v.y = tf32r(v.y); v.z = tf32r(v.z); v.w = tf32r(v.w);
    ((float4*)g_Wout32)[i] = v;
}

// ---------------- depthwise causal conv + bias + SiLU -> both layouts ------
__global__ __launch_bounds__(256)
void conv_silu_T_kernel(const float* __restrict__ conv_w, const float* __restrict__ conv_b)
{
    __shared__ float s[32][133];
    __shared__ float r[128][33];
    const int t0 = blockIdx.x * 128;
    const int d0 = blockIdx.y * 32;
    const int b  = blockIdx.z;

    for (int tt = threadIdx.y; tt < 131; tt += 8) {
        const int gt = t0 - 3 + tt;
        float v = 0.f;
        if (gt >= 0)
            v = g_xin[(size_t)(b * SEQ + gt) * DI + d0 + threadIdx.x];
        s[threadIdx.x][tt] = v;
    }
    __syncthreads();

    for (int dd = threadIdx.y; dd < 32; dd += 8) {
        const int d = d0 + dd;
        const float w0 = conv_w[d * 4 + 0];
        const float w1 = conv_w[d * 4 + 1];
        const float w2 = conv_w[d * 4 + 2];
        const float w3 = conv_w[d * 4 + 3];
        const float cb = conv_b[d];
#pragma unroll
        for (int tc = 0; tc < 4; tc++) {
            const int tl = tc * 32 + threadIdx.x;
            float acc = cb;
            acc = fmaf(s[dd][tl + 0], w0, acc);
            acc = fmaf(s[dd][tl + 1], w1, acc);
            acc = fmaf(s[dd][tl + 2], w2, acc);
            acc = fmaf(s[dd][tl + 3], w3, acc);
            const float v = siluf(acc);
            g_xconvT[(size_t)d * M_TOT + b * SEQ + t0 + tl] = v;
            r[tl][dd] = v;
        }
    }
    __syncthreads();
    for (int tt = threadIdx.y; tt < 128; tt += 8)
        g_xconvh[(size_t)(b * SEQ + t0 + tt) * DI + d0 + threadIdx.x] =
            __float2half_rn(r[tt][threadIdx.x]);
}

// ---------------- fused selective scan (EXACT reference tree) ----------------
__global__ __launch_bounds__(512)
void scan_kernel(const float* __restrict__ A_log, const float* __restrict__ Dp)
{
    __shared__ float ss[16][520];
    const int d = blockIdx.x, b = blockIdx.y;
    const int tid = threadIdx.x, warp = tid >> 5, lane = tid & 31;
    const int n = warp;
    const float a = -expf(A_log[d * DS + n]);
    const size_t cbase = (size_t)d * M_TOT + b * SEQ;
    const size_t nbase = (size_t)n * M_TOT + b * SEQ;
    const int t0 = lane * 16;

    float c[16], v[16];
#pragma unroll
    for (int q = 0; q < 4; q++) {
        const float4 d4 = *(const float4*)(g_deltaT + cbase + t0 + q * 4);
        const float4 x4 = *(const float4*)(g_xconvT + cbase + t0 + q * 4);
        const float4 b4 = *(const float4*)(g_BT + nbase + t0 + q * 4);
        const float dv[4] = {d4.x, d4.y, d4.z, d4.w};
        const float xv[4] = {x4.x, x4.y, x4.z, x4.w};
        const float bv[4] = {b4.x, b4.y, b4.z, b4.w};
#pragma unroll
        for (int i = 0; i < 4; i++) {
            c[q * 4 + i] = expf(dv[i] * a) + 1e-12f;
            v[q * 4 + i] = fabsf(dv[i] * bv[i] * xv[i]) + 1e-12f;
        }
    }

    // up-sweep levels 0..3 (lane-local)
#pragma unroll
    for (int lev = 0; lev < 4; lev++) {
        const int half = 1 << lev;
#pragma unroll
        for (int r = 2 * half - 1; r < 16; r += 2 * half) {
            v[r] = v[r - half] + c[r] * v[r];
            c[r] = c[r - half] * c[r];
        }
    }

    // up-sweep levels 4..8 (cross-lane on element 15)
    float C15 = c[15], V15 = v[15];
#pragma unroll
    for (int dd = 1; dd <= 16; dd <<= 1) {
        const float cl = __shfl_up_sync(0xffffffffu, C15, dd);
        const float vl = __shfl_up_sync(0xffffffffu, V15, dd);
        if ((lane & (2 * dd - 1)) == (2 * dd - 1)) {
            V15 = vl + C15 * V15;
            C15 = cl * C15;
        }
    }

    // down-sweep levels 8..4 (gather both shfls BEFORE updating)
#pragma unroll
    for (int dd = 16; dd >= 1; dd >>= 1) {
        const float vl = __shfl_up_sync(0xffffffffu, V15, dd);
        const float vr = __shfl_down_sync(0xffffffffu, V15, dd);
        const int m = lane & (2 * dd - 1);
        float nv = V15;
        if (m == 2 * dd - 1) nv = vl + C15 * V15;
        else if (m == dd - 1) nv = vr;
        V15 = nv;
    }
    c[15] = C15;
    v[15] = V15;

    // down-sweep levels 3..0 (lane-local)
#pragma unroll
    for (int lev = 3; lev >= 0; lev--) {
        const int half = 1 << lev;
#pragma unroll
        for (int r = 2 * half - 1; r < 16; r += 2 * half) {
            const float tmp = v[r];
            v[r] = v[r - half] + c[r] * v[r];
            v[r - half] = tmp;
        }
    }

    // multiply by C, stage per-state rows to smem
#pragma unroll
    for (int q = 0; q < 4; q++) {
        const float4 c4 = *(const float4*)(g_CT2 + nbase + t0 + q * 4);
        float4 o;
        o.x = v[q * 4 + 0] * c4.x;
        o.y = v[q * 4 + 1] * c4.y;
        o.z = v[q * 4 + 2] * c4.z;
        o.w = v[q * 4 + 3] * c4.w;
        *(float4*)&ss[warp][t0 + q * 4] = o;
    }
    __syncthreads();

    // reduce over 16 states + epilogue
    float acc = 0.f;
#pragma unroll
    for (int w = 0; w < 16; w++) acc += ss[w][tid];
    const float xct = g_xconvT[cbase + tid];
    const float gz  = g_zT[cbase + tid];
    const float yv  = fmaf(xct, Dp[d], acc) * gz;
    g_ypreT[cbase + tid] = tf32r(yv);
}

// ---------------- launch ----------------
extern "C" void kernel_launch(void* const* d_in, const int* in_sizes, int n_in,
                              void* d_out, int out_size)
{
    const float* x      = (const float*)d_in[0];
    const float* W_in   = (const float*)d_in[1];
    const float* conv_w = (const float*)d_in[2];
    const float* conv_b = (const float*)d_in[3];
    const float* W_x    = (const float*)d_in[4];
    const float* W_dt   = (const float*)d_in[5];
    const float* b_dt   = (const float*)d_in[6];
    const float* A_log  = (const float*)d_in[7];
    const float* Dp     = (const float*)d_in[8];
    const float* W_out  = (const float*)d_in[9];
    float* out = (float*)d_out;

    __half *xh, *Winh, *Wxh, *Wdth, *xconvh, *xdblh;
    float *Wout32, *deltaT, *ypreT;
    cudaGetSymbolAddress((void**)&xh,     g_xh);
    cudaGetSymbolAddress((void**)&Winh,   g_Winh);
    cudaGetSymbolAddress((void**)&Wxh,    g_Wxh);
    cudaGetSymbolAddress((void**)&Wdth,   g_Wdth);
    cudaGetSymbolAddress((void**)&xconvh, g_xconvh);
    cudaGetSymbolAddress((void**)&xdblh,  g_xdblh);
    cudaGetSymbolAddress((void**)&Wout32, g_Wout32);
    cudaGetSymbolAddress((void**)&deltaT, g_deltaT);
    cudaGetSymbolAddress((void**)&ypreT,  g_ypreT);

    cudaFuncSetAttribute((const void*)hgemm<1>, cudaFuncAttributeMaxDynamicSharedMemorySize, HSMEM);
    cudaFuncSetAttribute((const void*)hgemm<2>, cudaFuncAttributeMaxDynamicSharedMemorySize, HSMEM);
    cudaFuncSetAttribute((const void*)hgemm<3>, cudaFuncAttributeMaxDynamicSharedMemorySize, HSMEM);
    cudaFuncSetAttribute((const void*)tgemm_acol, cudaFuncAttributeMaxDynamicSharedMemorySize, T4SMEM);

    // 0) merged pre-pass
    prepass_kernel<<<(NTOT4 + 255) / 256, 256>>>(x, W_in, W_dt, W_x, W_out);

    // 1) xz = x @ W_in^T ; x_inner -> g_xin, z -> silu -> g_zT
    hgemm<2><<<dim3(XZ_LD / 128, M_TOT / 64), 256, HSMEM>>>(
        xh, DM, Winh, DM, nullptr, nullptr, 0, DM);

    // 2) conv + silu -> xconvT (f32) + xconvh (half)
    conv_silu_T_kernel<<<dim3(SEQ / 128, DI / 32, BATCH), dim3(32, 8)>>>(conv_w, conv_b);

    // 3) x_dbl = x_conv @ W_x^T ; delta_raw -> xdblh, B -> BT, C -> CT2
    hgemm<3><<<dim3(NX_PAD / 128, M_TOT / 64), 256, HSMEM>>>(
        xconvh, DI, Wxh, DI, nullptr, nullptr, 0, DI);

    // 4) deltaT = softplus(delta_raw @ W_dt^T + b_dt), transposed store
    hgemm<1><<<dim3(DI / 128, M_TOT / 64), 256, HSMEM>>>(
        xdblh, DI, Wdth, DI, b_dt, deltaT, M_TOT, DI);

    // 5) fused selective scan (exact reference tree) -> ypreT (tf32-rounded)
    scan_kernel<<<dim3(DI, BATCH), 512>>>(A_log, Dp);

    // 6) out = ypre @ W_out^T (tf32, A column-major via ypreT)
    tgemm_acol<<<dim3(DM / 128, M_TOT / 64), 128, T4SMEM>>>(
        ypreT, M_TOT, Wout32, DI, out, DM, DI);
}

// round 12
// speedup vs baseline: 4.5093x; 1.0018x over previous
#include <cuda_runtime.h>
#include <cuda_fp16.h>
#include <math.h>
#include <stdint.h>

// ---------------- problem constants ----------------
#define BATCH   2
#define SEQ     512
#define DM      768
#define DI      1536
#define DS      16
#define M_TOT   (BATCH*SEQ)   // 1024
#define XZ_LD   (2*DI)        // 3072
#define XDBL_LD (DI + 2*DS)   // 1568
#define NX_PAD  1664

// ---------------- scratch ----------------
__device__ __half g_xh    [M_TOT * DM];
__device__ __half g_Winh  [XZ_LD * DM];
__device__ __half g_Wxh   [NX_PAD * DI];
__device__ __half g_Wdth  [DI * DI];
__device__ __half g_xconvh[M_TOT * DI];
__device__ __half g_xdblh [M_TOT * DI];
__device__ float  g_Wout32[DM * DI];
__device__ float  g_xin   [M_TOT * DI];
__device__ float  g_zT    [DI * M_TOT];
__device__ float  g_xconvT[DI * M_TOT];
__device__ float  g_BT    [DS * M_TOT];
__device__ float  g_CT2   [DS * M_TOT];
__device__ float  g_deltaT[DI * M_TOT];
__device__ float  g_ypreT [DI * M_TOT];

// ---------------- helpers ----------------
__device__ __forceinline__ float softplusf(float x) {
    if (x > 20.f) return x;
    return log1pf(expf(x));
}
__device__ __forceinline__ float siluf(float x) {
    return x / (1.f + expf(-x));
}
__device__ __forceinline__ float tf32r(float x) {
    uint32_t u;
    asm("cvt.rna.tf32.f32 %0, %1;" : "=r"(u) : "f"(x));
    return __uint_as_float(u);
}
__device__ __forceinline__ void cpa16(uint32_t dst, const void* src) {
    asm volatile("cp.async.cg.shared.global [%0], [%1], 16;\n" :: "r"(dst), "l"(src));
}
__device__ __forceinline__ void cpa_commit() {
    asm volatile("cp.async.commit_group;\n" ::: "memory");
}
__device__ __forceinline__ void ldmx4(uint32_t* r, uint32_t addr) {
    asm volatile(
        "ldmatrix.sync.aligned.m8n8.x4.shared.b16 {%0,%1,%2,%3}, [%4];"
        : "=r"(r[0]), "=r"(r[1]), "=r"(r[2]), "=r"(r[3]) : "r"(addr));
}
__device__ __forceinline__ void mma_f16(float* c, const uint32_t* a, const uint32_t* b) {
    asm volatile(
        "mma.sync.aligned.m16n8k16.row.col.f32.f16.f16.f32 "
        "{%0,%1,%2,%3}, {%4,%5,%6,%7}, {%8,%9}, {%0,%1,%2,%3};"
        : "+f"(c[0]), "+f"(c[1]), "+f"(c[2]), "+f"(c[3])
        : "r"(a[0]), "r"(a[1]), "r"(a[2]), "r"(a[3]), "r"(b[0]), "r"(b[1]));
}
__device__ __forceinline__ void mma_tf32(float* c, const uint32_t* a, const uint32_t* b) {
    asm volatile(
        "mma.sync.aligned.m16n8k8.row.col.f32.tf32.tf32.f32 "
        "{%0,%1,%2,%3}, {%4,%5,%6,%7}, {%8,%9}, {%0,%1,%2,%3};"
        : "+f"(c[0]), "+f"(c[1]), "+f"(c[2]), "+f"(c[3])
        : "r"(a[0]), "r"(a[1]), "r"(a[2]), "r"(a[3]), "r"(b[0]), "r"(b[1]));
}

// ---------------- fp16 GEMM: act(A @ W^T) ----------------
// A row-major [1024,K] half, W row-major [N,K] half. 64x128x32 tile,
// 256 threads = 8 warps of 32x32, 2 CTAs/SM, ldmatrix fragment loads.
// 5-stage cp.async, 3 in flight, ONE __syncthreads per k-iter.
// Schedule: all 8 ldmatrix up front -> next-stage cp.async -> 16 MMAs.
#define GSTH 5
#define AROWH 40                               // 32 halves + 8 pad
#define HSTG_B ((64 + 128) * AROWH * 2)        // 15360 B per stage
#define HSMEM  (GSTH * HSTG_B)                 // 76800 B

template<int EPI>
__global__ __launch_bounds__(256, 2)
void hgemm(const __half* __restrict__ A, int lda,
           const __half* __restrict__ W, int ldw,
           const float* __restrict__ bias,
           float* __restrict__ C, int ldc, int K)
{
    extern __shared__ __align__(16) char smem[];
    const int tid = threadIdx.x, warp = tid >> 5, lane = tid & 31;
    const int bm = blockIdx.y * 64, bn = blockIdx.x * 128;
    const int wm = (warp & 1) * 32, wn = (warp >> 1) * 32;
    const uint32_t sbase = (uint32_t)__cvta_generic_to_shared(smem);

    // ldmatrix lane -> source row/col within a 16x16 tile
    const int lrow8 = (lane & 7) + ((lane >> 3) & 1) * 8;  // row 0..15
    const int lk8   = (lane >> 4) * 8;                     // k 0 or 8

    float acc[2][4][4];
#pragma unroll
    for (int i = 0; i < 2; i++)
#pragma unroll
        for (int j = 0; j < 4; j++)
#pragma unroll
            for (int k = 0; k < 4; k++) acc[i][j][k] = 0.f;

    const int nIter = K / 32;

    auto load_stage = [&](int s, int kt) {
        const uint32_t aB = sbase + (uint32_t)s * HSTG_B;
        const uint32_t bB = aB + 64 * AROWH * 2;
        {
            const int row = tid >> 2, ch = tid & 3;
            cpa16(aB + (uint32_t)(row * AROWH + ch * 8) * 2,
                  A + (size_t)(bm + row) * lda + kt * 32 + ch * 8);
        }
#pragma unroll
        for (int p = 0; p < 2; p++) {
            const int idx = tid + p * 256;
            const int row = idx >> 2, ch = idx & 3;
            cpa16(bB + (uint32_t)(row * AROWH + ch * 8) * 2,
                  W + (size_t)(bn + row) * ldw + kt * 32 + ch * 8);
        }
    };

    load_stage(0, 0); cpa_commit();
    load_stage(1, 1); cpa_commit();
    load_stage(2, 2); cpa_commit();

    for (int it = 0; it < nIter; it++) {
        asm volatile("cp.async.wait_group 2;\n" ::: "memory");
        __syncthreads();

        const uint32_t stg = sbase + (uint32_t)(it % GSTH) * HSTG_B;
        const uint32_t stgB = stg + 64 * AROWH * 2;

        // ---- load ALL fragments for both k-slices up front ----
        uint32_t af[2][2][4], bq[2][2][4];
#pragma unroll
        for (int ks = 0; ks < 2; ks++) {
#pragma unroll
            for (int mt = 0; mt < 2; mt++)
                ldmx4(af[ks][mt],
                      stg + (uint32_t)((wm + mt * 16 + lrow8) * AROWH + ks * 16 + lk8) * 2);
#pragma unroll
            for (int nh = 0; nh < 2; nh++)
                ldmx4(bq[ks][nh],
                      stgB + (uint32_t)((wn + nh * 16 + lrow8) * AROWH + ks * 16 + lk8) * 2);
        }

        // ---- overlap: issue next-stage global loads before the MMAs ----
        if (it + 3 < nIter) load_stage((it + 3) % GSTH, it + 3);
        cpa_commit();

        // ---- 16 MMAs ----
#pragma unroll
        for (int ks = 0; ks < 2; ks++) {
#pragma unroll
            for (int nt = 0; nt < 4; nt++) {
                uint32_t bf[2] = { bq[ks][nt >> 1][nt & 1], bq[ks][nt >> 1][(nt & 1) + 2] };
#pragma unroll
                for (int mt = 0; mt < 2; mt++)
                    mma_f16(acc[mt][nt], af[ks][mt], bf);
            }
        }
    }

    // ---- epilogue ----
#pragma unroll
    for (int mt = 0; mt < 2; mt++) {
        const int row = bm + wm + mt * 16 + (lane >> 2);
#pragma unroll
        for (int nt = 0; nt < 4; nt++) {
            const int col = bn + wn + nt * 8 + (lane & 3) * 2;
            const float v0 = acc[mt][nt][0], v1 = acc[mt][nt][1];
            const float v2 = acc[mt][nt][2], v3 = acc[mt][nt][3];
            if (EPI == 1) {
                const float b0 = bias[col], b1 = bias[col + 1];
                C[(size_t)col * ldc + row]            = softplusf(v0 + b0);
                C[(size_t)(col + 1) * ldc + row]      = softplusf(v1 + b1);
                C[(size_t)col * ldc + row + 8]        = softplusf(v2 + b0);
                C[(size_t)(col + 1) * ldc + row + 8]  = softplusf(v3 + b1);
            } else if (EPI == 2) {
                if (col < DI) {
                    *(float2*)(g_xin + (size_t)row * DI + col)       = make_float2(v0, v1);
                    *(float2*)(g_xin + (size_t)(row + 8) * DI + col) = make_float2(v2, v3);
                } else {
                    const int dd = col - DI;
                    g_zT[(size_t)dd * M_TOT + row]           = siluf(v0);
                    g_zT[(size_t)(dd + 1) * M_TOT + row]     = siluf(v1);
                    g_zT[(size_t)dd * M_TOT + row + 8]       = siluf(v2);
                    g_zT[(size_t)(dd + 1) * M_TOT + row + 8] = siluf(v3);
                }
            } else {  // EPI == 3
                if (col < DI) {
                    *(__half2*)(g_xdblh + (size_t)row * DI + col)       = __floats2half2_rn(v0, v1);
                    *(__half2*)(g_xdblh + (size_t)(row + 8) * DI + col) = __floats2half2_rn(v2, v3);
                } else if (col < DI + DS) {
                    const int nn = col - DI;
                    g_BT[(size_t)nn * M_TOT + row]           = v0;
                    g_BT[(size_t)(nn + 1) * M_TOT + row]     = v1;
                    g_BT[(size_t)nn * M_TOT + row + 8]       = v2;
                    g_BT[(size_t)(nn + 1) * M_TOT + row + 8] = v3;
                } else if (col < DI + 2 * DS) {
                    const int nn = col - DI - DS;
                    g_CT2[(size_t)nn * M_TOT + row]           = v0;
                    g_CT2[(size_t)(nn + 1) * M_TOT + row]     = v1;
                    g_CT2[(size_t)nn * M_TOT + row + 8]       = v2;
                    g_CT2[(size_t)(nn + 1) * M_TOT + row + 8] = v3;
                }
            }
        }
    }
}

// ---------------- tf32 ACOL GEMM (G6): out = ypreT^T @ Wout^T ---------
#define ACROW 72
#define T4_ASZ (16 * ACROW)
#define T4_BSZ (128 * 20)
#define T4_STG (T4_ASZ + T4_BSZ)
#define T4SMEM (3 * T4_STG * 4)        // 44544 B

__global__ __launch_bounds__(128)
void tgemm_acol(const float* __restrict__ A, int lda,
                const float* __restrict__ W, int ldw,
                float* __restrict__ C, int ldc, int K)
{
    extern __shared__ __align__(16) float smemf[];
    const int tid = threadIdx.x, warp = tid >> 5, lane = tid & 31;
    const int bm = blockIdx.y * 64, bn = blockIdx.x * 128;
    const int wn = warp * 32;
    const uint32_t sbase = (uint32_t)__cvta_generic_to_shared(smemf);

    float acc[4][4][4];
#pragma unroll
    for (int i = 0; i < 4; i++)
#pragma unroll
        for (int j = 0; j < 4; j++)
#pragma unroll
            for (int k = 0; k < 4; k++) acc[i][j][k] = 0.f;

    const int nIter = K / 16;

    auto load_stage = [&](int s, int kt) {
        const uint32_t aB = sbase + (uint32_t)s * T4_STG * 4;
        const uint32_t bB = aB + T4_ASZ * 4;
#pragma unroll
        for (int p = 0; p < 2; p++) {
            const int chunk = tid + p * 128;
            const int krow = chunk >> 4, mch = chunk & 15;
            cpa16(aB + (uint32_t)(krow * ACROW + mch * 4) * 4,
                  A + (size_t)(kt * 16 + krow) * lda + bm + mch * 4);
        }
#pragma unroll
        for (int p = 0; p < 4; p++) {
            const int row = (tid >> 2) + p * 32, ch = tid & 3;
            cpa16(bB + (uint32_t)(row * 20 + ch * 4) * 4,
                  W + (size_t)(bn + row) * ldw + kt * 16 + ch * 4);
        }
    };

    load_stage(0, 0); cpa_commit();
    load_stage(1, 1); cpa_commit();

    for (int it = 0; it < nIter; it++) {
        asm volatile("cp.async.wait_group 1;\n" ::: "memory");
        __syncthreads();

        const float* As = smemf + (size_t)(it % 3) * T4_STG;
        const float* Ws = As + T4_ASZ;

#pragma unroll
        for (int ks = 0; ks < 2; ks++) {
            const int k0 = ks * 8;
            const int ac = k0 + (lane & 3);
            uint32_t af[4][4];
#pragma unroll
            for (int mt = 0; mt < 4; mt++) {
                const int ar = mt * 16 + (lane >> 2);
                af[mt][0] = __float_as_uint(As[ac * ACROW + ar]);
                af[mt][1] = __float_as_uint(As[ac * ACROW + ar + 8]);
                af[mt][2] = __float_as_uint(As[(ac + 4) * ACROW + ar]);
                af[mt][3] = __float_as_uint(As[(ac + 4) * ACROW + ar + 8]);
            }
#pragma unroll
            for (int nt = 0; nt < 4; nt++) {
                const int br = wn + nt * 8 + (lane >> 2);
                const int bc = k0 + (lane & 3);
                uint32_t bf[2];
                bf[0] = __float_as_uint(Ws[br * 20 + bc]);
                bf[1] = __float_as_uint(Ws[br * 20 + bc + 4]);
#pragma unroll
                for (int mt = 0; mt < 4; mt++)
                    mma_tf32(acc[mt][nt], af[mt], bf);
            }
        }

        __syncthreads();
        if (it + 2 < nIter) load_stage((it + 2) % 3, it + 2);
        cpa_commit();
    }

#pragma unroll
    for (int mt = 0; mt < 4; mt++) {
        const int row = bm + mt * 16 + (lane >> 2);
#pragma unroll
        for (int nt = 0; nt < 4; nt++) {
            const int col = bn + wn + nt * 8 + (lane & 3) * 2;
            *(float2*)(C + (size_t)row * ldc + col)       = make_float2(acc[mt][nt][0], acc[mt][nt][1]);
            *(float2*)(C + (size_t)(row + 8) * ldc + col) = make_float2(acc[mt][nt][2], acc[mt][nt][3]);
        }
    }
}

// ---------------- merged pre-pass ----------------
#define NX4    (M_TOT * DM / 4)
#define NWIN4  (XZ_LD * DM / 4)
#define NWDT4  (DI * DI / 4)
#define NWXP4  (NX_PAD * DI / 4)
#define NWOUT4 (DM * DI / 4)
#define NTOT4  (NX4 + NWIN4 + NWDT4 + NWXP4 + NWOUT4)

__device__ __forceinline__ void cvt_h4(const float* src, __half* dst, int i) {
    float4 v = ((const float4*)src)[i];
    ((__half2*)dst)[i * 2]     = __floats2half2_rn(v.x, v.y);
    ((__half2*)dst)[i * 2 + 1] = __floats2half2_rn(v.z, v.w);
}

__global__ __launch_bounds__(256)
void prepass_kernel(const float* __restrict__ x, const float* __restrict__ win,
                    const float* __restrict__ wdt, const float* __restrict__ wx,
                    const float* __restrict__ wout)
{
    int i = blockIdx.x * 256 + threadIdx.x;
    if (i >= NTOT4) return;
    if (i < NX4)                    { cvt_h4(x, g_xh, i); return; }
    if ((i -= NX4) < NWIN4)         { cvt_h4(win, g_Winh, i); return; }
    if ((i -= NWIN4) < NWDT4)       { cvt_h4(wdt, g_Wdth, i); return; }
    if ((i -= NWDT4) < NWXP4) {
        const int n  = i / (DI / 4);
        const int k4 = i % (DI / 4);
        float4 v = make_float4(0.f, 0.f, 0.f, 0.f);
        if (n < XDBL_LD) v = ((const float4*)wx)[(size_t)n * (DI / 4) + k4];
        ((__half2*)g_Wxh)[i * 2]     = __floats2half2_rn(v.x, v.y);
        ((__half2*)g_Wxh)[i * 2 + 1] = __floats2half2_rn(v.z, v.w);
        return;
    }
    i -= NWXP4;
    float4 v = ((const float4*)wout)[i];
    v.x = tf32r(v.x); v.y = tf32r(v.y); v.z = tf32r(v.z); v.w = tf32r(v.w);
    ((float4*)g_Wout32)[i] = v;
}

// ---------------- depthwise causal conv + bias + SiLU -> both layouts ------
__global__ __launch_bounds__(256)
void conv_silu_T_kernel(const float* __restrict__ conv_w, const float* __restrict__ conv_b)
{
    __shared__ float s[32][133];
    __shared__ float r[128][33];
    const int t0 = blockIdx.x * 128;
    const int d0 = blockIdx.y * 32;
    const int b  = blockIdx.z;

    for (int tt = threadIdx.y; tt < 131; tt += 8) {
        const int gt = t0 - 3 + tt;
        float v = 0.f;
        if (gt >= 0)
            v = g_xin[(size_t)(b * SEQ + gt) * DI + d0 + threadIdx.x];
        s[threadIdx.x][tt] = v;
    }
    __syncthreads();

    for (int dd = threadIdx.y; dd < 32; dd += 8) {
        const int d = d0 + dd;
        const float w0 = conv_w[d * 4 + 0];
        const float w1 = conv_w[d * 4 + 1];
        const float w2 = conv_w[d * 4 + 2];
        const float w3 = conv_w[d * 4 + 3];
        const float cb = conv_b[d];
#pragma unroll
        for (int tc = 0; tc < 4; tc++) {
            const int tl = tc * 32 + threadIdx.x;
            float acc = cb;
            acc = fmaf(s[dd][tl + 0], w0, acc);
            acc = fmaf(s[dd][tl + 1], w1, acc);
            acc = fmaf(s[dd][tl + 2], w2, acc);
            acc = fmaf(s[dd][tl + 3], w3, acc);
            const float v = siluf(acc);
            g_xconvT[(size_t)d * M_TOT + b * SEQ + t0 + tl] = v;
            r[tl][dd] = v;
        }
    }
    __syncthreads();
    for (int tt = threadIdx.y; tt < 128; tt += 8)
        g_xconvh[(size_t)(b * SEQ + t0 + tt) * DI + d0 + threadIdx.x] =
            __float2half_rn(r[tt][threadIdx.x]);
}

// ---------------- fused selective scan (EXACT reference tree) ----------------
__global__ __launch_bounds__(512)
void scan_kernel(const float* __restrict__ A_log, const float* __restrict__ Dp)
{
    __shared__ float ss[16][520];
    const int d = blockIdx.x, b = blockIdx.y;
    const int tid = threadIdx.x, warp = tid >> 5, lane = tid & 31;
    const int n = warp;
    const float a = -expf(A_log[d * DS + n]);
    const size_t cbase = (size_t)d * M_TOT + b * SEQ;
    const size_t nbase = (size_t)n * M_TOT + b * SEQ;
    const int t0 = lane * 16;

    float c[16], v[16];
#pragma unroll
    for (int q = 0; q < 4; q++) {
        const float4 d4 = *(const float4*)(g_deltaT + cbase + t0 + q * 4);
        const float4 x4 = *(const float4*)(g_xconvT + cbase + t0 + q * 4);
        const float4 b4 = *(const float4*)(g_BT + nbase + t0 + q * 4);
        const float dv[4] = {d4.x, d4.y, d4.z, d4.w};
        const float xv[4] = {x4.x, x4.y, x4.z, x4.w};
        const float bv[4] = {b4.x, b4.y, b4.z, b4.w};
#pragma unroll
        for (int i = 0; i < 4; i++) {
            c[q * 4 + i] = expf(dv[i] * a) + 1e-12f;
            v[q * 4 + i] = fabsf(dv[i] * bv[i] * xv[i]) + 1e-12f;
        }
    }

    // up-sweep levels 0..3 (lane-local)
#pragma unroll
    for (int lev = 0; lev < 4; lev++) {
        const int half = 1 << lev;
#pragma unroll
        for (int r = 2 * half - 1; r < 16; r += 2 * half) {
            v[r] = v[r - half] + c[r] * v[r];
            c[r] = c[r - half] * c[r];
        }
    }

    // up-sweep levels 4..8 (cross-lane on element 15)
    float C15 = c[15], V15 = v[15];
#pragma unroll
    for (int dd = 1; dd <= 16; dd <<= 1) {
        const float cl = __shfl_up_sync(0xffffffffu, C15, dd);
        const float vl = __shfl_up_sync(0xffffffffu, V15, dd);
        if ((lane & (2 * dd - 1)) == (2 * dd - 1)) {
            V15 = vl + C15 * V15;
            C15 = cl * C15;
        }
    }

    // down-sweep levels 8..4 (gather both shfls BEFORE updating)
#pragma unroll
    for (int dd = 16; dd >= 1; dd >>= 1) {
        const float vl = __shfl_up_sync(0xffffffffu, V15, dd);
        const float vr = __shfl_down_sync(0xffffffffu, V15, dd);
        const int m = lane & (2 * dd - 1);
        float nv = V15;
        if (m == 2 * dd - 1) nv = vl + C15 * V15;
        else if (m == dd - 1) nv = vr;
        V15 = nv;
    }
    c[15] = C15;
    v[15] = V15;

    // down-sweep levels 3..0 (lane-local)
#pragma unroll
    for (int lev = 3; lev >= 0; lev--) {
        const int half = 1 << lev;
#pragma unroll
        for (int r = 2 * half - 1; r < 16; r += 2 * half) {
            const float tmp = v[r];
            v[r] = v[r - half] + c[r] * v[r];
            v[r - half] = tmp;
        }
    }

    // multiply by C, stage per-state rows to smem
#pragma unroll
    for (int q = 0; q < 4; q++) {
        const float4 c4 = *(const float4*)(g_CT2 + nbase + t0 + q * 4);
        float4 o;
        o.x = v[q * 4 + 0] * c4.x;
        o.y = v[q * 4 + 1] * c4.y;
        o.z = v[q * 4 + 2] * c4.z;
        o.w = v[q * 4 + 3] * c4.w;
        *(float4*)&ss[warp][t0 + q * 4] = o;
    }
    __syncthreads();

    // reduce over 16 states + epilogue
    float acc = 0.f;
#pragma unroll
    for (int w = 0; w < 16; w++) acc += ss[w][tid];
    const float xct = g_xconvT[cbase + tid];
    const float gz  = g_zT[cbase + tid];
    const float yv  = fmaf(xct, Dp[d], acc) * gz;
    g_ypreT[cbase + tid] = tf32r(yv);
}

// ---------------- launch ----------------
extern "C" void kernel_launch(void* const* d_in, const int* in_sizes, int n_in,
                              void* d_out, int out_size)
{
    const float* x      = (const float*)d_in[0];
    const float* W_in   = (const float*)d_in[1];
    const float* conv_w = (const float*)d_in[2];
    const float* conv_b = (const float*)d_in[3];
    const float* W_x    = (const float*)d_in[4];
    const float* W_dt   = (const float*)d_in[5];
    const float* b_dt   = (const float*)d_in[6];
    const float* A_log  = (const float*)d_in[7];
    const float* Dp     = (const float*)d_in[8];
    const float* W_out  = (const float*)d_in[9];
    float* out = (float*)d_out;

    __half *xh, *Winh, *Wxh, *Wdth, *xconvh, *xdblh;
    float *Wout32, *deltaT, *ypreT;
    cudaGetSymbolAddress((void**)&xh,     g_xh);
    cudaGetSymbolAddress((void**)&Winh,   g_Winh);
    cudaGetSymbolAddress((void**)&Wxh,    g_Wxh);
    cudaGetSymbolAddress((void**)&Wdth,   g_Wdth);
    cudaGetSymbolAddress((void**)&xconvh, g_xconvh);
    cudaGetSymbolAddress((void**)&xdblh,  g_xdblh);
    cudaGetSymbolAddress((void**)&Wout32, g_Wout32);
    cudaGetSymbolAddress((void**)&deltaT, g_deltaT);
    cudaGetSymbolAddress((void**)&ypreT,  g_ypreT);

    cudaFuncSetAttribute((const void*)hgemm<1>, cudaFuncAttributeMaxDynamicSharedMemorySize, HSMEM);
    cudaFuncSetAttribute((const void*)hgemm<2>, cudaFuncAttributeMaxDynamicSharedMemorySize, HSMEM);
    cudaFuncSetAttribute((const void*)hgemm<3>, cudaFuncAttributeMaxDynamicSharedMemorySize, HSMEM);
    cudaFuncSetAttribute((const void*)tgemm_acol, cudaFuncAttributeMaxDynamicSharedMemorySize, T4SMEM);

    // 0) merged pre-pass
    prepass_kernel<<<(NTOT4 + 255) / 256, 256>>>(x, W_in, W_dt, W_x, W_out);

    // 1) xz = x @ W_in^T ; x_inner -> g_xin, z -> silu -> g_zT
    hgemm<2><<<dim3(XZ_LD / 128, M_TOT / 64), 256, HSMEM>>>(
        xh, DM, Winh, DM, nullptr, nullptr, 0, DM);

    // 2) conv + silu -> xconvT (f32) + xconvh (half)
    conv_silu_T_kernel<<<dim3(SEQ / 128, DI / 32, BATCH), dim3(32, 8)>>>(conv_w, conv_b);

    // 3) x_dbl = x_conv @ W_x^T ; delta_raw -> xdblh, B -> BT, C -> CT2
    hgemm<3><<<dim3(NX_PAD / 128, M_TOT / 64), 256, HSMEM>>>(
        xconvh, DI, Wxh, DI, nullptr, nullptr, 0, DI);

    // 4) deltaT = softplus(delta_raw @ W_dt^T + b_dt), transposed store
    hgemm<1><<<dim3(DI / 128, M_TOT / 64), 256, HSMEM>>>(
        xdblh, DI, Wdth, DI, b_dt, deltaT, M_TOT, DI);

    // 5) fused selective scan (exact reference tree) -> ypreT (tf32-rounded)
    scan_kernel<<<dim3(DI, BATCH), 512>>>(A_log, Dp);

    // 6) out = ypre @ W_out^T (tf32, A column-major via ypreT)
    tgemm_acol<<<dim3(DM / 128, M_TOT / 64), 128, T4SMEM>>>(
        ypreT, M_TOT, Wout32, DI, out, DM, DI);
}

// round 13
// speedup vs baseline: 4.9297x; 1.0932x over previous
#include <cuda_runtime.h>
#include <cuda_fp16.h>
#include <math.h>
#include <stdint.h>

// ---------------- problem constants ----------------
#define BATCH   2
#define SEQ     512
#define DM      768
#define DI      1536
#define DS      16
#define M_TOT   (BATCH*SEQ)   // 1024
#define XZ_LD   (2*DI)        // 3072
#define XDBL_LD (DI + 2*DS)   // 1568
#define NX_PAD  1664

// ---------------- scratch ----------------
__device__ __half g_xh    [M_TOT * DM];
__device__ __half g_Winh  [XZ_LD * DM];
__device__ __half g_Wxh   [NX_PAD * DI];
__device__ __half g_Wdth  [DI * DI];
__device__ __half g_Wouth [DM * DI];
__device__ __half g_xconvh[M_TOT * DI];
__device__ __half g_xdblh [M_TOT * DI];
__device__ __half g_ypreh [M_TOT * DI];
__device__ float  g_xin   [M_TOT * DI];
__device__ float  g_zT    [DI * M_TOT];
__device__ float  g_xconvT[DI * M_TOT];
__device__ float  g_BT    [DS * M_TOT];
__device__ float  g_CT2   [DS * M_TOT];
__device__ float  g_deltaT[DI * M_TOT];
__device__ float  g_ypreT [DI * M_TOT];

// ---------------- helpers ----------------
__device__ __forceinline__ float softplusf(float x) {
    if (x > 20.f) return x;
    return log1pf(expf(x));
}
__device__ __forceinline__ float siluf(float x) {
    return x / (1.f + expf(-x));
}
__device__ __forceinline__ void cpa16(uint32_t dst, const void* src) {
    asm volatile("cp.async.cg.shared.global [%0], [%1], 16;\n" :: "r"(dst), "l"(src));
}
__device__ __forceinline__ void cpa_commit() {
    asm volatile("cp.async.commit_group;\n" ::: "memory");
}
__device__ __forceinline__ void ldmx4(uint32_t* r, uint32_t addr) {
    asm volatile(
        "ldmatrix.sync.aligned.m8n8.x4.shared.b16 {%0,%1,%2,%3}, [%4];"
        : "=r"(r[0]), "=r"(r[1]), "=r"(r[2]), "=r"(r[3]) : "r"(addr));
}
__device__ __forceinline__ void mma_f16(float* c, const uint32_t* a, const uint32_t* b) {
    asm volatile(
        "mma.sync.aligned.m16n8k16.row.col.f32.f16.f16.f32 "
        "{%0,%1,%2,%3}, {%4,%5,%6,%7}, {%8,%9}, {%0,%1,%2,%3};"
        : "+f"(c[0]), "+f"(c[1]), "+f"(c[2]), "+f"(c[3])
        : "r"(a[0]), "r"(a[1]), "r"(a[2]), "r"(a[3]), "r"(b[0]), "r"(b[1]));
}

// ---------------- fp16 GEMM: act(A @ W^T) ----------------
// A row-major [1024,K] half, W row-major [N,K] half. 64xBNx32 tile,
// 256 threads = 8 warps (2m x 4n), ldmatrix fragments, 5-stage cp.async.
// EPI: 0 plain f32 store, 1 softplus+bias->deltaT transposed,
//      2 split x_inner|silu(z)->zT, 3 split xdblh|BT|CT2.
#define GSTH 5
#define AROWH 40                               // 32 halves + 8 pad

template<int EPI, int BN>
__global__ __launch_bounds__(256, 2)
void hgemm(const __half* __restrict__ A, int lda,
           const __half* __restrict__ W, int ldw,
           const float* __restrict__ bias,
           float* __restrict__ C, int ldc, int K)
{
    constexpr int WN = BN / 4;          // per-warp n extent
    constexpr int NT = WN / 8;          // n mma tiles
    constexpr int NH = WN / 16;         // 16x16 ldmatrix tiles
    constexpr int HSTG = (64 + BN) * AROWH * 2;

    extern __shared__ __align__(16) char smem[];
    const int tid = threadIdx.x, warp = tid >> 5, lane = tid & 31;
    const int bm = blockIdx.y * 64, bn = blockIdx.x * BN;
    const int wm = (warp & 1) * 32, wn = (warp >> 1) * WN;
    const uint32_t sbase = (uint32_t)__cvta_generic_to_shared(smem);

    const int lrow8 = (lane & 7) + ((lane >> 3) & 1) * 8;
    const int lk8   = (lane >> 4) * 8;

    float acc[2][NT][4];
#pragma unroll
    for (int i = 0; i < 2; i++)
#pragma unroll
        for (int j = 0; j < NT; j++)
#pragma unroll
            for (int k = 0; k < 4; k++) acc[i][j][k] = 0.f;

    const int nIter = K / 32;

    auto load_stage = [&](int s, int kt) {
        const uint32_t aB = sbase + (uint32_t)s * HSTG;
        const uint32_t bB = aB + 64 * AROWH * 2;
        {
            const int row = tid >> 2, ch = tid & 3;
            cpa16(aB + (uint32_t)(row * AROWH + ch * 8) * 2,
                  A + (size_t)(bm + row) * lda + kt * 32 + ch * 8);
        }
#pragma unroll
        for (int p = 0; p < BN / 64; p++) {
            const int idx = tid + p * 256;
            const int row = idx >> 2, ch = idx & 3;
            cpa16(bB + (uint32_t)(row * AROWH + ch * 8) * 2,
                  W + (size_t)(bn + row) * ldw + kt * 32 + ch * 8);
        }
    };

    load_stage(0, 0); cpa_commit();
    load_stage(1, 1); cpa_commit();
    load_stage(2, 2); cpa_commit();

    for (int it = 0; it < nIter; it++) {
        asm volatile("cp.async.wait_group 2;\n" ::: "memory");
        __syncthreads();

        const uint32_t stg = sbase + (uint32_t)(it % GSTH) * HSTG;
        const uint32_t stgB = stg + 64 * AROWH * 2;

        uint32_t af[2][2][4], bq[2][NH][4];
#pragma unroll
        for (int ks = 0; ks < 2; ks++) {
#pragma unroll
            for (int mt = 0; mt < 2; mt++)
                ldmx4(af[ks][mt],
                      stg + (uint32_t)((wm + mt * 16 + lrow8) * AROWH + ks * 16 + lk8) * 2);
#pragma unroll
            for (int nh = 0; nh < NH; nh++)
                ldmx4(bq[ks][nh],
                      stgB + (uint32_t)((wn + nh * 16 + lrow8) * AROWH + ks * 16 + lk8) * 2);
        }

        if (it + 3 < nIter) load_stage((it + 3) % GSTH, it + 3);
        cpa_commit();

#pragma unroll
        for (int ks = 0; ks < 2; ks++) {
#pragma unroll
            for (int nt = 0; nt < NT; nt++) {
                uint32_t bf[2] = { bq[ks][nt >> 1][nt & 1], bq[ks][nt >> 1][(nt & 1) + 2] };
#pragma unroll
                for (int mt = 0; mt < 2; mt++)
                    mma_f16(acc[mt][nt], af[ks][mt], bf);
            }
        }
    }

    // ---- epilogue ----
#pragma unroll
    for (int mt = 0; mt < 2; mt++) {
        const int row = bm + wm + mt * 16 + (lane >> 2);
#pragma unroll
        for (int nt = 0; nt < NT; nt++) {
            const int col = bn + wn + nt * 8 + (lane & 3) * 2;
            const float v0 = acc[mt][nt][0], v1 = acc[mt][nt][1];
            const float v2 = acc[mt][nt][2], v3 = acc[mt][nt][3];
            if (EPI == 0) {
                *(float2*)(C + (size_t)row * ldc + col)       = make_float2(v0, v1);
                *(float2*)(C + (size_t)(row + 8) * ldc + col) = make_float2(v2, v3);
            } else if (EPI == 1) {
                const float b0 = bias[col], b1 = bias[col + 1];
                C[(size_t)col * ldc + row]            = softplusf(v0 + b0);
                C[(size_t)(col + 1) * ldc + row]      = softplusf(v1 + b1);
                C[(size_t)col * ldc + row + 8]        = softplusf(v2 + b0);
                C[(size_t)(col + 1) * ldc + row + 8]  = softplusf(v3 + b1);
            } else if (EPI == 2) {
                if (col < DI) {
                    *(float2*)(g_xin + (size_t)row * DI + col)       = make_float2(v0, v1);
                    *(float2*)(g_xin + (size_t)(row + 8) * DI + col) = make_float2(v2, v3);
                } else {
                    const int dd = col - DI;
                    g_zT[(size_t)dd * M_TOT + row]           = siluf(v0);
                    g_zT[(size_t)(dd + 1) * M_TOT + row]     = siluf(v1);
                    g_zT[(size_t)dd * M_TOT + row + 8]       = siluf(v2);
                    g_zT[(size_t)(dd + 1) * M_TOT + row + 8] = siluf(v3);
                }
            } else {  // EPI == 3
                if (col < DI) {
                    *(__half2*)(g_xdblh + (size_t)row * DI + col)       = __floats2half2_rn(v0, v1);
                    *(__half2*)(g_xdblh + (size_t)(row + 8) * DI + col) = __floats2half2_rn(v2, v3);
                } else if (col < DI + DS) {
                    const int nn = col - DI;
                    g_BT[(size_t)nn * M_TOT + row]           = v0;
                    g_BT[(size_t)(nn + 1) * M_TOT + row]     = v1;
                    g_BT[(size_t)nn * M_TOT + row + 8]       = v2;
                    g_BT[(size_t)(nn + 1) * M_TOT + row + 8] = v3;
                } else if (col < DI + 2 * DS) {
                    const int nn = col - DI - DS;
                    g_CT2[(size_t)nn * M_TOT + row]           = v0;
                    g_CT2[(size_t)(nn + 1) * M_TOT + row]     = v1;
                    g_CT2[(size_t)nn * M_TOT + row + 8]       = v2;
                    g_CT2[(size_t)(nn + 1) * M_TOT + row + 8] = v3;
                }
            }
        }
    }
}

#define HSMEM128 (GSTH * (64 + 128) * AROWH * 2)   // 76800
#define HSMEM64  (GSTH * (64 + 64) * AROWH * 2)    // 51200

// ---------------- merged pre-pass: MLP=4 per thread ----------------
#define NX4    (M_TOT * DM / 4)
#define NWIN4  (XZ_LD * DM / 4)
#define NWDT4  (DI * DI / 4)
#define NWXP4  (NX_PAD * DI / 4)
#define NWOUT4 (DM * DI / 4)
#define QX     (NX4 / 4)
#define QWIN   (NWIN4 / 4)
#define QWDT   (NWDT4 / 4)
#define QWXP   (NWXP4 / 4)
#define QWOUT  (NWOUT4 / 4)
#define QTOT   (QX + QWIN + QWDT + QWXP + QWOUT)

__device__ __forceinline__ void cvt4h(const float* __restrict__ src,
                                      __half* __restrict__ dst, int q, int Q) {
    float4 v[4];
#pragma unroll
    for (int k = 0; k < 4; k++) v[k] = ((const float4*)src)[q + k * Q];
#pragma unroll
    for (int k = 0; k < 4; k++) {
        const int i = q + k * Q;
        ((__half2*)dst)[i * 2]     = __floats2half2_rn(v[k].x, v[k].y);
        ((__half2*)dst)[i * 2 + 1] = __floats2half2_rn(v[k].z, v[k].w);
    }
}

__global__ __launch_bounds__(256)
void prepass_kernel(const float* __restrict__ x, const float* __restrict__ win,
                    const float* __restrict__ wdt, const float* __restrict__ wx,
                    const float* __restrict__ wout)
{
    int q = blockIdx.x * 256 + threadIdx.x;
    if (q >= QTOT) return;
    if (q < QX)                 { cvt4h(x, g_xh, q, QX); return; }
    if ((q -= QX) < QWIN)       { cvt4h(win, g_Winh, q, QWIN); return; }
    if ((q -= QWIN) < QWDT)     { cvt4h(wdt, g_Wdth, q, QWDT); return; }
    if ((q -= QWDT) < QWXP) {
        float4 v[4];
#pragma unroll
        for (int k = 0; k < 4; k++) {
            const int i = q + k * QWXP;
            const int n = i / (DI / 4);
            const int k4 = i % (DI / 4);
            v[k] = make_float4(0.f, 0.f, 0.f, 0.f);
            if (n < XDBL_LD) v[k] = ((const float4*)wx)[(size_t)n * (DI / 4) + k4];
        }
#pragma unroll
        for (int k = 0; k < 4; k++) {
            const int i = q + k * QWXP;
            ((__half2*)g_Wxh)[i * 2]     = __floats2half2_rn(v[k].x, v[k].y);
            ((__half2*)g_Wxh)[i * 2 + 1] = __floats2half2_rn(v[k].z, v[k].w);
        }
        return;
    }
    q -= QWXP;
    cvt4h(wout, g_Wouth, q, QWOUT);
}

// ---------------- depthwise causal conv + bias + SiLU -> both layouts ------
__global__ __launch_bounds__(256)
void conv_silu_T_kernel(const float* __restrict__ conv_w, const float* __restrict__ conv_b)
{
    __shared__ float s[32][133];
    __shared__ float r[128][33];
    const int t0 = blockIdx.x * 128;
    const int d0 = blockIdx.y * 32;
    const int b  = blockIdx.z;

    for (int tt = threadIdx.y; tt < 131; tt += 8) {
        const int gt = t0 - 3 + tt;
        float v = 0.f;
        if (gt >= 0)
            v = g_xin[(size_t)(b * SEQ + gt) * DI + d0 + threadIdx.x];
        s[threadIdx.x][tt] = v;
    }
    __syncthreads();

    for (int dd = threadIdx.y; dd < 32; dd += 8) {
        const int d = d0 + dd;
        const float w0 = conv_w[d * 4 + 0];
        const float w1 = conv_w[d * 4 + 1];
        const float w2 = conv_w[d * 4 + 2];
        const float w3 = conv_w[d * 4 + 3];
        const float cb = conv_b[d];
#pragma unroll
        for (int tc = 0; tc < 4; tc++) {
            const int tl = tc * 32 + threadIdx.x;
            float acc = cb;
            acc = fmaf(s[dd][tl + 0], w0, acc);
            acc = fmaf(s[dd][tl + 1], w1, acc);
            acc = fmaf(s[dd][tl + 2], w2, acc);
            acc = fmaf(s[dd][tl + 3], w3, acc);
            const float v = siluf(acc);
            g_xconvT[(size_t)d * M_TOT + b * SEQ + t0 + tl] = v;
            r[tl][dd] = v;
        }
    }
    __syncthreads();
    for (int tt = threadIdx.y; tt < 128; tt += 8)
        g_xconvh[(size_t)(b * SEQ + t0 + tt) * DI + d0 + threadIdx.x] =
            __float2half_rn(r[tt][threadIdx.x]);
}

// ---------------- ypreT (f32 [d][bt]) -> ypreh (half [bt][d]) ----------------
__global__ __launch_bounds__(256)
void transpose_h_kernel()
{
    __shared__ float ts[32][33];
    const int bt0 = blockIdx.x * 32;
    const int d0  = blockIdx.y * 32;
#pragma unroll
    for (int j = 0; j < 4; j++) {
        const int d = d0 + threadIdx.y + j * 8;
        ts[threadIdx.y + j * 8][threadIdx.x] =
            g_ypreT[(size_t)d * M_TOT + bt0 + threadIdx.x];
    }
    __syncthreads();
#pragma unroll
    for (int j = 0; j < 4; j++) {
        const int bt = bt0 + threadIdx.y + j * 8;
        g_ypreh[(size_t)bt * DI + d0 + threadIdx.x] =
            __float2half_rn(ts[threadIdx.x][threadIdx.y + j * 8]);
    }
}

// ---------------- fused selective scan (EXACT reference tree) ----------------
__global__ __launch_bounds__(512)
void scan_kernel(const float* __restrict__ A_log, const float* __restrict__ Dp)
{
    __shared__ float ss[16][520];
    const int d = blockIdx.x, b = blockIdx.y;
    const int tid = threadIdx.x, warp = tid >> 5, lane = tid & 31;
    const int n = warp;
    const float a = -expf(A_log[d * DS + n]);
    const size_t cbase = (size_t)d * M_TOT + b * SEQ;
    const size_t nbase = (size_t)n * M_TOT + b * SEQ;
    const int t0 = lane * 16;

    float c[16], v[16];
#pragma unroll
    for (int q = 0; q < 4; q++) {
        const float4 d4 = *(const float4*)(g_deltaT + cbase + t0 + q * 4);
        const float4 x4 = *(const float4*)(g_xconvT + cbase + t0 + q * 4);
        const float4 b4 = *(const float4*)(g_BT + nbase + t0 + q * 4);
        const float dv[4] = {d4.x, d4.y, d4.z, d4.w};
        const float xv[4] = {x4.x, x4.y, x4.z, x4.w};
        const float bv[4] = {b4.x, b4.y, b4.z, b4.w};
#pragma unroll
        for (int i = 0; i < 4; i++) {
            c[q * 4 + i] = expf(dv[i] * a) + 1e-12f;
            v[q * 4 + i] = fabsf(dv[i] * bv[i] * xv[i]) + 1e-12f;
        }
    }

    // up-sweep levels 0..3 (lane-local)
#pragma unroll
    for (int lev = 0; lev < 4; lev++) {
        const int half = 1 << lev;
#pragma unroll
        for (int r = 2 * half - 1; r < 16; r += 2 * half) {
            v[r] = v[r - half] + c[r] * v[r];
            c[r] = c[r - half] * c[r];
        }
    }

    // up-sweep levels 4..8 (cross-lane on element 15)
    float C15 = c[15], V15 = v[15];
#pragma unroll
    for (int dd = 1; dd <= 16; dd <<= 1) {
        const float cl = __shfl_up_sync(0xffffffffu, C15, dd);
        const float vl = __shfl_up_sync(0xffffffffu, V15, dd);
        if ((lane & (2 * dd - 1)) == (2 * dd - 1)) {
            V15 = vl + C15 * V15;
            C15 = cl * C15;
        }
    }

    // down-sweep levels 8..4 (gather both shfls BEFORE updating)
#pragma unroll
    for (int dd = 16; dd >= 1; dd >>= 1) {
        const float vl = __shfl_up_sync(0xffffffffu, V15, dd);
        const float vr = __shfl_down_sync(0xffffffffu, V15, dd);
        const int m = lane & (2 * dd - 1);
        float nv = V15;
        if (m == 2 * dd - 1) nv = vl + C15 * V15;
        else if (m == dd - 1) nv = vr;
        V15 = nv;
    }
    c[15] = C15;
    v[15] = V15;

    // down-sweep levels 3..0 (lane-local)
#pragma unroll
    for (int lev = 3; lev >= 0; lev--) {
        const int half = 1 << lev;
#pragma unroll
        for (int r = 2 * half - 1; r < 16; r += 2 * half) {
            const float tmp = v[r];
            v[r] = v[r - half] + c[r] * v[r];
            v[r - half] = tmp;
        }
    }

    // multiply by C, stage per-state rows to smem
#pragma unroll
    for (int q = 0; q < 4; q++) {
        const float4 c4 = *(const float4*)(g_CT2 + nbase + t0 + q * 4);
        float4 o;
        o.x = v[q * 4 + 0] * c4.x;
        o.y = v[q * 4 + 1] * c4.y;
        o.z = v[q * 4 + 2] * c4.z;
        o.w = v[q * 4 + 3] * c4.w;
        *(float4*)&ss[warp][t0 + q * 4] = o;
    }
    __syncthreads();

    // reduce over 16 states + epilogue
    float acc = 0.f;
#pragma unroll
    for (int w = 0; w < 16; w++) acc += ss[w][tid];
    const float xct = g_xconvT[cbase + tid];
    const float gz  = g_zT[cbase + tid];
    g_ypreT[cbase + tid] = fmaf(xct, Dp[d], acc) * gz;
}

// ---------------- launch ----------------
extern "C" void kernel_launch(void* const* d_in, const int* in_sizes, int n_in,
                              void* d_out, int out_size)
{
    const float* x      = (const float*)d_in[0];
    const float* W_in   = (const float*)d_in[1];
    const float* conv_w = (const float*)d_in[2];
    const float* conv_b = (const float*)d_in[3];
    const float* W_x    = (const float*)d_in[4];
    const float* W_dt   = (const float*)d_in[5];
    const float* b_dt   = (const float*)d_in[6];
    const float* A_log  = (const float*)d_in[7];
    const float* Dp     = (const float*)d_in[8];
    const float* W_out  = (const float*)d_in[9];
    float* out = (float*)d_out;

    __half *xh, *Winh, *Wxh, *Wdth, *Wouth, *xconvh, *xdblh, *ypreh;
    float *deltaT;
    cudaGetSymbolAddress((void**)&xh,     g_xh);
    cudaGetSymbolAddress((void**)&Winh,   g_Winh);
    cudaGetSymbolAddress((void**)&Wxh,    g_Wxh);
    cudaGetSymbolAddress((void**)&Wdth,   g_Wdth);
    cudaGetSymbolAddress((void**)&Wouth,  g_Wouth);
    cudaGetSymbolAddress((void**)&xconvh, g_xconvh);
    cudaGetSymbolAddress((void**)&xdblh,  g_xdblh);
    cudaGetSymbolAddress((void**)&ypreh,  g_ypreh);
    cudaGetSymbolAddress((void**)&deltaT, g_deltaT);

    cudaFuncSetAttribute((const void*)hgemm<1,128>, cudaFuncAttributeMaxDynamicSharedMemorySize, HSMEM128);
    cudaFuncSetAttribute((const void*)hgemm<2,128>, cudaFuncAttributeMaxDynamicSharedMemorySize, HSMEM128);
    cudaFuncSetAttribute((const void*)hgemm<3,128>, cudaFuncAttributeMaxDynamicSharedMemorySize, HSMEM128);
    cudaFuncSetAttribute((const void*)hgemm<0,64>,  cudaFuncAttributeMaxDynamicSharedMemorySize, HSMEM64);

    // 0) merged pre-pass (MLP=4)
    prepass_kernel<<<(QTOT + 255) / 256, 256>>>(x, W_in, W_dt, W_x, W_out);

    // 1) xz = x @ W_in^T ; x_inner -> g_xin, z -> silu -> g_zT
    hgemm<2,128><<<dim3(XZ_LD / 128, M_TOT / 64), 256, HSMEM128>>>(
        xh, DM, Winh, DM, nullptr, nullptr, 0, DM);

    // 2) conv + silu -> xconvT (f32) + xconvh (half)
    conv_silu_T_kernel<<<dim3(SEQ / 128, DI / 32, BATCH), dim3(32, 8)>>>(conv_w, conv_b);

    // 3) x_dbl = x_conv @ W_x^T ; delta_raw -> xdblh, B -> BT, C -> CT2
    hgemm<3,128><<<dim3(NX_PAD / 128, M_TOT / 64), 256, HSMEM128>>>(
        xconvh, DI, Wxh, DI, nullptr, nullptr, 0, DI);

    // 4) deltaT = softplus(delta_raw @ W_dt^T + b_dt), transposed store
    hgemm<1,128><<<dim3(DI / 128, M_TOT / 64), 256, HSMEM128>>>(
        xdblh, DI, Wdth, DI, b_dt, deltaT, M_TOT, DI);

    // 5) fused selective scan (exact reference tree) -> ypreT (f32)
    scan_kernel<<<dim3(DI, BATCH), 512>>>(A_log, Dp);

    // 5b) ypreT -> ypreh (half, row-major)
    transpose_h_kernel<<<dim3(M_TOT / 32, DI / 32), dim3(32, 8)>>>();

    // 6) out = ypre @ W_out^T (fp16 hgemm, BN=64 -> 192 CTAs)
    hgemm<0,64><<<dim3(DM / 64, M_TOT / 64), 256, HSMEM64>>>(
        ypreh, DI, Wouth, DI, nullptr, out, DM, DI);
}